// round 10
// baseline (speedup 1.0000x reference)
#include <cuda_runtime.h>
#include <cuda_fp16.h>
#include <stdint.h>

#define S_    2048
#define B_    2
#define D_    1024
#define H_    16
#define BH_   32
#define ROWS_ 4096
#define QLD_  3072
#define ARS_  6144   // B_*QLD_ : stride between seq rows in g_qkv

// ---- scratch (static device globals; no allocation) ----
__device__ float  g_qkv[(size_t)ROWS_ * 3072];         // q cols f32 (k,v blocks unused)
__device__ __half g_kh [(size_t)ROWS_ * 1024];         // K fp16 [s*B+b][h*64+d]
__device__ __half g_vh [(size_t)ROWS_ * 1024];         // V fp16 [s*B+b][h*64+d]
__device__ float  g_r  [(size_t)S_ * D_];              // [t][h*64+d]
__device__ __half g_bd [(size_t)BH_ * S_ * S_];        // Draw per (b,h), fp16
__device__ float  g_att[(size_t)ROWS_ * D_];           // attn_vec
__device__ float  g_y  [(size_t)ROWS_ * D_];           // x + attn_out

// ---------------- mma / cp.async / ldmatrix helpers ----------------
__device__ __forceinline__ void mma8(float* d, const uint32_t* a,
                                     const uint32_t* b, const float* c) {
    asm volatile(
        "mma.sync.aligned.m16n8k8.row.col.f32.tf32.tf32.f32 "
        "{%0,%1,%2,%3}, {%4,%5,%6,%7}, {%8,%9}, {%10,%11,%12,%13};\n"
        : "=f"(d[0]), "=f"(d[1]), "=f"(d[2]), "=f"(d[3])
        : "r"(a[0]), "r"(a[1]), "r"(a[2]), "r"(a[3]), "r"(b[0]), "r"(b[1]),
          "f"(c[0]), "f"(c[1]), "f"(c[2]), "f"(c[3]));
}
__device__ __forceinline__ void mma16h(float* d, const uint32_t* a,
                                       const uint32_t* b, const float* c) {
    asm volatile(
        "mma.sync.aligned.m16n8k16.row.col.f32.f16.f16.f32 "
        "{%0,%1,%2,%3}, {%4,%5,%6,%7}, {%8,%9}, {%10,%11,%12,%13};\n"
        : "=f"(d[0]), "=f"(d[1]), "=f"(d[2]), "=f"(d[3])
        : "r"(a[0]), "r"(a[1]), "r"(a[2]), "r"(a[3]), "r"(b[0]), "r"(b[1]),
          "f"(c[0]), "f"(c[1]), "f"(c[2]), "f"(c[3]));
}
__device__ __forceinline__ uint32_t f2u(float x) { return __float_as_uint(x); }
__device__ __forceinline__ uint32_t h2(float lo, float hi) {
    uint32_t d;
    asm("cvt.rn.f16x2.f32 %0, %1, %2;\n" : "=r"(d) : "f"(hi), "f"(lo));
    return d;   // d.lo = lo, d.hi = hi
}
// schedulable streaming loads/stores (intrinsics, NOT volatile asm)
__device__ __forceinline__ float ldcs_h(const __half* p) {
    unsigned short u = __ldcs((const unsigned short*)p);
    return __half2float(__ushort_as_half(u));
}
__device__ __forceinline__ void cpa16(uint32_t s, const void* g) {
    asm volatile("cp.async.cg.shared.global [%0], [%1], 16;\n" :: "r"(s), "l"(g));
}
__device__ __forceinline__ void cpcommit() { asm volatile("cp.async.commit_group;\n"); }
template <int N> __device__ __forceinline__ void cpwait() {
    asm volatile("cp.async.wait_group %0;\n" :: "n"(N));
}
__device__ __forceinline__ void ldsm4(uint32_t* r, uint32_t a) {
    asm volatile("ldmatrix.sync.aligned.m8n8.x4.shared.b16 {%0,%1,%2,%3}, [%4];\n"
        : "=r"(r[0]), "=r"(r[1]), "=r"(r[2]), "=r"(r[3]) : "r"(a));
}
__device__ __forceinline__ void ldsm4t(uint32_t* r, uint32_t a) {
    asm volatile("ldmatrix.sync.aligned.m8n8.x4.trans.shared.b16 {%0,%1,%2,%3}, [%4];\n"
        : "=r"(r[0]), "=r"(r[1]), "=r"(r[2]), "=r"(r[3]) : "r"(a));
}
__device__ __forceinline__ float ex2(float x) {
    float y; asm("ex2.approx.f32 %0, %1;" : "=f"(y) : "f"(x)); return y;
}

// ============================================================
// Projection GEMM, K=1024 fixed, tile 128x128x32, cp.async 2-stage.
// MODE 0: q cols -> g_qkv f32, K cols -> g_kh fp16, V cols -> g_vh fp16
// MODE 1: g_r = A@B    MODE 2: g_y = g_att@B + Xres
// (NO reg cap — R9 showed 128-cap spills this kernel.)
// ============================================================
template <int MODE>
__global__ __launch_bounds__(256) void pgemm(const float* __restrict__ A,
                                             const float* __restrict__ Bw,
                                             const float* __restrict__ Xres,
                                             int N)
{
    extern __shared__ float sm[];
    float* As = sm;               // 2 x 128 x 36
    float* Bs = sm + 9216;        // 2 x 32  x 136
    const float* Ap = (MODE == 2) ? (const float*)g_att : A;
    float* C = (MODE == 0) ? g_qkv : (MODE == 1) ? g_r : g_y;

    int tid = threadIdx.x, l = tid & 31, w = tid >> 5, wm = w >> 1, wn = w & 1;
    size_t m0 = (size_t)blockIdx.y * 128, n0 = (size_t)blockIdx.x * 128;
    uint32_t sA = (uint32_t)__cvta_generic_to_shared(As);
    uint32_t sB = (uint32_t)__cvta_generic_to_shared(Bs);

    float acc[2][8][4] = {};

#define STAGE(IT, BUF)                                                          \
    {                                                                           \
        int kk = (IT) * 32;                                                     \
        uint32_t ab = sA + (BUF) * 4608 * 4;                                    \
        _Pragma("unroll")                                                       \
        for (int t = 0; t < 4; t++) {                                           \
            int idx = tid + t * 256; int r = idx >> 3, c4 = (idx & 7) << 2;     \
            cpa16(ab + (r * 36 + c4) * 4, Ap + (m0 + r) * 1024 + kk + c4);      \
        }                                                                       \
        uint32_t bb = sB + (BUF) * 4352 * 4;                                    \
        _Pragma("unroll")                                                       \
        for (int t = 0; t < 4; t++) {                                           \
            int idx = tid + t * 256; int r = idx >> 5, c4 = (idx & 31) << 2;    \
            cpa16(bb + (r * 136 + c4) * 4, Bw + (size_t)(kk + r) * N + n0 + c4);\
        }                                                                       \
        cpcommit();                                                             \
    }

    STAGE(0, 0);
    for (int it = 0; it < 32; it++) {
        int buf = it & 1;
        if (it + 1 < 32) { STAGE(it + 1, buf ^ 1); cpwait<1>(); }
        else             { cpwait<0>(); }
        __syncthreads();
        const float* As_ = As + buf * 4608;
        const float* Bs_ = Bs + buf * 4352;
#pragma unroll
        for (int k8 = 0; k8 < 4; k8++) {
            uint32_t a[2][4];
#pragma unroll
            for (int mt = 0; mt < 2; mt++) {
                int r = wm * 32 + mt * 16 + (l >> 2);
                a[mt][0] = f2u(As_[r * 36 + k8 * 8 + (l & 3)]);
                a[mt][1] = f2u(As_[(r + 8) * 36 + k8 * 8 + (l & 3)]);
                a[mt][2] = f2u(As_[r * 36 + k8 * 8 + (l & 3) + 4]);
                a[mt][3] = f2u(As_[(r + 8) * 36 + k8 * 8 + (l & 3) + 4]);
            }
#pragma unroll
            for (int nt = 0; nt < 8; nt++) {
                uint32_t bf[2];
                int cb = wn * 64 + nt * 8 + (l >> 2);
                bf[0] = f2u(Bs_[(k8 * 8 + (l & 3)) * 136 + cb]);
                bf[1] = f2u(Bs_[(k8 * 8 + (l & 3) + 4) * 136 + cb]);
#pragma unroll
                for (int mt = 0; mt < 2; mt++)
                    mma8(acc[mt][nt], a[mt], bf, acc[mt][nt]);
            }
        }
        __syncthreads();
    }
#undef STAGE

    if (MODE == 0 && n0 >= 1024) {
        // K / V columns: write fp16 copies only (f32 never read)
        __half* dst = (n0 >= 2048) ? g_vh : g_kh;
        size_t cb = n0 - ((n0 >= 2048) ? 2048 : 1024);
#pragma unroll
        for (int mt = 0; mt < 2; mt++) {
            size_t r0 = m0 + wm * 32 + mt * 16 + (l >> 2);
#pragma unroll
            for (int nt = 0; nt < 8; nt++) {
                size_t c = cb + wn * 64 + nt * 8 + 2 * (l & 3);
                *(__half2*)(dst + r0 * 1024 + c) =
                    __floats2half2_rn(acc[mt][nt][0], acc[mt][nt][1]);
                *(__half2*)(dst + (r0 + 8) * 1024 + c) =
                    __floats2half2_rn(acc[mt][nt][2], acc[mt][nt][3]);
            }
        }
        return;
    }
#pragma unroll
    for (int mt = 0; mt < 2; mt++) {
        size_t r0 = m0 + wm * 32 + mt * 16 + (l >> 2);
#pragma unroll
        for (int nt = 0; nt < 8; nt++) {
            size_t c = n0 + wn * 64 + nt * 8 + 2 * (l & 3);
            float2 v0 = make_float2(acc[mt][nt][0], acc[mt][nt][1]);
            float2 v1 = make_float2(acc[mt][nt][2], acc[mt][nt][3]);
            if (MODE == 2) {
                float2 x0 = *(const float2*)(Xres + r0 * N + c);
                float2 x1 = *(const float2*)(Xres + (r0 + 8) * N + c);
                v0.x += x0.x; v0.y += x0.y; v1.x += x1.x; v1.y += x1.y;
            }
            *(float2*)(C + r0 * N + c) = v0;
            *(float2*)(C + (r0 + 8) * N + c) = v1;
        }
    }
}

// ============================================================
// Draw = (q + pos_bias_v) @ r^T per (b,h). 128x128, K=64, ldmatrix.
// Output fp16 with streaming-store intrinsics (written once, read once).
// ============================================================
__global__ __launch_bounds__(256, 2) void bd_gemm(const float* __restrict__ pbv)
{
    extern __shared__ float sm[];
    float* Qs = sm;               // 128 x 68
    float* Rs = sm + 8704;        // 128 x 68
    int tid = threadIdx.x, l = tid & 31, w = tid >> 5;
    int bh = blockIdx.z, b = bh >> 4, h = bh & 15;
    int i0 = blockIdx.y * 128, t0 = blockIdx.x * 128;
    const float* Qg = g_qkv + (size_t)b * QLD_ + h * 64;
    const float* Rg = g_r + h * 64;
    const float* bias = pbv + h * 64;

#pragma unroll
    for (int t = 0; t < 8; t++) {
        int idx = tid + t * 256; int r = idx >> 4, c4 = (idx & 15) << 2;
        float4 a4 = *(const float4*)(Qg + (size_t)(i0 + r) * ARS_ + c4);
        float4 u4 = *(const float4*)(bias + c4);
        a4.x += u4.x; a4.y += u4.y; a4.z += u4.z; a4.w += u4.w;
        *(float4*)&Qs[r * 68 + c4] = a4;
        *(float4*)&Rs[r * 68 + c4] = *(const float4*)(Rg + (size_t)(t0 + r) * D_ + c4);
    }
    __syncthreads();

    uint32_t sQ = (uint32_t)__cvta_generic_to_shared(Qs);
    uint32_t sR = (uint32_t)__cvta_generic_to_shared(Rs);
    uint32_t aoff = ((w * 16 + ((l >> 3) & 1) * 8 + (l & 7)) * 68 + ((l >> 4) & 1) * 4) * 4;
    uint32_t boff = ((((l >> 4) & 1) * 8 + (l & 7)) * 68 + ((l >> 3) & 1) * 4) * 4;

    uint32_t qa[8][4];
#pragma unroll
    for (int k8 = 0; k8 < 8; k8++) ldsm4(qa[k8], sQ + aoff + k8 * 32);

    float acc[16][4] = {};
#pragma unroll
    for (int k8 = 0; k8 < 8; k8++)
#pragma unroll
        for (int np = 0; np < 8; np++) {
            uint32_t kb[4];
            ldsm4(kb, sR + boff + np * 16 * 272 + k8 * 32);
            mma8(acc[2 * np],     qa[k8], kb,     acc[2 * np]);
            mma8(acc[2 * np + 1], qa[k8], kb + 2, acc[2 * np + 1]);
        }

    __half* out = g_bd + (size_t)bh * S_ * S_;
    int gr = i0 + w * 16 + (l >> 2);
#pragma unroll
    for (int nt = 0; nt < 16; nt++) {
        int gc = t0 + nt * 8 + 2 * (l & 3);
        __stcs((unsigned int*)(out + (size_t)gr * S_ + gc),
               h2(acc[nt][0], acc[nt][1]));
        __stcs((unsigned int*)(out + (size_t)(gr + 8) * S_ + gc),
               h2(acc[nt][2], acc[nt][3]));
    }
}

// ============================================================
// Fused attention, all-fp16 mma paths:
//  AC: (q+u) fp16 x K fp16, m16n8k16 (Q smem fp16, K via ldsm4)
//  PV: P fp16 (reg cvt, no shuffles) x V fp16 (ldsm4t)
// BD (fp16) gather via __ldcs intrinsics, pipelined in registers.
// smem 55 KB, 2 CTAs/SM.
// ============================================================
__device__ __forceinline__ float bdval(const __half* bd, int i, int j)
{
    if (j <= i)      return ldcs_h(bd + (size_t)i * S_ + (S_ - 1 + j - i));
    if (j == i + 1)  return 0.f;
    return ldcs_h(bd + (size_t)(i + 1) * S_ + (j - i - 2));
}

__global__ __launch_bounds__(256, 2) void fattn(const float* __restrict__ pbu)
{
    extern __shared__ __half smh[];
    __half* Qsh = smh;                      // 128 x 72 fp16 (persistent)
    __half* Ksh = smh + 9216;               // 128 x 72 fp16
    __half* Vsh = smh + 18432;              // 128 x 72 fp16
    int tid = threadIdx.x, l = tid & 31, w = tid >> 5;
    int bh = blockIdx.y, b = bh >> 4, h = bh & 15;
    int i0 = blockIdx.x * 128;
    const float*  Qg = g_qkv + (size_t)b * QLD_ + h * 64;
    const __half* Kg = g_kh + (size_t)b * 1024 + h * 64;   // row stride 2048
    const __half* Vg = g_vh + (size_t)b * 1024 + h * 64;   // row stride 2048
    const __half* bd = g_bd + (size_t)bh * S_ * S_;
    const float* bias = pbu + h * 64;
    uint32_t sQ = (uint32_t)__cvta_generic_to_shared(Qsh);
    uint32_t sK = (uint32_t)__cvta_generic_to_shared(Ksh);
    uint32_t sV = (uint32_t)__cvta_generic_to_shared(Vsh);

    // (q + bias_u) -> fp16 smem; prefetch K0 (group), V0 (group)
#pragma unroll
    for (int t = 0; t < 8; t++) {
        int idx = tid + t * 256; int r = idx >> 4, c4 = (idx & 15) << 2;
        float4 a4 = *(const float4*)(Qg + (size_t)(i0 + r) * ARS_ + c4);
        float4 u4 = *(const float4*)(bias + c4);
        *(__half2*)(Qsh + r * 72 + c4)     = __floats2half2_rn(a4.x + u4.x, a4.y + u4.y);
        *(__half2*)(Qsh + r * 72 + c4 + 2) = __floats2half2_rn(a4.z + u4.z, a4.w + u4.w);
    }
#pragma unroll
    for (int t = 0; t < 4; t++) {
        int idx = tid + t * 256; int r = idx >> 3, c8 = (idx & 7) << 3;
        cpa16(sK + (r * 72 + c8) * 2, Kg + (size_t)r * 2048 + c8);
    }
    cpcommit();
#pragma unroll
    for (int t = 0; t < 4; t++) {
        int idx = tid + t * 256; int r = idx >> 3, c8 = (idx & 7) << 3;
        cpa16(sV + (r * 72 + c8) * 2, Vg + (size_t)r * 2048 + c8);
    }
    cpcommit();

    // fp16 A-frag (Q rows w*16..w*16+15):
    uint32_t qoff  = (uint32_t)((w * 16 + (l & 7) + ((l >> 3) & 1) * 8) * 144
                                + ((l >> 4) & 1) * 16);
    // fp16 B-frag from row-major K (n = row, k-pairs contiguous):
    uint32_t kboff = (uint32_t)(((l & 7) + (l >> 4) * 8) * 144 + ((l >> 3) & 1) * 16);
    uint32_t vrbase = (uint32_t)((l & 7) + ((l >> 3) & 1) * 8);
    uint32_t vcoff  = (uint32_t)((l >> 4) * 8);

    float o[8][4] = {};
    float bdbuf[32];
    float mrow0 = -1e30f, mrow1 = -1e30f, lsum0 = 0.f, lsum1 = 0.f;
    int tc = l & 3;
    int lr0 = w * 16 + (l >> 2);
    int row0 = i0 + lr0, row1 = row0 + 8;
    const float CS = 0.1803368801111204f;   // 0.125 * log2(e)

#define LDBD(JB)                                                                \
    _Pragma("unroll")                                                           \
    for (int nt = 0; nt < 8; nt++) {                                            \
        int c0 = (JB) + nt * 8 + 2 * tc;                                        \
        bdbuf[nt * 4 + 0] = bdval(bd, row0, c0);                                \
        bdbuf[nt * 4 + 1] = bdval(bd, row0, c0 + 1);                            \
        bdbuf[nt * 4 + 2] = bdval(bd, row1, c0);                                \
        bdbuf[nt * 4 + 3] = bdval(bd, row1, c0 + 1);                            \
    }

    LDBD(0)              // BD for iter0/half0 — overlaps K0/V0 arrival
    __syncthreads();     // Qsh visible to ldmatrix

#define AC_MMA(HALF)                                                            \
    _Pragma("unroll")                                                           \
    for (int nt = 0; nt < 8; nt++)                                              \
        p[nt][0] = p[nt][1] = p[nt][2] = p[nt][3] = 0.f;                        \
    _Pragma("unroll")                                                           \
    for (int ks = 0; ks < 4; ks++) {                                            \
        uint32_t qf[4];                                                         \
        ldsm4(qf, sQ + qoff + ks * 32);                                         \
        _Pragma("unroll")                                                       \
        for (int np = 0; np < 4; np++) {                                        \
            uint32_t kb[4];                                                     \
            ldsm4(kb, sK + kboff + ((HALF) * 64 + np * 16) * 144 + ks * 32);    \
            mma16h(p[2 * np],     qf, kb,     p[2 * np]);                       \
            mma16h(p[2 * np + 1], qf, kb + 2, p[2 * np + 1]);                   \
        }                                                                       \
    }

#define SOFTMAX_STEP()                                                          \
    {                                                                           \
        float mx0 = -1e30f, mx1 = -1e30f;                                       \
        _Pragma("unroll")                                                       \
        for (int nt = 0; nt < 8; nt++) {                                        \
            float s;                                                            \
            s = (p[nt][0] + bdbuf[nt*4+0]) * CS; p[nt][0] = s; mx0 = fmaxf(mx0, s); \
            s = (p[nt][1] + bdbuf[nt*4+1]) * CS; p[nt][1] = s; mx0 = fmaxf(mx0, s); \
            s = (p[nt][2] + bdbuf[nt*4+2]) * CS; p[nt][2] = s; mx1 = fmaxf(mx1, s); \
            s = (p[nt][3] + bdbuf[nt*4+3]) * CS; p[nt][3] = s; mx1 = fmaxf(mx1, s); \
        }                                                                       \
        mx0 = fmaxf(mx0, __shfl_xor_sync(~0u, mx0, 1));                         \
        mx0 = fmaxf(mx0, __shfl_xor_sync(~0u, mx0, 2));                         \
        mx1 = fmaxf(mx1, __shfl_xor_sync(~0u, mx1, 1));                         \
        mx1 = fmaxf(mx1, __shfl_xor_sync(~0u, mx1, 2));                         \
        float mn0 = fmaxf(mrow0, mx0), mn1 = fmaxf(mrow1, mx1);                 \
        float al0 = ex2(mrow0 - mn0), al1 = ex2(mrow1 - mn1);                   \
        mrow0 = mn0; mrow1 = mn1;                                               \
        float rs0 = 0.f, rs1 = 0.f;                                             \
        _Pragma("unroll")                                                       \
        for (int nt = 0; nt < 8; nt++) {                                        \
            p[nt][0] = ex2(p[nt][0] - mn0); p[nt][1] = ex2(p[nt][1] - mn0);     \
            p[nt][2] = ex2(p[nt][2] - mn1); p[nt][3] = ex2(p[nt][3] - mn1);     \
            rs0 += p[nt][0] + p[nt][1]; rs1 += p[nt][2] + p[nt][3];             \
        }                                                                       \
        rs0 += __shfl_xor_sync(~0u, rs0, 1); rs0 += __shfl_xor_sync(~0u, rs0, 2);\
        rs1 += __shfl_xor_sync(~0u, rs1, 1); rs1 += __shfl_xor_sync(~0u, rs1, 2);\
        lsum0 = lsum0 * al0 + rs0;                                              \
        lsum1 = lsum1 * al1 + rs1;                                              \
        _Pragma("unroll")                                                       \
        for (int nt = 0; nt < 8; nt++) {                                        \
            o[nt][0] *= al0; o[nt][1] *= al0; o[nt][2] *= al1; o[nt][3] *= al1; \
        }                                                                       \
    }

#define CVT_P()                                                                 \
    uint32_t af[4][4];                                                          \
    _Pragma("unroll")                                                           \
    for (int ks = 0; ks < 4; ks++) {                                            \
        af[ks][0] = h2(p[2*ks][0],   p[2*ks][1]);                               \
        af[ks][1] = h2(p[2*ks][2],   p[2*ks][3]);                               \
        af[ks][2] = h2(p[2*ks+1][0], p[2*ks+1][1]);                             \
        af[ks][3] = h2(p[2*ks+1][2], p[2*ks+1][3]);                             \
    }

#define PV16(HALF)                                                              \
    _Pragma("unroll")                                                           \
    for (int ks = 0; ks < 4; ks++) {                                            \
        uint32_t vrow = (uint32_t)((HALF) * 64 + ks * 16) + vrbase;             \
        _Pragma("unroll")                                                       \
        for (int ntt = 0; ntt < 4; ntt++) {                                     \
            uint32_t vb[4];                                                     \
            ldsm4t(vb, sV + (vrow * 72 + ntt * 16 + vcoff) * 2);                \
            mma16h(o[2*ntt],   af[ks], vb,   o[2*ntt]);                         \
            mma16h(o[2*ntt+1], af[ks], vb+2, o[2*ntt+1]);                       \
        }                                                                       \
    }

    for (int it = 0; it < 16; it++) {
        cpwait<1>();          // K(it) landed; V(it) may be pending
        __syncthreads();      // all threads' K(it) visible

        {   // ---- half 0 ----
            float p[8][4];
            AC_MMA(0)
            SOFTMAX_STEP()
            CVT_P()           // p dead after this
            cpwait<0>();      // V(it) complete
            __syncthreads();
            LDBD(it * 128 + 64)   // BD half1 — covered by PV0 + AC1
            PV16(0)
        }
        {   // ---- half 1 ----
            float p[8][4];
            AC_MMA(1)
            SOFTMAX_STEP()
            CVT_P()
            __syncthreads();  // all warps done with Ksh
            if (it + 1 < 16) {
                const __half* kn = Kg + (size_t)((it + 1) * 128) * 2048;
#pragma unroll
                for (int t = 0; t < 4; t++) {
                    int idx = tid + t * 256; int r = idx >> 3, c8 = (idx & 7) << 3;
                    cpa16(sK + (r * 72 + c8) * 2, kn + (size_t)r * 2048 + c8);
                }
                cpcommit();
                LDBD((it + 1) * 128)   // BD next half0 — covered by PV1 + next AC0
            }
            PV16(1)
        }
        __syncthreads();      // all warps done reading Vsh
        if (it + 1 < 16) {
            const __half* vn = Vg + (size_t)((it + 1) * 128) * 2048;
#pragma unroll
            for (int t = 0; t < 4; t++) {
                int idx = tid + t * 256; int r = idx >> 3, c8 = (idx & 7) << 3;
                cpa16(sV + (r * 72 + c8) * 2, vn + (size_t)r * 2048 + c8);
            }
            cpcommit();
        }
    }
#undef LDBD
#undef AC_MMA
#undef SOFTMAX_STEP
#undef CVT_P
#undef PV16

    float inv0 = 1.f / lsum0, inv1 = 1.f / lsum1;
#pragma unroll
    for (int nt = 0; nt < 8; nt++) {
        int c = h * 64 + nt * 8 + 2 * tc;
        *(float2*)(g_att + ((size_t)row0 * B_ + b) * D_ + c) =
            make_float2(o[nt][0] * inv0, o[nt][1] * inv0);
        *(float2*)(g_att + ((size_t)row1 * B_ + b) * D_ + c) =
            make_float2(o[nt][2] * inv1, o[nt][3] * inv1);
    }
}

// ============================================================
// LayerNorm over D=1024 per row.
// ============================================================
__global__ __launch_bounds__(256) void ln_k(const float* __restrict__ gamma,
                                            const float* __restrict__ beta,
                                            float* __restrict__ out)
{
    __shared__ float reds[8], redq[8];
    const float* y = g_y + (size_t)blockIdx.x * D_;
    int tid = threadIdx.x;
    float v[4];
    float s = 0.f, q = 0.f;
#pragma unroll
    for (int t = 0; t < 4; t++) {
        v[t] = y[tid + t * 256];
        s += v[t]; q += v[t] * v[t];
    }
#pragma unroll
    for (int o = 16; o; o >>= 1) {
        s += __shfl_xor_sync(0xffffffffu, s, o);
        q += __shfl_xor_sync(0xffffffffu, q, o);
    }
    if ((tid & 31) == 0) { reds[tid >> 5] = s; redq[tid >> 5] = q; }
    __syncthreads();
    float ts = 0.f, tq = 0.f;
#pragma unroll
    for (int wv = 0; wv < 8; wv++) { ts += reds[wv]; tq += redq[wv]; }
    float mu = ts * (1.f / 1024.f);
    float var = tq * (1.f / 1024.f) - mu * mu;
    float inv = rsqrtf(var + 1e-5f);
    float* op = out + (size_t)blockIdx.x * D_;
#pragma unroll
    for (int t = 0; t < 4; t++) {
        int c = tid + t * 256;
        op[c] = (v[t] - mu) * inv * gamma[c] + beta[c];
    }
}

// ============================================================
extern "C" void kernel_launch(void* const* d_in, const int* in_sizes, int n_in,
                              void* d_out, int out_size)
{
    const float* x    = (const float*)d_in[0];
    const float* pe   = (const float*)d_in[1];
    const float* pbu  = (const float*)d_in[2];
    const float* pbv  = (const float*)d_in[3];
    const float* Wqkv = (const float*)d_in[4];
    const float* Wrel = (const float*)d_in[5];
    const float* Wo   = (const float*)d_in[6];
    const float* gam  = (const float*)d_in[7];
    const float* bet  = (const float*)d_in[8];
    float* out = (float*)d_out;

    const int PG_SMEM = 71680;     // (9216 + 8704) * 4
    const int BD_SMEM = 69632;     // 2 * 128*68 * 4
    const int FA_SMEM = 55296;     // 3 * 128*72 * 2
    cudaFuncSetAttribute(pgemm<0>, cudaFuncAttributeMaxDynamicSharedMemorySize, PG_SMEM);
    cudaFuncSetAttribute(pgemm<1>, cudaFuncAttributeMaxDynamicSharedMemorySize, PG_SMEM);
    cudaFuncSetAttribute(pgemm<2>, cudaFuncAttributeMaxDynamicSharedMemorySize, PG_SMEM);
    cudaFuncSetAttribute(bd_gemm,  cudaFuncAttributeMaxDynamicSharedMemorySize, BD_SMEM);
    cudaFuncSetAttribute(fattn,    cudaFuncAttributeMaxDynamicSharedMemorySize, FA_SMEM);

    // 1) qkv = x @ W_qkv  (q -> f32; k,v -> fp16)
    pgemm<0><<<dim3(24, 32), 256, PG_SMEM>>>(x, Wqkv, nullptr, 3072);
    // 2) r = pos_emb @ W_relemb
    pgemm<1><<<dim3(8, 16), 256, PG_SMEM>>>(pe, Wrel, nullptr, 1024);
    // 3) Draw = (q + pbv) @ r^T per (b,h), fp16 out
    bd_gemm<<<dim3(16, 16, 32), 256, BD_SMEM>>>(pbv);
    // 4) fused: scores + rel-shift + softmax + PV
    fattn<<<dim3(16, 32), 256, FA_SMEM>>>(pbu);
    // 5) y = x + attn_vec @ W_o
    pgemm<2><<<dim3(8, 32), 256, PG_SMEM>>>(nullptr, Wo, x, 1024);
    // 6) layernorm
    ln_k<<<4096, 256>>>(gam, bet, out);
}

// round 11
// speedup vs baseline: 1.4342x; 1.4342x over previous
#include <cuda_runtime.h>
#include <cuda_fp16.h>
#include <stdint.h>

#define S_    2048
#define B_    2
#define D_    1024
#define H_    16
#define BH_   32
#define ROWS_ 4096
#define QLD_  3072
#define ARS_  6144   // B_*QLD_ : stride between seq rows in g_qkv

// ---- scratch (static device globals; no allocation) ----
__device__ float  g_qkv[(size_t)ROWS_ * 3072];         // q cols f32 (k,v blocks unused)
__device__ __half g_kh [(size_t)ROWS_ * 1024];         // K fp16 [s*B+b][h*64+d]
__device__ __half g_vh [(size_t)ROWS_ * 1024];         // V fp16 [s*B+b][h*64+d]
__device__ float  g_r  [(size_t)S_ * D_];              // [t][h*64+d]
__device__ float  g_bd [(size_t)BH_ * S_ * S_];        // PRE-SHIFTED BD per (b,h), f32
__device__ float  g_att[(size_t)ROWS_ * D_];           // attn_vec
__device__ float  g_y  [(size_t)ROWS_ * D_];           // x + attn_out

// ---------------- mma / cp.async / ldmatrix helpers ----------------
__device__ __forceinline__ void mma8(float* d, const uint32_t* a,
                                     const uint32_t* b, const float* c) {
    asm volatile(
        "mma.sync.aligned.m16n8k8.row.col.f32.tf32.tf32.f32 "
        "{%0,%1,%2,%3}, {%4,%5,%6,%7}, {%8,%9}, {%10,%11,%12,%13};\n"
        : "=f"(d[0]), "=f"(d[1]), "=f"(d[2]), "=f"(d[3])
        : "r"(a[0]), "r"(a[1]), "r"(a[2]), "r"(a[3]), "r"(b[0]), "r"(b[1]),
          "f"(c[0]), "f"(c[1]), "f"(c[2]), "f"(c[3]));
}
__device__ __forceinline__ void mma16h(float* d, const uint32_t* a,
                                       const uint32_t* b, const float* c) {
    asm volatile(
        "mma.sync.aligned.m16n8k16.row.col.f32.f16.f16.f32 "
        "{%0,%1,%2,%3}, {%4,%5,%6,%7}, {%8,%9}, {%10,%11,%12,%13};\n"
        : "=f"(d[0]), "=f"(d[1]), "=f"(d[2]), "=f"(d[3])
        : "r"(a[0]), "r"(a[1]), "r"(a[2]), "r"(a[3]), "r"(b[0]), "r"(b[1]),
          "f"(c[0]), "f"(c[1]), "f"(c[2]), "f"(c[3]));
}
__device__ __forceinline__ uint32_t f2u(float x) { return __float_as_uint(x); }
__device__ __forceinline__ uint32_t h2(float lo, float hi) {
    uint32_t d;
    asm("cvt.rn.f16x2.f32 %0, %1, %2;\n" : "=r"(d) : "f"(hi), "f"(lo));
    return d;   // d.lo = lo, d.hi = hi
}
__device__ __forceinline__ void cpa16(uint32_t s, const void* g) {
    asm volatile("cp.async.cg.shared.global [%0], [%1], 16;\n" :: "r"(s), "l"(g));
}
__device__ __forceinline__ void cpcommit() { asm volatile("cp.async.commit_group;\n"); }
template <int N> __device__ __forceinline__ void cpwait() {
    asm volatile("cp.async.wait_group %0;\n" :: "n"(N));
}
__device__ __forceinline__ void ldsm4(uint32_t* r, uint32_t a) {
    asm volatile("ldmatrix.sync.aligned.m8n8.x4.shared.b16 {%0,%1,%2,%3}, [%4];\n"
        : "=r"(r[0]), "=r"(r[1]), "=r"(r[2]), "=r"(r[3]) : "r"(a));
}
__device__ __forceinline__ void ldsm4t(uint32_t* r, uint32_t a) {
    asm volatile("ldmatrix.sync.aligned.m8n8.x4.trans.shared.b16 {%0,%1,%2,%3}, [%4];\n"
        : "=r"(r[0]), "=r"(r[1]), "=r"(r[2]), "=r"(r[3]) : "r"(a));
}
__device__ __forceinline__ float ex2(float x) {
    float y; asm("ex2.approx.f32 %0, %1;" : "=f"(y) : "f"(x)); return y;
}

// ============================================================
// Projection GEMM, K=1024 fixed, tile 128x128x32, cp.async 2-stage.
// MODE 0: q cols -> g_qkv f32, K cols -> g_kh fp16, V cols -> g_vh fp16
// MODE 1: g_r = A@B    MODE 2: g_y = g_att@B + Xres   (R8 version, no cap)
// ============================================================
template <int MODE>
__global__ __launch_bounds__(256) void pgemm(const float* __restrict__ A,
                                             const float* __restrict__ Bw,
                                             const float* __restrict__ Xres,
                                             int N)
{
    extern __shared__ float sm[];
    float* As = sm;               // 2 x 128 x 36
    float* Bs = sm + 9216;        // 2 x 32  x 136
    const float* Ap = (MODE == 2) ? (const float*)g_att : A;
    float* C = (MODE == 0) ? g_qkv : (MODE == 1) ? g_r : g_y;

    int tid = threadIdx.x, l = tid & 31, w = tid >> 5, wm = w >> 1, wn = w & 1;
    size_t m0 = (size_t)blockIdx.y * 128, n0 = (size_t)blockIdx.x * 128;
    uint32_t sA = (uint32_t)__cvta_generic_to_shared(As);
    uint32_t sB = (uint32_t)__cvta_generic_to_shared(Bs);

    float acc[2][8][4] = {};

#define STAGE(IT, BUF)                                                          \
    {                                                                           \
        int kk = (IT) * 32;                                                     \
        uint32_t ab = sA + (BUF) * 4608 * 4;                                    \
        _Pragma("unroll")                                                       \
        for (int t = 0; t < 4; t++) {                                           \
            int idx = tid + t * 256; int r = idx >> 3, c4 = (idx & 7) << 2;     \
            cpa16(ab + (r * 36 + c4) * 4, Ap + (m0 + r) * 1024 + kk + c4);      \
        }                                                                       \
        uint32_t bb = sB + (BUF) * 4352 * 4;                                    \
        _Pragma("unroll")                                                       \
        for (int t = 0; t < 4; t++) {                                           \
            int idx = tid + t * 256; int r = idx >> 5, c4 = (idx & 31) << 2;    \
            cpa16(bb + (r * 136 + c4) * 4, Bw + (size_t)(kk + r) * N + n0 + c4);\
        }                                                                       \
        cpcommit();                                                             \
    }

    STAGE(0, 0);
    for (int it = 0; it < 32; it++) {
        int buf = it & 1;
        if (it + 1 < 32) { STAGE(it + 1, buf ^ 1); cpwait<1>(); }
        else             { cpwait<0>(); }
        __syncthreads();
        const float* As_ = As + buf * 4608;
        const float* Bs_ = Bs + buf * 4352;
#pragma unroll
        for (int k8 = 0; k8 < 4; k8++) {
            uint32_t a[2][4];
#pragma unroll
            for (int mt = 0; mt < 2; mt++) {
                int r = wm * 32 + mt * 16 + (l >> 2);
                a[mt][0] = f2u(As_[r * 36 + k8 * 8 + (l & 3)]);
                a[mt][1] = f2u(As_[(r + 8) * 36 + k8 * 8 + (l & 3)]);
                a[mt][2] = f2u(As_[r * 36 + k8 * 8 + (l & 3) + 4]);
                a[mt][3] = f2u(As_[(r + 8) * 36 + k8 * 8 + (l & 3) + 4]);
            }
#pragma unroll
            for (int nt = 0; nt < 8; nt++) {
                uint32_t bf[2];
                int cb = wn * 64 + nt * 8 + (l >> 2);
                bf[0] = f2u(Bs_[(k8 * 8 + (l & 3)) * 136 + cb]);
                bf[1] = f2u(Bs_[(k8 * 8 + (l & 3) + 4) * 136 + cb]);
#pragma unroll
                for (int mt = 0; mt < 2; mt++)
                    mma8(acc[mt][nt], a[mt], bf, acc[mt][nt]);
            }
        }
        __syncthreads();
    }
#undef STAGE

    if (MODE == 0 && n0 >= 1024) {
        // K / V columns: write fp16 copies only (f32 never read)
        __half* dst = (n0 >= 2048) ? g_vh : g_kh;
        size_t cb = n0 - ((n0 >= 2048) ? 2048 : 1024);
#pragma unroll
        for (int mt = 0; mt < 2; mt++) {
            size_t r0 = m0 + wm * 32 + mt * 16 + (l >> 2);
#pragma unroll
            for (int nt = 0; nt < 8; nt++) {
                size_t c = cb + wn * 64 + nt * 8 + 2 * (l & 3);
                *(__half2*)(dst + r0 * 1024 + c) =
                    __floats2half2_rn(acc[mt][nt][0], acc[mt][nt][1]);
                *(__half2*)(dst + (r0 + 8) * 1024 + c) =
                    __floats2half2_rn(acc[mt][nt][2], acc[mt][nt][3]);
            }
        }
        return;
    }
#pragma unroll
    for (int mt = 0; mt < 2; mt++) {
        size_t r0 = m0 + wm * 32 + mt * 16 + (l >> 2);
#pragma unroll
        for (int nt = 0; nt < 8; nt++) {
            size_t c = n0 + wn * 64 + nt * 8 + 2 * (l & 3);
            float2 v0 = make_float2(acc[mt][nt][0], acc[mt][nt][1]);
            float2 v1 = make_float2(acc[mt][nt][2], acc[mt][nt][3]);
            if (MODE == 2) {
                float2 x0 = *(const float2*)(Xres + r0 * N + c);
                float2 x1 = *(const float2*)(Xres + (r0 + 8) * N + c);
                v0.x += x0.x; v0.y += x0.y; v1.x += x1.x; v1.y += x1.y;
            }
            *(float2*)(C + r0 * N + c) = v0;
            *(float2*)(C + (r0 + 8) * N + c) = v1;
        }
    }
}

// ============================================================
// Draw = (q + pos_bias_v) @ r^T per (b,h), stored PRE-SHIFTED:
//   Draw[r,t] -> (r,   t-(S-1)+r)  if t >= S-1-r
//             -> (r-1, t+r+1)      else (dropped when r==0)
// Row i's column j=i+1 is never written (it's the rel-shift zero;
// fattn masks it). Streaming scalar stores, written once/read once.
// ============================================================
__device__ __forceinline__ void bd_store_pair(float* out, int r, int t,
                                              float v0, float v1)
{
    int thr = S_ - 1 - r;
    if (t >= thr) {                       // both elements branch (a)
        float* p = out + (size_t)r * S_ + (t - (S_ - 1) + r);
        __stcs(p, v0); __stcs(p + 1, v1);
    } else if (t + 1 < thr) {             // both elements branch (b)
        if (r > 0) {
            float* p = out + (size_t)(r - 1) * S_ + (t + r + 1);
            __stcs(p, v0); __stcs(p + 1, v1);
        }
    } else {                              // straddle: t=(b), t+1=(a)
        if (r > 0) __stcs(out + (size_t)(r - 1) * S_ + (S_ - 1), v0);
        __stcs(out + (size_t)r * S_, v1);
    }
}

__global__ __launch_bounds__(256, 2) void bd_gemm(const float* __restrict__ pbv)
{
    extern __shared__ float sm[];
    float* Qs = sm;               // 128 x 68
    float* Rs = sm + 8704;        // 128 x 68
    int tid = threadIdx.x, l = tid & 31, w = tid >> 5;
    int bh = blockIdx.z, b = bh >> 4, h = bh & 15;
    int i0 = blockIdx.y * 128, t0 = blockIdx.x * 128;
    const float* Qg = g_qkv + (size_t)b * QLD_ + h * 64;
    const float* Rg = g_r + h * 64;
    const float* bias = pbv + h * 64;

#pragma unroll
    for (int t = 0; t < 8; t++) {
        int idx = tid + t * 256; int r = idx >> 4, c4 = (idx & 15) << 2;
        float4 a4 = *(const float4*)(Qg + (size_t)(i0 + r) * ARS_ + c4);
        float4 u4 = *(const float4*)(bias + c4);
        a4.x += u4.x; a4.y += u4.y; a4.z += u4.z; a4.w += u4.w;
        *(float4*)&Qs[r * 68 + c4] = a4;
        *(float4*)&Rs[r * 68 + c4] = *(const float4*)(Rg + (size_t)(t0 + r) * D_ + c4);
    }
    __syncthreads();

    uint32_t sQ = (uint32_t)__cvta_generic_to_shared(Qs);
    uint32_t sR = (uint32_t)__cvta_generic_to_shared(Rs);
    uint32_t aoff = ((w * 16 + ((l >> 3) & 1) * 8 + (l & 7)) * 68 + ((l >> 4) & 1) * 4) * 4;
    uint32_t boff = ((((l >> 4) & 1) * 8 + (l & 7)) * 68 + ((l >> 3) & 1) * 4) * 4;

    uint32_t qa[8][4];
#pragma unroll
    for (int k8 = 0; k8 < 8; k8++) ldsm4(qa[k8], sQ + aoff + k8 * 32);

    float acc[16][4] = {};
#pragma unroll
    for (int k8 = 0; k8 < 8; k8++)
#pragma unroll
        for (int np = 0; np < 8; np++) {
            uint32_t kb[4];
            ldsm4(kb, sR + boff + np * 16 * 272 + k8 * 32);
            mma8(acc[2 * np],     qa[k8], kb,     acc[2 * np]);
            mma8(acc[2 * np + 1], qa[k8], kb + 2, acc[2 * np + 1]);
        }

    float* out = g_bd + (size_t)bh * S_ * S_;
    int gr = i0 + w * 16 + (l >> 2);
#pragma unroll
    for (int nt = 0; nt < 16; nt++) {
        int gc = t0 + nt * 8 + 2 * (l & 3);
        bd_store_pair(out, gr,     gc, acc[nt][0], acc[nt][1]);
        bd_store_pair(out, gr + 8, gc, acc[nt][2], acc[nt][3]);
    }
}

// ============================================================
// Fused attention, all-fp16 mma paths, K/V DOUBLE-BUFFERED
// (prefetch 2 iters ahead, 2 barriers/iter). BD is pre-shifted:
// row-linear aligned float2 loads + j==row+1 zero mask.
// smem 90 KB, 2 CTAs/SM.
// ============================================================
__global__ __launch_bounds__(256, 2) void fattn(const float* __restrict__ pbu)
{
    extern __shared__ __half smh[];
    __half* Qsh = smh;                      // 128 x 72 fp16 (persistent)
    // K bufs: [9216, 18432), [18432, 27648)   (halves)
    // V bufs: [27648, 36864), [36864, 46080)
    int tid = threadIdx.x, l = tid & 31, w = tid >> 5;
    int bh = blockIdx.y, b = bh >> 4, h = bh & 15;
    int i0 = blockIdx.x * 128;
    const float*  Qg = g_qkv + (size_t)b * QLD_ + h * 64;
    const __half* Kg = g_kh + (size_t)b * 1024 + h * 64;   // row stride 2048
    const __half* Vg = g_vh + (size_t)b * 1024 + h * 64;   // row stride 2048
    const float*  bd = g_bd + (size_t)bh * S_ * S_;
    const float* bias = pbu + h * 64;
    uint32_t sQ     = (uint32_t)__cvta_generic_to_shared(Qsh);
    uint32_t sKbase = (uint32_t)__cvta_generic_to_shared(smh + 9216);
    uint32_t sVbase = (uint32_t)__cvta_generic_to_shared(smh + 27648);

    // (q + bias_u) -> fp16 smem
#pragma unroll
    for (int t = 0; t < 8; t++) {
        int idx = tid + t * 256; int r = idx >> 4, c4 = (idx & 15) << 2;
        float4 a4 = *(const float4*)(Qg + (size_t)(i0 + r) * ARS_ + c4);
        float4 u4 = *(const float4*)(bias + c4);
        *(__half2*)(Qsh + r * 72 + c4)     = __floats2half2_rn(a4.x + u4.x, a4.y + u4.y);
        *(__half2*)(Qsh + r * 72 + c4 + 2) = __floats2half2_rn(a4.z + u4.z, a4.w + u4.w);
    }

// one cp.async group = K(IT)+V(IT) into buffer offset BO (bytes)
#define PFKV(IT, BO)                                                            \
    {                                                                           \
        const __half* kn = Kg + (size_t)((IT) * 128) * 2048;                    \
        const __half* vn = Vg + (size_t)((IT) * 128) * 2048;                    \
        _Pragma("unroll")                                                       \
        for (int t = 0; t < 4; t++) {                                           \
            int idx = tid + t * 256; int r = idx >> 3, c8 = (idx & 7) << 3;     \
            cpa16(sKbase + (BO) + (r * 72 + c8) * 2, kn + (size_t)r * 2048 + c8);\
            cpa16(sVbase + (BO) + (r * 72 + c8) * 2, vn + (size_t)r * 2048 + c8);\
        }                                                                       \
        cpcommit();                                                             \
    }

    PFKV(0, 0)
    PFKV(1, 18432)

    // fragment offsets (within one K/V buffer)
    uint32_t qoff  = (uint32_t)((w * 16 + (l & 7) + ((l >> 3) & 1) * 8) * 144
                                + ((l >> 4) & 1) * 16);
    uint32_t kboff = (uint32_t)(((l & 7) + (l >> 4) * 8) * 144 + ((l >> 3) & 1) * 16);
    uint32_t vrbase = (uint32_t)((l & 7) + ((l >> 3) & 1) * 8);
    uint32_t vcoff  = (uint32_t)((l >> 4) * 8);

    float o[8][4] = {};
    float bdbuf[32];
    float mrow0 = -1e30f, mrow1 = -1e30f, lsum0 = 0.f, lsum1 = 0.f;
    int tc = l & 3;
    int lr0 = w * 16 + (l >> 2);
    int row0 = i0 + lr0, row1 = row0 + 8;
    const float CS = 0.1803368801111204f;   // 0.125 * log2(e)

// pre-shifted BD: row-linear aligned float2 loads, mask j==row+1 -> 0
#define LDBD(JB)                                                                \
    _Pragma("unroll")                                                           \
    for (int nt = 0; nt < 8; nt++) {                                            \
        int c0 = (JB) + nt * 8 + 2 * tc;                                        \
        float2 v0 = __ldcs((const float2*)(bd + (size_t)row0 * S_ + c0));       \
        float2 v1 = __ldcs((const float2*)(bd + (size_t)row1 * S_ + c0));       \
        bdbuf[nt * 4 + 0] = (c0     == row0 + 1) ? 0.f : v0.x;                  \
        bdbuf[nt * 4 + 1] = (c0 + 1 == row0 + 1) ? 0.f : v0.y;                  \
        bdbuf[nt * 4 + 2] = (c0     == row1 + 1) ? 0.f : v1.x;                  \
        bdbuf[nt * 4 + 3] = (c0 + 1 == row1 + 1) ? 0.f : v1.y;                  \
    }

    LDBD(0)              // BD for iter0/half0 — overlaps K0/V0 arrival

#define AC_MMA(HALF)                                                            \
    _Pragma("unroll")                                                           \
    for (int nt = 0; nt < 8; nt++)                                              \
        p[nt][0] = p[nt][1] = p[nt][2] = p[nt][3] = 0.f;                        \
    _Pragma("unroll")                                                           \
    for (int ks = 0; ks < 4; ks++) {                                            \
        uint32_t qf[4];                                                         \
        ldsm4(qf, sQ + qoff + ks * 32);                                         \
        _Pragma("unroll")                                                       \
        for (int np = 0; np < 4; np++) {                                        \
            uint32_t kb[4];                                                     \
            ldsm4(kb, sK + kboff + ((HALF) * 64 + np * 16) * 144 + ks * 32);    \
            mma16h(p[2 * np],     qf, kb,     p[2 * np]);                       \
            mma16h(p[2 * np + 1], qf, kb + 2, p[2 * np + 1]);                   \
        }                                                                       \
    }

#define SOFTMAX_STEP()                                                          \
    {                                                                           \
        float mx0 = -1e30f, mx1 = -1e30f;                                       \
        _Pragma("unroll")                                                       \
        for (int nt = 0; nt < 8; nt++) {                                        \
            float s;                                                            \
            s = (p[nt][0] + bdbuf[nt*4+0]) * CS; p[nt][0] = s; mx0 = fmaxf(mx0, s); \
            s = (p[nt][1] + bdbuf[nt*4+1]) * CS; p[nt][1] = s; mx0 = fmaxf(mx0, s); \
            s = (p[nt][2] + bdbuf[nt*4+2]) * CS; p[nt][2] = s; mx1 = fmaxf(mx1, s); \
            s = (p[nt][3] + bdbuf[nt*4+3]) * CS; p[nt][3] = s; mx1 = fmaxf(mx1, s); \
        }                                                                       \
        mx0 = fmaxf(mx0, __shfl_xor_sync(~0u, mx0, 1));                         \
        mx0 = fmaxf(mx0, __shfl_xor_sync(~0u, mx0, 2));                         \
        mx1 = fmaxf(mx1, __shfl_xor_sync(~0u, mx1, 1));                         \
        mx1 = fmaxf(mx1, __shfl_xor_sync(~0u, mx1, 2));                         \
        float mn0 = fmaxf(mrow0, mx0), mn1 = fmaxf(mrow1, mx1);                 \
        float al0 = ex2(mrow0 - mn0), al1 = ex2(mrow1 - mn1);                   \
        mrow0 = mn0; mrow1 = mn1;                                               \
        float rs0 = 0.f, rs1 = 0.f;                                             \
        _Pragma("unroll")                                                       \
        for (int nt = 0; nt < 8; nt++) {                                        \
            p[nt][0] = ex2(p[nt][0] - mn0); p[nt][1] = ex2(p[nt][1] - mn0);     \
            p[nt][2] = ex2(p[nt][2] - mn1); p[nt][3] = ex2(p[nt][3] - mn1);     \
            rs0 += p[nt][0] + p[nt][1]; rs1 += p[nt][2] + p[nt][3];             \
        }                                                                       \
        rs0 += __shfl_xor_sync(~0u, rs0, 1); rs0 += __shfl_xor_sync(~0u, rs0, 2);\
        rs1 += __shfl_xor_sync(~0u, rs1, 1); rs1 += __shfl_xor_sync(~0u, rs1, 2);\
        lsum0 = lsum0 * al0 + rs0;                                              \
        lsum1 = lsum1 * al1 + rs1;                                              \
        _Pragma("unroll")                                                       \
        for (int nt = 0; nt < 8; nt++) {                                        \
            o[nt][0] *= al0; o[nt][1] *= al0; o[nt][2] *= al1; o[nt][3] *= al1; \
        }                                                                       \
    }

#define CVT_P()                                                                 \
    uint32_t af[4][4];                                                          \
    _Pragma("unroll")                                                           \
    for (int ks = 0; ks < 4; ks++) {                                            \
        af[ks][0] = h2(p[2*ks][0],   p[2*ks][1]);                               \
        af[ks][1] = h2(p[2*ks][2],   p[2*ks][3]);                               \
        af[ks][2] = h2(p[2*ks+1][0], p[2*ks+1][1]);                             \
        af[ks][3] = h2(p[2*ks+1][2], p[2*ks+1][3]);                             \
    }

#define PV16(HALF)                                                              \
    _Pragma("unroll")                                                           \
    for (int ks = 0; ks < 4; ks++) {                                            \
        uint32_t vrow = (uint32_t)((HALF) * 64 + ks * 16) + vrbase;             \
        _Pragma("unroll")                                                       \
        for (int ntt = 0; ntt < 4; ntt++) {                                     \
            uint32_t vb[4];                                                     \
            ldsm4t(vb, sV + (vrow * 72 + ntt * 16 + vcoff) * 2);                \
            mma16h(o[2*ntt],   af[ks], vb,   o[2*ntt]);                         \
            mma16h(o[2*ntt+1], af[ks], vb+2, o[2*ntt+1]);                       \
        }                                                                       \
    }

    for (int it = 0; it < 16; it++) {
        uint32_t bo = (uint32_t)(it & 1) * 18432;
        uint32_t sK = sKbase + bo;
        uint32_t sV = sVbase + bo;
        if (it == 15) cpwait<0>(); else cpwait<1>();   // K/V(it) landed
        __syncthreads();      // buffers + (iter0) Qsh visible to all warps

        {   // ---- half 0 ----
            float p[8][4];
            AC_MMA(0)
            SOFTMAX_STEP()
            CVT_P()
            LDBD(it * 128 + 64)       // BD half1 — covered by PV0 + AC1
            PV16(0)
        }
        {   // ---- half 1 ----
            float p[8][4];
            AC_MMA(1)
            SOFTMAX_STEP()
            CVT_P()
            if (it + 1 < 16) LDBD((it + 1) * 128)   // next iter's BD half0
            PV16(1)
        }
        __syncthreads();      // all warps done reading this buffer
        if (it + 2 < 16) PFKV(it + 2, bo)   // refill freed buffer
    }
#undef PFKV
#undef LDBD
#undef AC_MMA
#undef SOFTMAX_STEP
#undef CVT_P
#undef PV16

    float inv0 = 1.f / lsum0, inv1 = 1.f / lsum1;
#pragma unroll
    for (int nt = 0; nt < 8; nt++) {
        int c = h * 64 + nt * 8 + 2 * tc;
        *(float2*)(g_att + ((size_t)row0 * B_ + b) * D_ + c) =
            make_float2(o[nt][0] * inv0, o[nt][1] * inv0);
        *(float2*)(g_att + ((size_t)row1 * B_ + b) * D_ + c) =
            make_float2(o[nt][2] * inv1, o[nt][3] * inv1);
    }
}

// ============================================================
// LayerNorm over D=1024 per row.
// ============================================================
__global__ __launch_bounds__(256) void ln_k(const float* __restrict__ gamma,
                                            const float* __restrict__ beta,
                                            float* __restrict__ out)
{
    __shared__ float reds[8], redq[8];
    const float* y = g_y + (size_t)blockIdx.x * D_;
    int tid = threadIdx.x;
    float v[4];
    float s = 0.f, q = 0.f;
#pragma unroll
    for (int t = 0; t < 4; t++) {
        v[t] = y[tid + t * 256];
        s += v[t]; q += v[t] * v[t];
    }
#pragma unroll
    for (int o = 16; o; o >>= 1) {
        s += __shfl_xor_sync(0xffffffffu, s, o);
        q += __shfl_xor_sync(0xffffffffu, q, o);
    }
    if ((tid & 31) == 0) { reds[tid >> 5] = s; redq[tid >> 5] = q; }
    __syncthreads();
    float ts = 0.f, tq = 0.f;
#pragma unroll
    for (int wv = 0; wv < 8; wv++) { ts += reds[wv]; tq += redq[wv]; }
    float mu = ts * (1.f / 1024.f);
    float var = tq * (1.f / 1024.f) - mu * mu;
    float inv = rsqrtf(var + 1e-5f);
    float* op = out + (size_t)blockIdx.x * D_;
#pragma unroll
    for (int t = 0; t < 4; t++) {
        int c = tid + t * 256;
        op[c] = (v[t] - mu) * inv * gamma[c] + beta[c];
    }
}

// ============================================================
extern "C" void kernel_launch(void* const* d_in, const int* in_sizes, int n_in,
                              void* d_out, int out_size)
{
    const float* x    = (const float*)d_in[0];
    const float* pe   = (const float*)d_in[1];
    const float* pbu  = (const float*)d_in[2];
    const float* pbv  = (const float*)d_in[3];
    const float* Wqkv = (const float*)d_in[4];
    const float* Wrel = (const float*)d_in[5];
    const float* Wo   = (const float*)d_in[6];
    const float* gam  = (const float*)d_in[7];
    const float* bet  = (const float*)d_in[8];
    float* out = (float*)d_out;

    const int PG_SMEM = 71680;     // (9216 + 8704) * 4
    const int BD_SMEM = 69632;     // 2 * 128*68 * 4
    const int FA_SMEM = 92160;     // (9216 + 4*9216) halves * 2B
    cudaFuncSetAttribute(pgemm<0>, cudaFuncAttributeMaxDynamicSharedMemorySize, PG_SMEM);
    cudaFuncSetAttribute(pgemm<1>, cudaFuncAttributeMaxDynamicSharedMemorySize, PG_SMEM);
    cudaFuncSetAttribute(pgemm<2>, cudaFuncAttributeMaxDynamicSharedMemorySize, PG_SMEM);
    cudaFuncSetAttribute(bd_gemm,  cudaFuncAttributeMaxDynamicSharedMemorySize, BD_SMEM);
    cudaFuncSetAttribute(fattn,    cudaFuncAttributeMaxDynamicSharedMemorySize, FA_SMEM);

    // 1) qkv = x @ W_qkv  (q -> f32; k,v -> fp16)
    pgemm<0><<<dim3(24, 32), 256, PG_SMEM>>>(x, Wqkv, nullptr, 3072);
    // 2) r = pos_emb @ W_relemb
    pgemm<1><<<dim3(8, 16), 256, PG_SMEM>>>(pe, Wrel, nullptr, 1024);
    // 3) pre-shifted Draw = (q + pbv) @ r^T per (b,h)
    bd_gemm<<<dim3(16, 16, 32), 256, BD_SMEM>>>(pbv);
    // 4) fused: scores + shifted-BD add + softmax + PV
    fattn<<<dim3(16, 32), 256, FA_SMEM>>>(pbu);
    // 5) y = x + attn_vec @ W_o
    pgemm<2><<<dim3(8, 32), 256, PG_SMEM>>>(nullptr, Wo, x, 1024);
    // 6) layernorm
    ln_k<<<4096, 256>>>(gam, bet, out);
}

// round 12
// speedup vs baseline: 1.5598x; 1.0876x over previous
#include <cuda_runtime.h>
#include <cuda_fp16.h>
#include <stdint.h>

#define S_    2048
#define B_    2
#define D_    1024
#define H_    16
#define BH_   32
#define ROWS_ 4096
#define QLD_  3072
#define ARS_  6144   // B_*QLD_ : stride between seq rows in g_qkv

// ---- scratch (static device globals; no allocation) ----
__device__ float  g_qkv[(size_t)ROWS_ * 3072];         // q cols f32 (k,v blocks unused)
__device__ __half g_kh [(size_t)ROWS_ * 1024];         // K fp16 [s*B+b][h*64+d]
__device__ __half g_vh [(size_t)ROWS_ * 1024];         // V fp16 [s*B+b][h*64+d]
__device__ float  g_r  [(size_t)S_ * D_];              // [t][h*64+d]
__device__ float  g_bd [(size_t)BH_ * S_ * S_];        // PRE-SHIFTED BD per (b,h), f32
__device__ float  g_att[(size_t)ROWS_ * D_];           // attn_vec
__device__ float  g_y  [(size_t)ROWS_ * D_];           // x + attn_out

// ---------------- mma / cp.async / ldmatrix helpers ----------------
__device__ __forceinline__ void mma8(float* d, const uint32_t* a,
                                     const uint32_t* b, const float* c) {
    asm volatile(
        "mma.sync.aligned.m16n8k8.row.col.f32.tf32.tf32.f32 "
        "{%0,%1,%2,%3}, {%4,%5,%6,%7}, {%8,%9}, {%10,%11,%12,%13};\n"
        : "=f"(d[0]), "=f"(d[1]), "=f"(d[2]), "=f"(d[3])
        : "r"(a[0]), "r"(a[1]), "r"(a[2]), "r"(a[3]), "r"(b[0]), "r"(b[1]),
          "f"(c[0]), "f"(c[1]), "f"(c[2]), "f"(c[3]));
}
__device__ __forceinline__ void mma16h(float* d, const uint32_t* a,
                                       const uint32_t* b, const float* c) {
    asm volatile(
        "mma.sync.aligned.m16n8k16.row.col.f32.f16.f16.f32 "
        "{%0,%1,%2,%3}, {%4,%5,%6,%7}, {%8,%9}, {%10,%11,%12,%13};\n"
        : "=f"(d[0]), "=f"(d[1]), "=f"(d[2]), "=f"(d[3])
        : "r"(a[0]), "r"(a[1]), "r"(a[2]), "r"(a[3]), "r"(b[0]), "r"(b[1]),
          "f"(c[0]), "f"(c[1]), "f"(c[2]), "f"(c[3]));
}
__device__ __forceinline__ uint32_t f2u(float x) { return __float_as_uint(x); }
__device__ __forceinline__ uint32_t h2(float lo, float hi) {
    uint32_t d;
    asm("cvt.rn.f16x2.f32 %0, %1, %2;\n" : "=r"(d) : "f"(hi), "f"(lo));
    return d;   // d.lo = lo, d.hi = hi
}
__device__ __forceinline__ void cpa16(uint32_t s, const void* g) {
    asm volatile("cp.async.cg.shared.global [%0], [%1], 16;\n" :: "r"(s), "l"(g));
}
__device__ __forceinline__ void cpcommit() { asm volatile("cp.async.commit_group;\n"); }
template <int N> __device__ __forceinline__ void cpwait() {
    asm volatile("cp.async.wait_group %0;\n" :: "n"(N));
}
__device__ __forceinline__ void ldsm4(uint32_t* r, uint32_t a) {
    asm volatile("ldmatrix.sync.aligned.m8n8.x4.shared.b16 {%0,%1,%2,%3}, [%4];\n"
        : "=r"(r[0]), "=r"(r[1]), "=r"(r[2]), "=r"(r[3]) : "r"(a));
}
__device__ __forceinline__ void ldsm4t(uint32_t* r, uint32_t a) {
    asm volatile("ldmatrix.sync.aligned.m8n8.x4.trans.shared.b16 {%0,%1,%2,%3}, [%4];\n"
        : "=r"(r[0]), "=r"(r[1]), "=r"(r[2]), "=r"(r[3]) : "r"(a));
}
__device__ __forceinline__ float ex2(float x) {
    float y; asm("ex2.approx.f32 %0, %1;" : "=f"(y) : "f"(x)); return y;
}

// ============================================================
// Projection GEMM, K=1024 fixed, tile 128x128x32, cp.async 2-stage.
// MODE 0: q cols -> g_qkv f32, K cols -> g_kh fp16, V cols -> g_vh fp16
// MODE 1: g_r = A@B    MODE 2: g_y = g_att@B + Xres
// ============================================================
template <int MODE>
__global__ __launch_bounds__(256) void pgemm(const float* __restrict__ A,
                                             const float* __restrict__ Bw,
                                             const float* __restrict__ Xres,
                                             int N)
{
    extern __shared__ float sm[];
    float* As = sm;               // 2 x 128 x 36
    float* Bs = sm + 9216;        // 2 x 32  x 136
    const float* Ap = (MODE == 2) ? (const float*)g_att : A;
    float* C = (MODE == 0) ? g_qkv : (MODE == 1) ? g_r : g_y;

    int tid = threadIdx.x, l = tid & 31, w = tid >> 5, wm = w >> 1, wn = w & 1;
    size_t m0 = (size_t)blockIdx.y * 128, n0 = (size_t)blockIdx.x * 128;
    uint32_t sA = (uint32_t)__cvta_generic_to_shared(As);
    uint32_t sB = (uint32_t)__cvta_generic_to_shared(Bs);

    float acc[2][8][4] = {};

#define STAGE(IT, BUF)                                                          \
    {                                                                           \
        int kk = (IT) * 32;                                                     \
        uint32_t ab = sA + (BUF) * 4608 * 4;                                    \
        _Pragma("unroll")                                                       \
        for (int t = 0; t < 4; t++) {                                           \
            int idx = tid + t * 256; int r = idx >> 3, c4 = (idx & 7) << 2;     \
            cpa16(ab + (r * 36 + c4) * 4, Ap + (m0 + r) * 1024 + kk + c4);      \
        }                                                                       \
        uint32_t bb = sB + (BUF) * 4352 * 4;                                    \
        _Pragma("unroll")                                                       \
        for (int t = 0; t < 4; t++) {                                           \
            int idx = tid + t * 256; int r = idx >> 5, c4 = (idx & 31) << 2;    \
            cpa16(bb + (r * 136 + c4) * 4, Bw + (size_t)(kk + r) * N + n0 + c4);\
        }                                                                       \
        cpcommit();                                                             \
    }

    STAGE(0, 0);
    for (int it = 0; it < 32; it++) {
        int buf = it & 1;
        if (it + 1 < 32) { STAGE(it + 1, buf ^ 1); cpwait<1>(); }
        else             { cpwait<0>(); }
        __syncthreads();
        const float* As_ = As + buf * 4608;
        const float* Bs_ = Bs + buf * 4352;
#pragma unroll
        for (int k8 = 0; k8 < 4; k8++) {
            uint32_t a[2][4];
#pragma unroll
            for (int mt = 0; mt < 2; mt++) {
                int r = wm * 32 + mt * 16 + (l >> 2);
                a[mt][0] = f2u(As_[r * 36 + k8 * 8 + (l & 3)]);
                a[mt][1] = f2u(As_[(r + 8) * 36 + k8 * 8 + (l & 3)]);
                a[mt][2] = f2u(As_[r * 36 + k8 * 8 + (l & 3) + 4]);
                a[mt][3] = f2u(As_[(r + 8) * 36 + k8 * 8 + (l & 3) + 4]);
            }
#pragma unroll
            for (int nt = 0; nt < 8; nt++) {
                uint32_t bf[2];
                int cb = wn * 64 + nt * 8 + (l >> 2);
                bf[0] = f2u(Bs_[(k8 * 8 + (l & 3)) * 136 + cb]);
                bf[1] = f2u(Bs_[(k8 * 8 + (l & 3) + 4) * 136 + cb]);
#pragma unroll
                for (int mt = 0; mt < 2; mt++)
                    mma8(acc[mt][nt], a[mt], bf, acc[mt][nt]);
            }
        }
        __syncthreads();
    }
#undef STAGE

    if (MODE == 0 && n0 >= 1024) {
        // K / V columns: write fp16 copies only (f32 never read)
        __half* dst = (n0 >= 2048) ? g_vh : g_kh;
        size_t cb = n0 - ((n0 >= 2048) ? 2048 : 1024);
#pragma unroll
        for (int mt = 0; mt < 2; mt++) {
            size_t r0 = m0 + wm * 32 + mt * 16 + (l >> 2);
#pragma unroll
            for (int nt = 0; nt < 8; nt++) {
                size_t c = cb + wn * 64 + nt * 8 + 2 * (l & 3);
                *(__half2*)(dst + r0 * 1024 + c) =
                    __floats2half2_rn(acc[mt][nt][0], acc[mt][nt][1]);
                *(__half2*)(dst + (r0 + 8) * 1024 + c) =
                    __floats2half2_rn(acc[mt][nt][2], acc[mt][nt][3]);
            }
        }
        return;
    }
#pragma unroll
    for (int mt = 0; mt < 2; mt++) {
        size_t r0 = m0 + wm * 32 + mt * 16 + (l >> 2);
#pragma unroll
        for (int nt = 0; nt < 8; nt++) {
            size_t c = n0 + wn * 64 + nt * 8 + 2 * (l & 3);
            float2 v0 = make_float2(acc[mt][nt][0], acc[mt][nt][1]);
            float2 v1 = make_float2(acc[mt][nt][2], acc[mt][nt][3]);
            if (MODE == 2) {
                float2 x0 = *(const float2*)(Xres + r0 * N + c);
                float2 x1 = *(const float2*)(Xres + (r0 + 8) * N + c);
                v0.x += x0.x; v0.y += x0.y; v1.x += x1.x; v1.y += x1.y;
            }
            *(float2*)(C + r0 * N + c) = v0;
            *(float2*)(C + (r0 + 8) * N + c) = v1;
        }
    }
}

// ============================================================
// Draw = (q + pos_bias_v) @ r^T per (b,h), stored PRE-SHIFTED.
// Shift map (single expression): for Draw cell (i, t),
//   tcol = t + i + 1;  if tcol >= S -> (row i,   col tcol - S)
//                      else        -> (row i-1, col tcol)  [dropped if i==0]
// Row i's column j=i+1 is never written (rel-shift zero; fattn masks).
// Epilogue stages the tile in smem then does warp-per-row coalesced
// streaming stores (lane l -> col l+32j: consecutive addresses).
// ============================================================
__global__ __launch_bounds__(256, 2) void bd_gemm(const float* __restrict__ pbv)
{
    extern __shared__ float sm[];
    float* Qs = sm;               // 128 x 68
    float* Rs = sm + 8704;        // 128 x 68
    int tid = threadIdx.x, l = tid & 31, w = tid >> 5;
    int bh = blockIdx.z, b = bh >> 4, h = bh & 15;
    int i0 = blockIdx.y * 128, t0 = blockIdx.x * 128;
    const float* Qg = g_qkv + (size_t)b * QLD_ + h * 64;
    const float* Rg = g_r + h * 64;
    const float* bias = pbv + h * 64;

#pragma unroll
    for (int t = 0; t < 8; t++) {
        int idx = tid + t * 256; int r = idx >> 4, c4 = (idx & 15) << 2;
        float4 a4 = *(const float4*)(Qg + (size_t)(i0 + r) * ARS_ + c4);
        float4 u4 = *(const float4*)(bias + c4);
        a4.x += u4.x; a4.y += u4.y; a4.z += u4.z; a4.w += u4.w;
        *(float4*)&Qs[r * 68 + c4] = a4;
        *(float4*)&Rs[r * 68 + c4] = *(const float4*)(Rg + (size_t)(t0 + r) * D_ + c4);
    }
    __syncthreads();

    uint32_t sQ = (uint32_t)__cvta_generic_to_shared(Qs);
    uint32_t sR = (uint32_t)__cvta_generic_to_shared(Rs);
    uint32_t aoff = ((w * 16 + ((l >> 3) & 1) * 8 + (l & 7)) * 68 + ((l >> 4) & 1) * 4) * 4;
    uint32_t boff = ((((l >> 4) & 1) * 8 + (l & 7)) * 68 + ((l >> 3) & 1) * 4) * 4;

    uint32_t qa[8][4];
#pragma unroll
    for (int k8 = 0; k8 < 8; k8++) ldsm4(qa[k8], sQ + aoff + k8 * 32);

    float acc[16][4] = {};
#pragma unroll
    for (int k8 = 0; k8 < 8; k8++)
#pragma unroll
        for (int np = 0; np < 8; np++) {
            uint32_t kb[4];
            ldsm4(kb, sR + boff + np * 16 * 272 + k8 * 32);
            mma8(acc[2 * np],     qa[k8], kb,     acc[2 * np]);
            mma8(acc[2 * np + 1], qa[k8], kb + 2, acc[2 * np + 1]);
        }

    // ---- stage tile in smem (Qs/Rs dead), then coalesced shifted stores ----
    __syncthreads();                       // all ldsm4 reads done
    float* stage = sm;                     // 128 x 132 = 67584 B
    int lr0 = w * 16 + (l >> 2);
#pragma unroll
    for (int nt = 0; nt < 16; nt++) {
        int c = nt * 8 + 2 * (l & 3);
        *(float2*)&stage[lr0 * 132 + c]       = make_float2(acc[nt][0], acc[nt][1]);
        *(float2*)&stage[(lr0 + 8) * 132 + c] = make_float2(acc[nt][2], acc[nt][3]);
    }
    __syncthreads();

    float* out = g_bd + (size_t)bh * S_ * S_;
#pragma unroll
    for (int rr = 0; rr < 16; rr++) {
        int r = w * 16 + rr;               // local row in tile
        int gi = i0 + r;                   // global Draw row i
        int base = t0 + gi + 1;
#pragma unroll
        for (int j = 0; j < 4; j++) {
            int c = l + 32 * j;
            int tcol = base + c;
            float v = stage[r * 132 + c];
            if (tcol >= S_)      __stcs(out + (size_t)gi * S_ + (tcol - S_), v);
            else if (gi > 0)     __stcs(out + (size_t)(gi - 1) * S_ + tcol, v);
        }
    }
}

// ============================================================
// Fused attention, all-fp16 mma paths, K/V double-buffered,
// pre-shifted BD: row-linear float2 loads + j==row+1 zero mask.
// smem 90 KB, 2 CTAs/SM.  (unchanged from R11)
// ============================================================
__global__ __launch_bounds__(256, 2) void fattn(const float* __restrict__ pbu)
{
    extern __shared__ __half smh[];
    __half* Qsh = smh;                      // 128 x 72 fp16 (persistent)
    int tid = threadIdx.x, l = tid & 31, w = tid >> 5;
    int bh = blockIdx.y, b = bh >> 4, h = bh & 15;
    int i0 = blockIdx.x * 128;
    const float*  Qg = g_qkv + (size_t)b * QLD_ + h * 64;
    const __half* Kg = g_kh + (size_t)b * 1024 + h * 64;   // row stride 2048
    const __half* Vg = g_vh + (size_t)b * 1024 + h * 64;   // row stride 2048
    const float*  bd = g_bd + (size_t)bh * S_ * S_;
    const float* bias = pbu + h * 64;
    uint32_t sQ     = (uint32_t)__cvta_generic_to_shared(Qsh);
    uint32_t sKbase = (uint32_t)__cvta_generic_to_shared(smh + 9216);
    uint32_t sVbase = (uint32_t)__cvta_generic_to_shared(smh + 27648);

    // (q + bias_u) -> fp16 smem
#pragma unroll
    for (int t = 0; t < 8; t++) {
        int idx = tid + t * 256; int r = idx >> 4, c4 = (idx & 15) << 2;
        float4 a4 = *(const float4*)(Qg + (size_t)(i0 + r) * ARS_ + c4);
        float4 u4 = *(const float4*)(bias + c4);
        *(__half2*)(Qsh + r * 72 + c4)     = __floats2half2_rn(a4.x + u4.x, a4.y + u4.y);
        *(__half2*)(Qsh + r * 72 + c4 + 2) = __floats2half2_rn(a4.z + u4.z, a4.w + u4.w);
    }

#define PFKV(IT, BO)                                                            \
    {                                                                           \
        const __half* kn = Kg + (size_t)((IT) * 128) * 2048;                    \
        const __half* vn = Vg + (size_t)((IT) * 128) * 2048;                    \
        _Pragma("unroll")                                                       \
        for (int t = 0; t < 4; t++) {                                           \
            int idx = tid + t * 256; int r = idx >> 3, c8 = (idx & 7) << 3;     \
            cpa16(sKbase + (BO) + (r * 72 + c8) * 2, kn + (size_t)r * 2048 + c8);\
            cpa16(sVbase + (BO) + (r * 72 + c8) * 2, vn + (size_t)r * 2048 + c8);\
        }                                                                       \
        cpcommit();                                                             \
    }

    PFKV(0, 0)
    PFKV(1, 18432)

    uint32_t qoff  = (uint32_t)((w * 16 + (l & 7) + ((l >> 3) & 1) * 8) * 144
                                + ((l >> 4) & 1) * 16);
    uint32_t kboff = (uint32_t)(((l & 7) + (l >> 4) * 8) * 144 + ((l >> 3) & 1) * 16);
    uint32_t vrbase = (uint32_t)((l & 7) + ((l >> 3) & 1) * 8);
    uint32_t vcoff  = (uint32_t)((l >> 4) * 8);

    float o[8][4] = {};
    float bdbuf[32];
    float mrow0 = -1e30f, mrow1 = -1e30f, lsum0 = 0.f, lsum1 = 0.f;
    int tc = l & 3;
    int lr0 = w * 16 + (l >> 2);
    int row0 = i0 + lr0, row1 = row0 + 8;
    const float CS = 0.1803368801111204f;   // 0.125 * log2(e)

#define LDBD(JB)                                                                \
    _Pragma("unroll")                                                           \
    for (int nt = 0; nt < 8; nt++) {                                            \
        int c0 = (JB) + nt * 8 + 2 * tc;                                        \
        float2 v0 = __ldcs((const float2*)(bd + (size_t)row0 * S_ + c0));       \
        float2 v1 = __ldcs((const float2*)(bd + (size_t)row1 * S_ + c0));       \
        bdbuf[nt * 4 + 0] = (c0     == row0 + 1) ? 0.f : v0.x;                  \
        bdbuf[nt * 4 + 1] = (c0 + 1 == row0 + 1) ? 0.f : v0.y;                  \
        bdbuf[nt * 4 + 2] = (c0     == row1 + 1) ? 0.f : v1.x;                  \
        bdbuf[nt * 4 + 3] = (c0 + 1 == row1 + 1) ? 0.f : v1.y;                  \
    }

    LDBD(0)

#define AC_MMA(HALF)                                                            \
    _Pragma("unroll")                                                           \
    for (int nt = 0; nt < 8; nt++)                                              \
        p[nt][0] = p[nt][1] = p[nt][2] = p[nt][3] = 0.f;                        \
    _Pragma("unroll")                                                           \
    for (int ks = 0; ks < 4; ks++) {                                            \
        uint32_t qf[4];                                                         \
        ldsm4(qf, sQ + qoff + ks * 32);                                         \
        _Pragma("unroll")                                                       \
        for (int np = 0; np < 4; np++) {                                        \
            uint32_t kb[4];                                                     \
            ldsm4(kb, sK + kboff + ((HALF) * 64 + np * 16) * 144 + ks * 32);    \
            mma16h(p[2 * np],     qf, kb,     p[2 * np]);                       \
            mma16h(p[2 * np + 1], qf, kb + 2, p[2 * np + 1]);                   \
        }                                                                       \
    }

#define SOFTMAX_STEP()                                                          \
    {                                                                           \
        float mx0 = -1e30f, mx1 = -1e30f;                                       \
        _Pragma("unroll")                                                       \
        for (int nt = 0; nt < 8; nt++) {                                        \
            float s;                                                            \
            s = (p[nt][0] + bdbuf[nt*4+0]) * CS; p[nt][0] = s; mx0 = fmaxf(mx0, s); \
            s = (p[nt][1] + bdbuf[nt*4+1]) * CS; p[nt][1] = s; mx0 = fmaxf(mx0, s); \
            s = (p[nt][2] + bdbuf[nt*4+2]) * CS; p[nt][2] = s; mx1 = fmaxf(mx1, s); \
            s = (p[nt][3] + bdbuf[nt*4+3]) * CS; p[nt][3] = s; mx1 = fmaxf(mx1, s); \
        }                                                                       \
        mx0 = fmaxf(mx0, __shfl_xor_sync(~0u, mx0, 1));                         \
        mx0 = fmaxf(mx0, __shfl_xor_sync(~0u, mx0, 2));                         \
        mx1 = fmaxf(mx1, __shfl_xor_sync(~0u, mx1, 1));                         \
        mx1 = fmaxf(mx1, __shfl_xor_sync(~0u, mx1, 2));                         \
        float mn0 = fmaxf(mrow0, mx0), mn1 = fmaxf(mrow1, mx1);                 \
        float al0 = ex2(mrow0 - mn0), al1 = ex2(mrow1 - mn1);                   \
        mrow0 = mn0; mrow1 = mn1;                                               \
        float rs0 = 0.f, rs1 = 0.f;                                             \
        _Pragma("unroll")                                                       \
        for (int nt = 0; nt < 8; nt++) {                                        \
            p[nt][0] = ex2(p[nt][0] - mn0); p[nt][1] = ex2(p[nt][1] - mn0);     \
            p[nt][2] = ex2(p[nt][2] - mn1); p[nt][3] = ex2(p[nt][3] - mn1);     \
            rs0 += p[nt][0] + p[nt][1]; rs1 += p[nt][2] + p[nt][3];             \
        }                                                                       \
        rs0 += __shfl_xor_sync(~0u, rs0, 1); rs0 += __shfl_xor_sync(~0u, rs0, 2);\
        rs1 += __shfl_xor_sync(~0u, rs1, 1); rs1 += __shfl_xor_sync(~0u, rs1, 2);\
        lsum0 = lsum0 * al0 + rs0;                                              \
        lsum1 = lsum1 * al1 + rs1;                                              \
        _Pragma("unroll")                                                       \
        for (int nt = 0; nt < 8; nt++) {                                        \
            o[nt][0] *= al0; o[nt][1] *= al0; o[nt][2] *= al1; o[nt][3] *= al1; \
        }                                                                       \
    }

#define CVT_P()                                                                 \
    uint32_t af[4][4];                                                          \
    _Pragma("unroll")                                                           \
    for (int ks = 0; ks < 4; ks++) {                                            \
        af[ks][0] = h2(p[2*ks][0],   p[2*ks][1]);                               \
        af[ks][1] = h2(p[2*ks][2],   p[2*ks][3]);                               \
        af[ks][2] = h2(p[2*ks+1][0], p[2*ks+1][1]);                             \
        af[ks][3] = h2(p[2*ks+1][2], p[2*ks+1][3]);                             \
    }

#define PV16(HALF)                                                              \
    _Pragma("unroll")                                                           \
    for (int ks = 0; ks < 4; ks++) {                                            \
        uint32_t vrow = (uint32_t)((HALF) * 64 + ks * 16) + vrbase;             \
        _Pragma("unroll")                                                       \
        for (int ntt = 0; ntt < 4; ntt++) {                                     \
            uint32_t vb[4];                                                     \
            ldsm4t(vb, sV + (vrow * 72 + ntt * 16 + vcoff) * 2);                \
            mma16h(o[2*ntt],   af[ks], vb,   o[2*ntt]);                         \
            mma16h(o[2*ntt+1], af[ks], vb+2, o[2*ntt+1]);                       \
        }                                                                       \
    }

    for (int it = 0; it < 16; it++) {
        uint32_t bo = (uint32_t)(it & 1) * 18432;
        uint32_t sK = sKbase + bo;
        uint32_t sV = sVbase + bo;
        if (it == 15) cpwait<0>(); else cpwait<1>();   // K/V(it) landed
        __syncthreads();

        {   // ---- half 0 ----
            float p[8][4];
            AC_MMA(0)
            SOFTMAX_STEP()
            CVT_P()
            LDBD(it * 128 + 64)
            PV16(0)
        }
        {   // ---- half 1 ----
            float p[8][4];
            AC_MMA(1)
            SOFTMAX_STEP()
            CVT_P()
            if (it + 1 < 16) LDBD((it + 1) * 128)
            PV16(1)
        }
        __syncthreads();
        if (it + 2 < 16) PFKV(it + 2, bo)
    }
#undef PFKV
#undef LDBD
#undef AC_MMA
#undef SOFTMAX_STEP
#undef CVT_P
#undef PV16

    float inv0 = 1.f / lsum0, inv1 = 1.f / lsum1;
#pragma unroll
    for (int nt = 0; nt < 8; nt++) {
        int c = h * 64 + nt * 8 + 2 * tc;
        *(float2*)(g_att + ((size_t)row0 * B_ + b) * D_ + c) =
            make_float2(o[nt][0] * inv0, o[nt][1] * inv0);
        *(float2*)(g_att + ((size_t)row1 * B_ + b) * D_ + c) =
            make_float2(o[nt][2] * inv1, o[nt][3] * inv1);
    }
}

// ============================================================
// LayerNorm over D=1024 per row.
// ============================================================
__global__ __launch_bounds__(256) void ln_k(const float* __restrict__ gamma,
                                            const float* __restrict__ beta,
                                            float* __restrict__ out)
{
    __shared__ float reds[8], redq[8];
    const float* y = g_y + (size_t)blockIdx.x * D_;
    int tid = threadIdx.x;
    float v[4];
    float s = 0.f, q = 0.f;
#pragma unroll
    for (int t = 0; t < 4; t++) {
        v[t] = y[tid + t * 256];
        s += v[t]; q += v[t] * v[t];
    }
#pragma unroll
    for (int o = 16; o; o >>= 1) {
        s += __shfl_xor_sync(0xffffffffu, s, o);
        q += __shfl_xor_sync(0xffffffffu, q, o);
    }
    if ((tid & 31) == 0) { reds[tid >> 5] = s; redq[tid >> 5] = q; }
    __syncthreads();
    float ts = 0.f, tq = 0.f;
#pragma unroll
    for (int wv = 0; wv < 8; wv++) { ts += reds[wv]; tq += redq[wv]; }
    float mu = ts * (1.f / 1024.f);
    float var = tq * (1.f / 1024.f) - mu * mu;
    float inv = rsqrtf(var + 1e-5f);
    float* op = out + (size_t)blockIdx.x * D_;
#pragma unroll
    for (int t = 0; t < 4; t++) {
        int c = tid + t * 256;
        op[c] = (v[t] - mu) * inv * gamma[c] + beta[c];
    }
}

// ============================================================
extern "C" void kernel_launch(void* const* d_in, const int* in_sizes, int n_in,
                              void* d_out, int out_size)
{
    const float* x    = (const float*)d_in[0];
    const float* pe   = (const float*)d_in[1];
    const float* pbu  = (const float*)d_in[2];
    const float* pbv  = (const float*)d_in[3];
    const float* Wqkv = (const float*)d_in[4];
    const float* Wrel = (const float*)d_in[5];
    const float* Wo   = (const float*)d_in[6];
    const float* gam  = (const float*)d_in[7];
    const float* bet  = (const float*)d_in[8];
    float* out = (float*)d_out;

    const int PG_SMEM = 71680;     // (9216 + 8704) * 4
    const int BD_SMEM = 69632;     // 2 * 128*68 * 4 (also fits 128x132 stage)
    const int FA_SMEM = 92160;     // fp16: Q + 2xK + 2xV buffers
    cudaFuncSetAttribute(pgemm<0>, cudaFuncAttributeMaxDynamicSharedMemorySize, PG_SMEM);
    cudaFuncSetAttribute(pgemm<1>, cudaFuncAttributeMaxDynamicSharedMemorySize, PG_SMEM);
    cudaFuncSetAttribute(pgemm<2>, cudaFuncAttributeMaxDynamicSharedMemorySize, PG_SMEM);
    cudaFuncSetAttribute(bd_gemm,  cudaFuncAttributeMaxDynamicSharedMemorySize, BD_SMEM);
    cudaFuncSetAttribute(fattn,    cudaFuncAttributeMaxDynamicSharedMemorySize, FA_SMEM);

    // 1) qkv = x @ W_qkv  (q -> f32; k,v -> fp16)
    pgemm<0><<<dim3(24, 32), 256, PG_SMEM>>>(x, Wqkv, nullptr, 3072);
    // 2) r = pos_emb @ W_relemb
    pgemm<1><<<dim3(8, 16), 256, PG_SMEM>>>(pe, Wrel, nullptr, 1024);
    // 3) pre-shifted Draw = (q + pbv) @ r^T per (b,h)
    bd_gemm<<<dim3(16, 16, 32), 256, BD_SMEM>>>(pbv);
    // 4) fused: scores + shifted-BD add + softmax + PV
    fattn<<<dim3(16, 32), 256, FA_SMEM>>>(pbu);
    // 5) y = x + attn_vec @ W_o
    pgemm<2><<<dim3(8, 32), 256, PG_SMEM>>>(nullptr, Wo, x, 1024);
    // 6) layernorm
    ln_k<<<4096, 256>>>(gam, bet, out);
}

// round 13
// speedup vs baseline: 1.5987x; 1.0249x over previous
#include <cuda_runtime.h>
#include <cuda_fp16.h>
#include <stdint.h>

#define S_    2048
#define B_    2
#define D_    1024
#define H_    16
#define BH_   32
#define ROWS_ 4096
#define QLD_  3072
#define ARS_  6144   // B_*QLD_ : stride between seq rows in g_qkv

// ---- scratch (static device globals; no allocation) ----
__device__ float  g_qkv[(size_t)ROWS_ * 3072];         // q cols f32 (k,v blocks unused)
__device__ __half g_kh [(size_t)ROWS_ * 1024];         // K fp16 [s*B+b][h*64+d]
__device__ __half g_vh [(size_t)ROWS_ * 1024];         // V fp16 [s*B+b][h*64+d]
__device__ float  g_r  [(size_t)S_ * D_];              // [t][h*64+d]
__device__ __half g_bd [(size_t)BH_ * S_ * S_];        // PRE-SHIFTED BD per (b,h), fp16
__device__ float  g_att[(size_t)ROWS_ * D_];           // attn_vec
__device__ float  g_y  [(size_t)ROWS_ * D_];           // x + attn_out

// ---------------- mma / cp.async / ldmatrix helpers ----------------
__device__ __forceinline__ void mma8(float* d, const uint32_t* a,
                                     const uint32_t* b, const float* c) {
    asm volatile(
        "mma.sync.aligned.m16n8k8.row.col.f32.tf32.tf32.f32 "
        "{%0,%1,%2,%3}, {%4,%5,%6,%7}, {%8,%9}, {%10,%11,%12,%13};\n"
        : "=f"(d[0]), "=f"(d[1]), "=f"(d[2]), "=f"(d[3])
        : "r"(a[0]), "r"(a[1]), "r"(a[2]), "r"(a[3]), "r"(b[0]), "r"(b[1]),
          "f"(c[0]), "f"(c[1]), "f"(c[2]), "f"(c[3]));
}
__device__ __forceinline__ void mma16h(float* d, const uint32_t* a,
                                       const uint32_t* b, const float* c) {
    asm volatile(
        "mma.sync.aligned.m16n8k16.row.col.f32.f16.f16.f32 "
        "{%0,%1,%2,%3}, {%4,%5,%6,%7}, {%8,%9}, {%10,%11,%12,%13};\n"
        : "=f"(d[0]), "=f"(d[1]), "=f"(d[2]), "=f"(d[3])
        : "r"(a[0]), "r"(a[1]), "r"(a[2]), "r"(a[3]), "r"(b[0]), "r"(b[1]),
          "f"(c[0]), "f"(c[1]), "f"(c[2]), "f"(c[3]));
}
__device__ __forceinline__ uint32_t f2u(float x) { return __float_as_uint(x); }
__device__ __forceinline__ uint32_t h2(float lo, float hi) {
    uint32_t d;
    asm("cvt.rn.f16x2.f32 %0, %1, %2;\n" : "=r"(d) : "f"(hi), "f"(lo));
    return d;   // d.lo = lo, d.hi = hi
}
__device__ __forceinline__ void cpa16(uint32_t s, const void* g) {
    asm volatile("cp.async.cg.shared.global [%0], [%1], 16;\n" :: "r"(s), "l"(g));
}
__device__ __forceinline__ void cpcommit() { asm volatile("cp.async.commit_group;\n"); }
template <int N> __device__ __forceinline__ void cpwait() {
    asm volatile("cp.async.wait_group %0;\n" :: "n"(N));
}
__device__ __forceinline__ void ldsm4(uint32_t* r, uint32_t a) {
    asm volatile("ldmatrix.sync.aligned.m8n8.x4.shared.b16 {%0,%1,%2,%3}, [%4];\n"
        : "=r"(r[0]), "=r"(r[1]), "=r"(r[2]), "=r"(r[3]) : "r"(a));
}
__device__ __forceinline__ void ldsm4t(uint32_t* r, uint32_t a) {
    asm volatile("ldmatrix.sync.aligned.m8n8.x4.trans.shared.b16 {%0,%1,%2,%3}, [%4];\n"
        : "=r"(r[0]), "=r"(r[1]), "=r"(r[2]), "=r"(r[3]) : "r"(a));
}
__device__ __forceinline__ float ex2(float x) {
    float y; asm("ex2.approx.f32 %0, %1;" : "=f"(y) : "f"(x)); return y;
}

// ============================================================
// Projection GEMM, K=1024 fixed, tile 128x128x32, cp.async 2-stage.
// MODE 0: q cols -> g_qkv f32, K cols -> g_kh fp16, V cols -> g_vh fp16
// MODE 1: g_r = A@B    MODE 2: g_y = g_att@B + Xres
// ============================================================
template <int MODE>
__global__ __launch_bounds__(256) void pgemm(const float* __restrict__ A,
                                             const float* __restrict__ Bw,
                                             const float* __restrict__ Xres,
                                             int N)
{
    extern __shared__ float sm[];
    float* As = sm;               // 2 x 128 x 36
    float* Bs = sm + 9216;        // 2 x 32  x 136
    const float* Ap = (MODE == 2) ? (const float*)g_att : A;
    float* C = (MODE == 0) ? g_qkv : (MODE == 1) ? g_r : g_y;

    int tid = threadIdx.x, l = tid & 31, w = tid >> 5, wm = w >> 1, wn = w & 1;
    size_t m0 = (size_t)blockIdx.y * 128, n0 = (size_t)blockIdx.x * 128;
    uint32_t sA = (uint32_t)__cvta_generic_to_shared(As);
    uint32_t sB = (uint32_t)__cvta_generic_to_shared(Bs);

    float acc[2][8][4] = {};

#define STAGE(IT, BUF)                                                          \
    {                                                                           \
        int kk = (IT) * 32;                                                     \
        uint32_t ab = sA + (BUF) * 4608 * 4;                                    \
        _Pragma("unroll")                                                       \
        for (int t = 0; t < 4; t++) {                                           \
            int idx = tid + t * 256; int r = idx >> 3, c4 = (idx & 7) << 2;     \
            cpa16(ab + (r * 36 + c4) * 4, Ap + (m0 + r) * 1024 + kk + c4);      \
        }                                                                       \
        uint32_t bb = sB + (BUF) * 4352 * 4;                                    \
        _Pragma("unroll")                                                       \
        for (int t = 0; t < 4; t++) {                                           \
            int idx = tid + t * 256; int r = idx >> 5, c4 = (idx & 31) << 2;    \
            cpa16(bb + (r * 136 + c4) * 4, Bw + (size_t)(kk + r) * N + n0 + c4);\
        }                                                                       \
        cpcommit();                                                             \
    }

    STAGE(0, 0);
    for (int it = 0; it < 32; it++) {
        int buf = it & 1;
        if (it + 1 < 32) { STAGE(it + 1, buf ^ 1); cpwait<1>(); }
        else             { cpwait<0>(); }
        __syncthreads();
        const float* As_ = As + buf * 4608;
        const float* Bs_ = Bs + buf * 4352;
#pragma unroll
        for (int k8 = 0; k8 < 4; k8++) {
            uint32_t a[2][4];
#pragma unroll
            for (int mt = 0; mt < 2; mt++) {
                int r = wm * 32 + mt * 16 + (l >> 2);
                a[mt][0] = f2u(As_[r * 36 + k8 * 8 + (l & 3)]);
                a[mt][1] = f2u(As_[(r + 8) * 36 + k8 * 8 + (l & 3)]);
                a[mt][2] = f2u(As_[r * 36 + k8 * 8 + (l & 3) + 4]);
                a[mt][3] = f2u(As_[(r + 8) * 36 + k8 * 8 + (l & 3) + 4]);
            }
#pragma unroll
            for (int nt = 0; nt < 8; nt++) {
                uint32_t bf[2];
                int cb = wn * 64 + nt * 8 + (l >> 2);
                bf[0] = f2u(Bs_[(k8 * 8 + (l & 3)) * 136 + cb]);
                bf[1] = f2u(Bs_[(k8 * 8 + (l & 3) + 4) * 136 + cb]);
#pragma unroll
                for (int mt = 0; mt < 2; mt++)
                    mma8(acc[mt][nt], a[mt], bf, acc[mt][nt]);
            }
        }
        __syncthreads();
    }
#undef STAGE

    if (MODE == 0 && n0 >= 1024) {
        // K / V columns: write fp16 copies only (f32 never read)
        __half* dst = (n0 >= 2048) ? g_vh : g_kh;
        size_t cb = n0 - ((n0 >= 2048) ? 2048 : 1024);
#pragma unroll
        for (int mt = 0; mt < 2; mt++) {
            size_t r0 = m0 + wm * 32 + mt * 16 + (l >> 2);
#pragma unroll
            for (int nt = 0; nt < 8; nt++) {
                size_t c = cb + wn * 64 + nt * 8 + 2 * (l & 3);
                *(__half2*)(dst + r0 * 1024 + c) =
                    __floats2half2_rn(acc[mt][nt][0], acc[mt][nt][1]);
                *(__half2*)(dst + (r0 + 8) * 1024 + c) =
                    __floats2half2_rn(acc[mt][nt][2], acc[mt][nt][3]);
            }
        }
        return;
    }
#pragma unroll
    for (int mt = 0; mt < 2; mt++) {
        size_t r0 = m0 + wm * 32 + mt * 16 + (l >> 2);
#pragma unroll
        for (int nt = 0; nt < 8; nt++) {
            size_t c = n0 + wn * 64 + nt * 8 + 2 * (l & 3);
            float2 v0 = make_float2(acc[mt][nt][0], acc[mt][nt][1]);
            float2 v1 = make_float2(acc[mt][nt][2], acc[mt][nt][3]);
            if (MODE == 2) {
                float2 x0 = *(const float2*)(Xres + r0 * N + c);
                float2 x1 = *(const float2*)(Xres + (r0 + 8) * N + c);
                v0.x += x0.x; v0.y += x0.y; v1.x += x1.x; v1.y += x1.y;
            }
            *(float2*)(C + r0 * N + c) = v0;
            *(float2*)(C + (r0 + 8) * N + c) = v1;
        }
    }
}

// ============================================================
// Draw = (q + pos_bias_v) @ r^T per (b,h), stored PRE-SHIFTED, fp16.
//   tcol = t + i + 1;  if tcol >= S -> (row i,   col tcol - S)
//                      else        -> (row i-1, col tcol)  [dropped if i==0]
// Row i's column j=i+1 is never written (rel-shift zero; fattn masks).
// Smem-staged epilogue: warp-per-row, lane-consecutive fp16 streaming stores.
// ============================================================
__global__ __launch_bounds__(256, 2) void bd_gemm(const float* __restrict__ pbv)
{
    extern __shared__ float sm[];
    float* Qs = sm;               // 128 x 68
    float* Rs = sm + 8704;        // 128 x 68
    int tid = threadIdx.x, l = tid & 31, w = tid >> 5;
    int bh = blockIdx.z, b = bh >> 4, h = bh & 15;
    int i0 = blockIdx.y * 128, t0 = blockIdx.x * 128;
    const float* Qg = g_qkv + (size_t)b * QLD_ + h * 64;
    const float* Rg = g_r + h * 64;
    const float* bias = pbv + h * 64;

#pragma unroll
    for (int t = 0; t < 8; t++) {
        int idx = tid + t * 256; int r = idx >> 4, c4 = (idx & 15) << 2;
        float4 a4 = *(const float4*)(Qg + (size_t)(i0 + r) * ARS_ + c4);
        float4 u4 = *(const float4*)(bias + c4);
        a4.x += u4.x; a4.y += u4.y; a4.z += u4.z; a4.w += u4.w;
        *(float4*)&Qs[r * 68 + c4] = a4;
        *(float4*)&Rs[r * 68 + c4] = *(const float4*)(Rg + (size_t)(t0 + r) * D_ + c4);
    }
    __syncthreads();

    uint32_t sQ = (uint32_t)__cvta_generic_to_shared(Qs);
    uint32_t sR = (uint32_t)__cvta_generic_to_shared(Rs);
    uint32_t aoff = ((w * 16 + ((l >> 3) & 1) * 8 + (l & 7)) * 68 + ((l >> 4) & 1) * 4) * 4;
    uint32_t boff = ((((l >> 4) & 1) * 8 + (l & 7)) * 68 + ((l >> 3) & 1) * 4) * 4;

    uint32_t qa[8][4];
#pragma unroll
    for (int k8 = 0; k8 < 8; k8++) ldsm4(qa[k8], sQ + aoff + k8 * 32);

    float acc[16][4] = {};
#pragma unroll
    for (int k8 = 0; k8 < 8; k8++)
#pragma unroll
        for (int np = 0; np < 8; np++) {
            uint32_t kb[4];
            ldsm4(kb, sR + boff + np * 16 * 272 + k8 * 32);
            mma8(acc[2 * np],     qa[k8], kb,     acc[2 * np]);
            mma8(acc[2 * np + 1], qa[k8], kb + 2, acc[2 * np + 1]);
        }

    // ---- stage tile in smem (Qs/Rs dead), then coalesced shifted fp16 stores ----
    __syncthreads();                       // all ldsm4 reads done
    float* stage = sm;                     // 128 x 132 = 67584 B
    int lr0 = w * 16 + (l >> 2);
#pragma unroll
    for (int nt = 0; nt < 16; nt++) {
        int c = nt * 8 + 2 * (l & 3);
        *(float2*)&stage[lr0 * 132 + c]       = make_float2(acc[nt][0], acc[nt][1]);
        *(float2*)&stage[(lr0 + 8) * 132 + c] = make_float2(acc[nt][2], acc[nt][3]);
    }
    __syncthreads();

    __half* out = g_bd + (size_t)bh * S_ * S_;
#pragma unroll
    for (int rr = 0; rr < 16; rr++) {
        int r = w * 16 + rr;               // local row in tile
        int gi = i0 + r;                   // global Draw row i
        int base = t0 + gi + 1;
#pragma unroll
        for (int j = 0; j < 4; j++) {
            int c = l + 32 * j;
            int tcol = base + c;
            __half v = __float2half_rn(stage[r * 132 + c]);
            if (tcol >= S_)      __stcs(out + (size_t)gi * S_ + (tcol - S_), v);
            else if (gi > 0)     __stcs(out + (size_t)(gi - 1) * S_ + tcol, v);
        }
    }
}

// ============================================================
// Fused attention, all-fp16 mma paths, K/V double-buffered,
// pre-shifted fp16 BD: row-linear aligned __half2 loads + mask.
// smem 90 KB, 2 CTAs/SM.
// ============================================================
__global__ __launch_bounds__(256, 2) void fattn(const float* __restrict__ pbu)
{
    extern __shared__ __half smh[];
    __half* Qsh = smh;                      // 128 x 72 fp16 (persistent)
    int tid = threadIdx.x, l = tid & 31, w = tid >> 5;
    int bh = blockIdx.y, b = bh >> 4, h = bh & 15;
    int i0 = blockIdx.x * 128;
    const float*  Qg = g_qkv + (size_t)b * QLD_ + h * 64;
    const __half* Kg = g_kh + (size_t)b * 1024 + h * 64;   // row stride 2048
    const __half* Vg = g_vh + (size_t)b * 1024 + h * 64;   // row stride 2048
    const __half* bd = g_bd + (size_t)bh * S_ * S_;
    const float* bias = pbu + h * 64;
    uint32_t sQ     = (uint32_t)__cvta_generic_to_shared(Qsh);
    uint32_t sKbase = (uint32_t)__cvta_generic_to_shared(smh + 9216);
    uint32_t sVbase = (uint32_t)__cvta_generic_to_shared(smh + 27648);

    // (q + bias_u) -> fp16 smem
#pragma unroll
    for (int t = 0; t < 8; t++) {
        int idx = tid + t * 256; int r = idx >> 4, c4 = (idx & 15) << 2;
        float4 a4 = *(const float4*)(Qg + (size_t)(i0 + r) * ARS_ + c4);
        float4 u4 = *(const float4*)(bias + c4);
        *(__half2*)(Qsh + r * 72 + c4)     = __floats2half2_rn(a4.x + u4.x, a4.y + u4.y);
        *(__half2*)(Qsh + r * 72 + c4 + 2) = __floats2half2_rn(a4.z + u4.z, a4.w + u4.w);
    }

#define PFKV(IT, BO)                                                            \
    {                                                                           \
        const __half* kn = Kg + (size_t)((IT) * 128) * 2048;                    \
        const __half* vn = Vg + (size_t)((IT) * 128) * 2048;                    \
        _Pragma("unroll")                                                       \
        for (int t = 0; t < 4; t++) {                                           \
            int idx = tid + t * 256; int r = idx >> 3, c8 = (idx & 7) << 3;     \
            cpa16(sKbase + (BO) + (r * 72 + c8) * 2, kn + (size_t)r * 2048 + c8);\
            cpa16(sVbase + (BO) + (r * 72 + c8) * 2, vn + (size_t)r * 2048 + c8);\
        }                                                                       \
        cpcommit();                                                             \
    }

    PFKV(0, 0)
    PFKV(1, 18432)

    uint32_t qoff  = (uint32_t)((w * 16 + (l & 7) + ((l >> 3) & 1) * 8) * 144
                                + ((l >> 4) & 1) * 16);
    uint32_t kboff = (uint32_t)(((l & 7) + (l >> 4) * 8) * 144 + ((l >> 3) & 1) * 16);
    uint32_t vrbase = (uint32_t)((l & 7) + ((l >> 3) & 1) * 8);
    uint32_t vcoff  = (uint32_t)((l >> 4) * 8);

    float o[8][4] = {};
    float bdbuf[32];
    float mrow0 = -1e30f, mrow1 = -1e30f, lsum0 = 0.f, lsum1 = 0.f;
    int tc = l & 3;
    int lr0 = w * 16 + (l >> 2);
    int row0 = i0 + lr0, row1 = row0 + 8;
    const float CS = 0.1803368801111204f;   // 0.125 * log2(e)

// pre-shifted fp16 BD: row-linear aligned __half2 loads, mask j==row+1 -> 0
#define LDBD(JB)                                                                \
    _Pragma("unroll")                                                           \
    for (int nt = 0; nt < 8; nt++) {                                            \
        int c0 = (JB) + nt * 8 + 2 * tc;                                        \
        __half2 h0 = __ldcs((const __half2*)(bd + (size_t)row0 * S_ + c0));     \
        __half2 h1 = __ldcs((const __half2*)(bd + (size_t)row1 * S_ + c0));     \
        float2 v0 = __half22float2(h0);                                         \
        float2 v1 = __half22float2(h1);                                         \
        bdbuf[nt * 4 + 0] = (c0     == row0 + 1) ? 0.f : v0.x;                  \
        bdbuf[nt * 4 + 1] = (c0 + 1 == row0 + 1) ? 0.f : v0.y;                  \
        bdbuf[nt * 4 + 2] = (c0     == row1 + 1) ? 0.f : v1.x;                  \
        bdbuf[nt * 4 + 3] = (c0 + 1 == row1 + 1) ? 0.f : v1.y;                  \
    }

    LDBD(0)

#define AC_MMA(HALF)                                                            \
    _Pragma("unroll")                                                           \
    for (int nt = 0; nt < 8; nt++)                                              \
        p[nt][0] = p[nt][1] = p[nt][2] = p[nt][3] = 0.f;                        \
    _Pragma("unroll")                                                           \
    for (int ks = 0; ks < 4; ks++) {                                            \
        uint32_t qf[4];                                                         \
        ldsm4(qf, sQ + qoff + ks * 32);                                         \
        _Pragma("unroll")                                                       \
        for (int np = 0; np < 4; np++) {                                        \
            uint32_t kb[4];                                                     \
            ldsm4(kb, sK + kboff + ((HALF) * 64 + np * 16) * 144 + ks * 32);    \
            mma16h(p[2 * np],     qf, kb,     p[2 * np]);                       \
            mma16h(p[2 * np + 1], qf, kb + 2, p[2 * np + 1]);                   \
        }                                                                       \
    }

#define SOFTMAX_STEP()                                                          \
    {                                                                           \
        float mx0 = -1e30f, mx1 = -1e30f;                                       \
        _Pragma("unroll")                                                       \
        for (int nt = 0; nt < 8; nt++) {                                        \
            float s;                                                            \
            s = (p[nt][0] + bdbuf[nt*4+0]) * CS; p[nt][0] = s; mx0 = fmaxf(mx0, s); \
            s = (p[nt][1] + bdbuf[nt*4+1]) * CS; p[nt][1] = s; mx0 = fmaxf(mx0, s); \
            s = (p[nt][2] + bdbuf[nt*4+2]) * CS; p[nt][2] = s; mx1 = fmaxf(mx1, s); \
            s = (p[nt][3] + bdbuf[nt*4+3]) * CS; p[nt][3] = s; mx1 = fmaxf(mx1, s); \
        }                                                                       \
        mx0 = fmaxf(mx0, __shfl_xor_sync(~0u, mx0, 1));                         \
        mx0 = fmaxf(mx0, __shfl_xor_sync(~0u, mx0, 2));                         \
        mx1 = fmaxf(mx1, __shfl_xor_sync(~0u, mx1, 1));                         \
        mx1 = fmaxf(mx1, __shfl_xor_sync(~0u, mx1, 2));                         \
        float mn0 = fmaxf(mrow0, mx0), mn1 = fmaxf(mrow1, mx1);                 \
        float al0 = ex2(mrow0 - mn0), al1 = ex2(mrow1 - mn1);                   \
        mrow0 = mn0; mrow1 = mn1;                                               \
        float rs0 = 0.f, rs1 = 0.f;                                             \
        _Pragma("unroll")                                                       \
        for (int nt = 0; nt < 8; nt++) {                                        \
            p[nt][0] = ex2(p[nt][0] - mn0); p[nt][1] = ex2(p[nt][1] - mn0);     \
            p[nt][2] = ex2(p[nt][2] - mn1); p[nt][3] = ex2(p[nt][3] - mn1);     \
            rs0 += p[nt][0] + p[nt][1]; rs1 += p[nt][2] + p[nt][3];             \
        }                                                                       \
        rs0 += __shfl_xor_sync(~0u, rs0, 1); rs0 += __shfl_xor_sync(~0u, rs0, 2);\
        rs1 += __shfl_xor_sync(~0u, rs1, 1); rs1 += __shfl_xor_sync(~0u, rs1, 2);\
        lsum0 = lsum0 * al0 + rs0;                                              \
        lsum1 = lsum1 * al1 + rs1;                                              \
        _Pragma("unroll")                                                       \
        for (int nt = 0; nt < 8; nt++) {                                        \
            o[nt][0] *= al0; o[nt][1] *= al0; o[nt][2] *= al1; o[nt][3] *= al1; \
        }                                                                       \
    }

#define CVT_P()                                                                 \
    uint32_t af[4][4];                                                          \
    _Pragma("unroll")                                                           \
    for (int ks = 0; ks < 4; ks++) {                                            \
        af[ks][0] = h2(p[2*ks][0],   p[2*ks][1]);                               \
        af[ks][1] = h2(p[2*ks][2],   p[2*ks][3]);                               \
        af[ks][2] = h2(p[2*ks+1][0], p[2*ks+1][1]);                             \
        af[ks][3] = h2(p[2*ks+1][2], p[2*ks+1][3]);                             \
    }

#define PV16(HALF)                                                              \
    _Pragma("unroll")                                                           \
    for (int ks = 0; ks < 4; ks++) {                                            \
        uint32_t vrow = (uint32_t)((HALF) * 64 + ks * 16) + vrbase;             \
        _Pragma("unroll")                                                       \
        for (int ntt = 0; ntt < 4; ntt++) {                                     \
            uint32_t vb[4];                                                     \
            ldsm4t(vb, sV + (vrow * 72 + ntt * 16 + vcoff) * 2);                \
            mma16h(o[2*ntt],   af[ks], vb,   o[2*ntt]);                         \
            mma16h(o[2*ntt+1], af[ks], vb+2, o[2*ntt+1]);                       \
        }                                                                       \
    }

    for (int it = 0; it < 16; it++) {
        uint32_t bo = (uint32_t)(it & 1) * 18432;
        uint32_t sK = sKbase + bo;
        uint32_t sV = sVbase + bo;
        if (it == 15) cpwait<0>(); else cpwait<1>();   // K/V(it) landed
        __syncthreads();

        {   // ---- half 0 ----
            float p[8][4];
            AC_MMA(0)
            SOFTMAX_STEP()
            CVT_P()
            LDBD(it * 128 + 64)
            PV16(0)
        }
        {   // ---- half 1 ----
            float p[8][4];
            AC_MMA(1)
            SOFTMAX_STEP()
            CVT_P()
            if (it + 1 < 16) LDBD((it + 1) * 128)
            PV16(1)
        }
        __syncthreads();
        if (it + 2 < 16) PFKV(it + 2, bo)
    }
#undef PFKV
#undef LDBD
#undef AC_MMA
#undef SOFTMAX_STEP
#undef CVT_P
#undef PV16

    float inv0 = 1.f / lsum0, inv1 = 1.f / lsum1;
#pragma unroll
    for (int nt = 0; nt < 8; nt++) {
        int c = h * 64 + nt * 8 + 2 * tc;
        *(float2*)(g_att + ((size_t)row0 * B_ + b) * D_ + c) =
            make_float2(o[nt][0] * inv0, o[nt][1] * inv0);
        *(float2*)(g_att + ((size_t)row1 * B_ + b) * D_ + c) =
            make_float2(o[nt][2] * inv1, o[nt][3] * inv1);
    }
}

// ============================================================
// LayerNorm over D=1024 per row.
// ============================================================
__global__ __launch_bounds__(256) void ln_k(const float* __restrict__ gamma,
                                            const float* __restrict__ beta,
                                            float* __restrict__ out)
{
    __shared__ float reds[8], redq[8];
    const float* y = g_y + (size_t)blockIdx.x * D_;
    int tid = threadIdx.x;
    float v[4];
    float s = 0.f, q = 0.f;
#pragma unroll
    for (int t = 0; t < 4; t++) {
        v[t] = y[tid + t * 256];
        s += v[t]; q += v[t] * v[t];
    }
#pragma unroll
    for (int o = 16; o; o >>= 1) {
        s += __shfl_xor_sync(0xffffffffu, s, o);
        q += __shfl_xor_sync(0xffffffffu, q, o);
    }
    if ((tid & 31) == 0) { reds[tid >> 5] = s; redq[tid >> 5] = q; }
    __syncthreads();
    float ts = 0.f, tq = 0.f;
#pragma unroll
    for (int wv = 0; wv < 8; wv++) { ts += reds[wv]; tq += redq[wv]; }
    float mu = ts * (1.f / 1024.f);
    float var = tq * (1.f / 1024.f) - mu * mu;
    float inv = rsqrtf(var + 1e-5f);
    float* op = out + (size_t)blockIdx.x * D_;
#pragma unroll
    for (int t = 0; t < 4; t++) {
        int c = tid + t * 256;
        op[c] = (v[t] - mu) * inv * gamma[c] + beta[c];
    }
}

// ============================================================
extern "C" void kernel_launch(void* const* d_in, const int* in_sizes, int n_in,
                              void* d_out, int out_size)
{
    const float* x    = (const float*)d_in[0];
    const float* pe   = (const float*)d_in[1];
    const float* pbu  = (const float*)d_in[2];
    const float* pbv  = (const float*)d_in[3];
    const float* Wqkv = (const float*)d_in[4];
    const float* Wrel = (const float*)d_in[5];
    const float* Wo   = (const float*)d_in[6];
    const float* gam  = (const float*)d_in[7];
    const float* bet  = (const float*)d_in[8];
    float* out = (float*)d_out;

    const int PG_SMEM = 71680;     // (9216 + 8704) * 4
    const int BD_SMEM = 69632;     // 2 * 128*68 * 4 (also fits 128x132 stage)
    const int FA_SMEM = 92160;     // fp16: Q + 2xK + 2xV buffers
    cudaFuncSetAttribute(pgemm<0>, cudaFuncAttributeMaxDynamicSharedMemorySize, PG_SMEM);
    cudaFuncSetAttribute(pgemm<1>, cudaFuncAttributeMaxDynamicSharedMemorySize, PG_SMEM);
    cudaFuncSetAttribute(pgemm<2>, cudaFuncAttributeMaxDynamicSharedMemorySize, PG_SMEM);
    cudaFuncSetAttribute(bd_gemm,  cudaFuncAttributeMaxDynamicSharedMemorySize, BD_SMEM);
    cudaFuncSetAttribute(fattn,    cudaFuncAttributeMaxDynamicSharedMemorySize, FA_SMEM);

    // 1) qkv = x @ W_qkv  (q -> f32; k,v -> fp16)
    pgemm<0><<<dim3(24, 32), 256, PG_SMEM>>>(x, Wqkv, nullptr, 3072);
    // 2) r = pos_emb @ W_relemb
    pgemm<1><<<dim3(8, 16), 256, PG_SMEM>>>(pe, Wrel, nullptr, 1024);
    // 3) pre-shifted fp16 Draw = (q + pbv) @ r^T per (b,h)
    bd_gemm<<<dim3(16, 16, 32), 256, BD_SMEM>>>(pbv);
    // 4) fused: scores + shifted-BD add + softmax + PV
    fattn<<<dim3(16, 32), 256, FA_SMEM>>>(pbu);
    // 5) y = x + attn_vec @ W_o
    pgemm<2><<<dim3(8, 32), 256, PG_SMEM>>>(nullptr, Wo, x, 1024);
    // 6) layernorm
    ln_k<<<4096, 256>>>(gam, bet, out);
}

// round 15
// speedup vs baseline: 1.8700x; 1.1697x over previous
#include <cuda_runtime.h>
#include <cuda_fp16.h>
#include <stdint.h>

#define S_    2048
#define B_    2
#define D_    1024
#define H_    16
#define BH_   32
#define ROWS_ 4096

// ---- scratch (static device globals; no allocation) ----
__device__ __half g_xh  [(size_t)ROWS_ * 1024];        // x fp16
__device__ __half g_peh [(size_t)S_ * 1024];           // pos_emb fp16
__device__ __half g_wqkvh[(size_t)1024 * 3072];        // W_qkv fp16
__device__ __half g_wrelh[(size_t)1024 * 1024];        // W_relemb fp16
__device__ __half g_woh [(size_t)1024 * 1024];         // W_o fp16
__device__ float  g_q  [(size_t)ROWS_ * 1024];         // q f32 [s*B+b][h*64+d]
__device__ __half g_kh [(size_t)ROWS_ * 1024];         // K fp16
__device__ __half g_vh [(size_t)ROWS_ * 1024];         // V fp16
__device__ float  g_r  [(size_t)S_ * D_];              // r f32 [t][h*64+d]
__device__ __half g_bd [(size_t)BH_ * S_ * S_];        // PRE-SHIFTED BD, fp16
__device__ __half g_atth[(size_t)ROWS_ * 1024];        // attn_vec fp16
__device__ float  g_y  [(size_t)ROWS_ * D_];           // x + attn_out

// ---------------- mma / cp.async / ldmatrix helpers ----------------
__device__ __forceinline__ void mma8(float* d, const uint32_t* a,
                                     const uint32_t* b, const float* c) {
    asm volatile(
        "mma.sync.aligned.m16n8k8.row.col.f32.tf32.tf32.f32 "
        "{%0,%1,%2,%3}, {%4,%5,%6,%7}, {%8,%9}, {%10,%11,%12,%13};\n"
        : "=f"(d[0]), "=f"(d[1]), "=f"(d[2]), "=f"(d[3])
        : "r"(a[0]), "r"(a[1]), "r"(a[2]), "r"(a[3]), "r"(b[0]), "r"(b[1]),
          "f"(c[0]), "f"(c[1]), "f"(c[2]), "f"(c[3]));
}
__device__ __forceinline__ void mma16h(float* d, const uint32_t* a,
                                       const uint32_t* b, const float* c) {
    asm volatile(
        "mma.sync.aligned.m16n8k16.row.col.f32.f16.f16.f32 "
        "{%0,%1,%2,%3}, {%4,%5,%6,%7}, {%8,%9}, {%10,%11,%12,%13};\n"
        : "=f"(d[0]), "=f"(d[1]), "=f"(d[2]), "=f"(d[3])
        : "r"(a[0]), "r"(a[1]), "r"(a[2]), "r"(a[3]), "r"(b[0]), "r"(b[1]),
          "f"(c[0]), "f"(c[1]), "f"(c[2]), "f"(c[3]));
}
__device__ __forceinline__ uint32_t f2u(float x) { return __float_as_uint(x); }
__device__ __forceinline__ uint32_t h2(float lo, float hi) {
    uint32_t d;
    asm("cvt.rn.f16x2.f32 %0, %1, %2;\n" : "=r"(d) : "f"(hi), "f"(lo));
    return d;
}
__device__ __forceinline__ void cpa16(uint32_t s, const void* g) {
    asm volatile("cp.async.cg.shared.global [%0], [%1], 16;\n" :: "r"(s), "l"(g));
}
__device__ __forceinline__ void cpcommit() { asm volatile("cp.async.commit_group;\n"); }
template <int N> __device__ __forceinline__ void cpwait() {
    asm volatile("cp.async.wait_group %0;\n" :: "n"(N));
}
__device__ __forceinline__ void ldsm4(uint32_t* r, uint32_t a) {
    asm volatile("ldmatrix.sync.aligned.m8n8.x4.shared.b16 {%0,%1,%2,%3}, [%4];\n"
        : "=r"(r[0]), "=r"(r[1]), "=r"(r[2]), "=r"(r[3]) : "r"(a));
}
__device__ __forceinline__ void ldsm4t(uint32_t* r, uint32_t a) {
    asm volatile("ldmatrix.sync.aligned.m8n8.x4.trans.shared.b16 {%0,%1,%2,%3}, [%4];\n"
        : "=r"(r[0]), "=r"(r[1]), "=r"(r[2]), "=r"(r[3]) : "r"(a));
}
__device__ __forceinline__ float ex2(float x) {
    float y; asm("ex2.approx.f32 %0, %1;" : "=f"(y) : "f"(x)); return y;
}

// ============================================================
// f32 -> fp16 conversion (float4 groups)
// ============================================================
__global__ __launch_bounds__(256) void cvt_h(const float* __restrict__ s,
                                             __half* __restrict__ d, int n)
{
    int i = (blockIdx.x * 256 + threadIdx.x) * 4;
    if (i < n) {
        float4 v = *(const float4*)(s + i);
        *(__half2*)(d + i)     = __floats2half2_rn(v.x, v.y);
        *(__half2*)(d + i + 2) = __floats2half2_rn(v.z, v.w);
    }
}

// ============================================================
// fp16 projection GEMM: C[M,N] = A[M,1024] @ B[1024,N].
// Tile 128x128x32, m16n8k16, A via ldsm4, B via ldsm4t,
// 2-stage cp.async. MODE 0: q->g_q f32 / k->g_kh / v->g_vh.
// MODE 1: g_r f32.  MODE 2: A = g_atth (device symbol!),
//                   g_y = acc + Xres (f32).
// ============================================================
template <int MODE>
__global__ __launch_bounds__(256) void pgemm_h(const __half* __restrict__ Ah,
                                               const __half* __restrict__ Bh,
                                               const float* __restrict__ Xres,
                                               int N)
{
    extern __shared__ __half smH[];
    // A bufs: bytes [0,10240),[10240,20480)  (128 x 40 halves each)
    // B bufs: bytes [20480,29184),[29184,37888) (32 x 136 halves each)
    uint32_t sb = (uint32_t)__cvta_generic_to_shared(smH);
    int tid = threadIdx.x, l = tid & 31, w = tid >> 5;
    size_t m0 = (size_t)blockIdx.y * 128, n0 = (size_t)blockIdx.x * 128;
    const __half* Ap = (MODE == 2) ? (const __half*)g_atth : Ah;   // device-side symbol

    float acc[16][4] = {};

#define STG(IT, BUF)                                                            \
    {                                                                           \
        int kk = (IT) * 32;                                                     \
        uint32_t ab = sb + (BUF) * 10240;                                       \
        _Pragma("unroll")                                                       \
        for (int t = 0; t < 2; t++) {                                           \
            int idx = tid + t * 256; int r = idx >> 2, c8 = (idx & 3) << 3;     \
            cpa16(ab + (r * 40 + c8) * 2, Ap + (m0 + r) * 1024 + kk + c8);      \
        }                                                                       \
        uint32_t bb = sb + 20480 + (BUF) * 8704;                                \
        _Pragma("unroll")                                                       \
        for (int t = 0; t < 2; t++) {                                           \
            int idx = tid + t * 256; int r = idx >> 4, c8 = (idx & 15) << 3;    \
            cpa16(bb + (r * 136 + c8) * 2, Bh + (size_t)(kk + r) * N + n0 + c8);\
        }                                                                       \
        cpcommit();                                                             \
    }

    uint32_t aoff = (uint32_t)((w * 16 + (l & 7) + ((l >> 3) & 1) * 8) * 80
                               + ((l >> 4) & 1) * 16);
    uint32_t boff = (uint32_t)(((l & 7) + ((l >> 3) & 1) * 8) * 272 + (l >> 4) * 16);

    STG(0, 0);
    for (int it = 0; it < 32; it++) {
        int buf = it & 1;
        if (it + 1 < 32) { STG(it + 1, buf ^ 1); cpwait<1>(); }
        else             { cpwait<0>(); }
        __syncthreads();
        uint32_t ab = sb + buf * 10240;
        uint32_t bb = sb + 20480 + buf * 8704;
#pragma unroll
        for (int ks = 0; ks < 2; ks++) {
            uint32_t af[4];
            ldsm4(af, ab + aoff + ks * 32);
#pragma unroll
            for (int nb = 0; nb < 8; nb++) {
                uint32_t vb[4];
                ldsm4t(vb, bb + boff + ks * 16 * 272 + nb * 32);
                mma16h(acc[2 * nb],     af, vb,     acc[2 * nb]);
                mma16h(acc[2 * nb + 1], af, vb + 2, acc[2 * nb + 1]);
            }
        }
        __syncthreads();
    }
#undef STG

    size_t r0 = m0 + w * 16 + (l >> 2);
    if (MODE == 0) {
        if (n0 < 1024) {          // q -> f32, stride 1024
#pragma unroll
            for (int nn = 0; nn < 16; nn++) {
                size_t c = n0 + nn * 8 + 2 * (l & 3);
                *(float2*)(g_q + r0 * 1024 + c)       = make_float2(acc[nn][0], acc[nn][1]);
                *(float2*)(g_q + (r0 + 8) * 1024 + c) = make_float2(acc[nn][2], acc[nn][3]);
            }
        } else {                  // k / v -> fp16
            __half* dst = (n0 >= 2048) ? g_vh : g_kh;
            size_t cb = n0 - ((n0 >= 2048) ? 2048 : 1024);
#pragma unroll
            for (int nn = 0; nn < 16; nn++) {
                size_t c = cb + nn * 8 + 2 * (l & 3);
                *(__half2*)(dst + r0 * 1024 + c) =
                    __floats2half2_rn(acc[nn][0], acc[nn][1]);
                *(__half2*)(dst + (r0 + 8) * 1024 + c) =
                    __floats2half2_rn(acc[nn][2], acc[nn][3]);
            }
        }
        return;
    }
#pragma unroll
    for (int nn = 0; nn < 16; nn++) {
        size_t c = n0 + nn * 8 + 2 * (l & 3);
        float2 v0 = make_float2(acc[nn][0], acc[nn][1]);
        float2 v1 = make_float2(acc[nn][2], acc[nn][3]);
        if (MODE == 2) {
            float2 x0 = *(const float2*)(Xres + r0 * N + c);
            float2 x1 = *(const float2*)(Xres + (r0 + 8) * N + c);
            v0.x += x0.x; v0.y += x0.y; v1.x += x1.x; v1.y += x1.y;
        }
        float* C = (MODE == 1) ? g_r : g_y;
        *(float2*)(C + r0 * N + c) = v0;
        *(float2*)(C + (r0 + 8) * N + c) = v1;
    }
}

// ============================================================
// Draw = (q + pos_bias_v) @ r^T per (b,h), stored PRE-SHIFTED, fp16.
//   tcol = t + i + 1;  if tcol >= S -> (row i, col tcol-S)
//                      else -> (row i-1, col tcol) [dropped if i==0]
// Smem-staged epilogue, lane-consecutive fp16 streaming stores.
// ============================================================
__global__ __launch_bounds__(256, 2) void bd_gemm(const float* __restrict__ pbv)
{
    extern __shared__ float sm[];
    float* Qs = sm;               // 128 x 68
    float* Rs = sm + 8704;        // 128 x 68
    int tid = threadIdx.x, l = tid & 31, w = tid >> 5;
    int bh = blockIdx.z, b = bh >> 4, h = bh & 15;
    int i0 = blockIdx.y * 128, t0 = blockIdx.x * 128;
    const float* Qg = g_q + (size_t)b * 1024 + h * 64;   // row stride 2048
    const float* Rg = g_r + h * 64;
    const float* bias = pbv + h * 64;

#pragma unroll
    for (int t = 0; t < 8; t++) {
        int idx = tid + t * 256; int r = idx >> 4, c4 = (idx & 15) << 2;
        float4 a4 = *(const float4*)(Qg + (size_t)(i0 + r) * 2048 + c4);
        float4 u4 = *(const float4*)(bias + c4);
        a4.x += u4.x; a4.y += u4.y; a4.z += u4.z; a4.w += u4.w;
        *(float4*)&Qs[r * 68 + c4] = a4;
        *(float4*)&Rs[r * 68 + c4] = *(const float4*)(Rg + (size_t)(t0 + r) * D_ + c4);
    }
    __syncthreads();

    uint32_t sQ = (uint32_t)__cvta_generic_to_shared(Qs);
    uint32_t sR = (uint32_t)__cvta_generic_to_shared(Rs);
    uint32_t aoff = ((w * 16 + ((l >> 3) & 1) * 8 + (l & 7)) * 68 + ((l >> 4) & 1) * 4) * 4;
    uint32_t boff = ((((l >> 4) & 1) * 8 + (l & 7)) * 68 + ((l >> 3) & 1) * 4) * 4;

    uint32_t qa[8][4];
#pragma unroll
    for (int k8 = 0; k8 < 8; k8++) ldsm4(qa[k8], sQ + aoff + k8 * 32);

    float acc[16][4] = {};
#pragma unroll
    for (int k8 = 0; k8 < 8; k8++)
#pragma unroll
        for (int np = 0; np < 8; np++) {
            uint32_t kb[4];
            ldsm4(kb, sR + boff + np * 16 * 272 + k8 * 32);
            mma8(acc[2 * np],     qa[k8], kb,     acc[2 * np]);
            mma8(acc[2 * np + 1], qa[k8], kb + 2, acc[2 * np + 1]);
        }

    __syncthreads();                       // all ldsm4 reads done
    float* stage = sm;                     // 128 x 132
    int lr0 = w * 16 + (l >> 2);
#pragma unroll
    for (int nt = 0; nt < 16; nt++) {
        int c = nt * 8 + 2 * (l & 3);
        *(float2*)&stage[lr0 * 132 + c]       = make_float2(acc[nt][0], acc[nt][1]);
        *(float2*)&stage[(lr0 + 8) * 132 + c] = make_float2(acc[nt][2], acc[nt][3]);
    }
    __syncthreads();

    __half* out = g_bd + (size_t)bh * S_ * S_;
#pragma unroll
    for (int rr = 0; rr < 16; rr++) {
        int r = w * 16 + rr;
        int gi = i0 + r;
        int base = t0 + gi + 1;
#pragma unroll
        for (int j = 0; j < 4; j++) {
            int c = l + 32 * j;
            int tcol = base + c;
            __half v = __float2half_rn(stage[r * 132 + c]);
            if (tcol >= S_)      __stcs(out + (size_t)gi * S_ + (tcol - S_), v);
            else if (gi > 0)     __stcs(out + (size_t)(gi - 1) * S_ + tcol, v);
        }
    }
}

// ============================================================
// Fused attention: all-fp16 mma, K/V double-buffered,
// pre-shifted fp16 BD. Output -> g_atth fp16.
// ============================================================
__global__ __launch_bounds__(256, 2) void fattn(const float* __restrict__ pbu)
{
    extern __shared__ __half smh[];
    __half* Qsh = smh;                      // 128 x 72 fp16 (persistent)
    int tid = threadIdx.x, l = tid & 31, w = tid >> 5;
    int bh = blockIdx.y, b = bh >> 4, h = bh & 15;
    int i0 = blockIdx.x * 128;
    const float*  Qg = g_q + (size_t)b * 1024 + h * 64;    // row stride 2048
    const __half* Kg = g_kh + (size_t)b * 1024 + h * 64;   // row stride 2048
    const __half* Vg = g_vh + (size_t)b * 1024 + h * 64;
    const __half* bd = g_bd + (size_t)bh * S_ * S_;
    const float* bias = pbu + h * 64;
    uint32_t sQ     = (uint32_t)__cvta_generic_to_shared(Qsh);
    uint32_t sKbase = (uint32_t)__cvta_generic_to_shared(smh + 9216);
    uint32_t sVbase = (uint32_t)__cvta_generic_to_shared(smh + 27648);

#pragma unroll
    for (int t = 0; t < 8; t++) {
        int idx = tid + t * 256; int r = idx >> 4, c4 = (idx & 15) << 2;
        float4 a4 = *(const float4*)(Qg + (size_t)(i0 + r) * 2048 + c4);
        float4 u4 = *(const float4*)(bias + c4);
        *(__half2*)(Qsh + r * 72 + c4)     = __floats2half2_rn(a4.x + u4.x, a4.y + u4.y);
        *(__half2*)(Qsh + r * 72 + c4 + 2) = __floats2half2_rn(a4.z + u4.z, a4.w + u4.w);
    }

#define PFKV(IT, BO)                                                            \
    {                                                                           \
        const __half* kn = Kg + (size_t)((IT) * 128) * 2048;                    \
        const __half* vn = Vg + (size_t)((IT) * 128) * 2048;                    \
        _Pragma("unroll")                                                       \
        for (int t = 0; t < 4; t++) {                                           \
            int idx = tid + t * 256; int r = idx >> 3, c8 = (idx & 7) << 3;     \
            cpa16(sKbase + (BO) + (r * 72 + c8) * 2, kn + (size_t)r * 2048 + c8);\
            cpa16(sVbase + (BO) + (r * 72 + c8) * 2, vn + (size_t)r * 2048 + c8);\
        }                                                                       \
        cpcommit();                                                             \
    }

    PFKV(0, 0)
    PFKV(1, 18432)

    uint32_t qoff  = (uint32_t)((w * 16 + (l & 7) + ((l >> 3) & 1) * 8) * 144
                                + ((l >> 4) & 1) * 16);
    uint32_t kboff = (uint32_t)(((l & 7) + (l >> 4) * 8) * 144 + ((l >> 3) & 1) * 16);
    uint32_t vrbase = (uint32_t)((l & 7) + ((l >> 3) & 1) * 8);
    uint32_t vcoff  = (uint32_t)((l >> 4) * 8);

    float o[8][4] = {};
    float bdbuf[32];
    float mrow0 = -1e30f, mrow1 = -1e30f, lsum0 = 0.f, lsum1 = 0.f;
    int tc = l & 3;
    int lr0 = w * 16 + (l >> 2);
    int row0 = i0 + lr0, row1 = row0 + 8;
    const float CS = 0.1803368801111204f;   // 0.125 * log2(e)

#define LDBD(JB)                                                                \
    _Pragma("unroll")                                                           \
    for (int nt = 0; nt < 8; nt++) {                                            \
        int c0 = (JB) + nt * 8 + 2 * tc;                                        \
        __half2 h0 = __ldcs((const __half2*)(bd + (size_t)row0 * S_ + c0));     \
        __half2 h1 = __ldcs((const __half2*)(bd + (size_t)row1 * S_ + c0));     \
        float2 v0 = __half22float2(h0);                                         \
        float2 v1 = __half22float2(h1);                                         \
        bdbuf[nt * 4 + 0] = (c0     == row0 + 1) ? 0.f : v0.x;                  \
        bdbuf[nt * 4 + 1] = (c0 + 1 == row0 + 1) ? 0.f : v0.y;                  \
        bdbuf[nt * 4 + 2] = (c0     == row1 + 1) ? 0.f : v1.x;                  \
        bdbuf[nt * 4 + 3] = (c0 + 1 == row1 + 1) ? 0.f : v1.y;                  \
    }

    LDBD(0)

#define AC_MMA(HALF)                                                            \
    _Pragma("unroll")                                                           \
    for (int nt = 0; nt < 8; nt++)                                              \
        p[nt][0] = p[nt][1] = p[nt][2] = p[nt][3] = 0.f;                        \
    _Pragma("unroll")                                                           \
    for (int ks = 0; ks < 4; ks++) {                                            \
        uint32_t qf[4];                                                         \
        ldsm4(qf, sQ + qoff + ks * 32);                                         \
        _Pragma("unroll")                                                       \
        for (int np = 0; np < 4; np++) {                                        \
            uint32_t kb[4];                                                     \
            ldsm4(kb, sK + kboff + ((HALF) * 64 + np * 16) * 144 + ks * 32);    \
            mma16h(p[2 * np],     qf, kb,     p[2 * np]);                       \
            mma16h(p[2 * np + 1], qf, kb + 2, p[2 * np + 1]);                   \
        }                                                                       \
    }

#define SOFTMAX_STEP()                                                          \
    {                                                                           \
        float mx0 = -1e30f, mx1 = -1e30f;                                       \
        _Pragma("unroll")                                                       \
        for (int nt = 0; nt < 8; nt++) {                                        \
            float s;                                                            \
            s = (p[nt][0] + bdbuf[nt*4+0]) * CS; p[nt][0] = s; mx0 = fmaxf(mx0, s); \
            s = (p[nt][1] + bdbuf[nt*4+1]) * CS; p[nt][1] = s; mx0 = fmaxf(mx0, s); \
            s = (p[nt][2] + bdbuf[nt*4+2]) * CS; p[nt][2] = s; mx1 = fmaxf(mx1, s); \
            s = (p[nt][3] + bdbuf[nt*4+3]) * CS; p[nt][3] = s; mx1 = fmaxf(mx1, s); \
        }                                                                       \
        mx0 = fmaxf(mx0, __shfl_xor_sync(~0u, mx0, 1));                         \
        mx0 = fmaxf(mx0, __shfl_xor_sync(~0u, mx0, 2));                         \
        mx1 = fmaxf(mx1, __shfl_xor_sync(~0u, mx1, 1));                         \
        mx1 = fmaxf(mx1, __shfl_xor_sync(~0u, mx1, 2));                         \
        float mn0 = fmaxf(mrow0, mx0), mn1 = fmaxf(mrow1, mx1);                 \
        float al0 = ex2(mrow0 - mn0), al1 = ex2(mrow1 - mn1);                   \
        mrow0 = mn0; mrow1 = mn1;                                               \
        float rs0 = 0.f, rs1 = 0.f;                                             \
        _Pragma("unroll")                                                       \
        for (int nt = 0; nt < 8; nt++) {                                        \
            p[nt][0] = ex2(p[nt][0] - mn0); p[nt][1] = ex2(p[nt][1] - mn0);     \
            p[nt][2] = ex2(p[nt][2] - mn1); p[nt][3] = ex2(p[nt][3] - mn1);     \
            rs0 += p[nt][0] + p[nt][1]; rs1 += p[nt][2] + p[nt][3];             \
        }                                                                       \
        rs0 += __shfl_xor_sync(~0u, rs0, 1); rs0 += __shfl_xor_sync(~0u, rs0, 2);\
        rs1 += __shfl_xor_sync(~0u, rs1, 1); rs1 += __shfl_xor_sync(~0u, rs1, 2);\
        lsum0 = lsum0 * al0 + rs0;                                              \
        lsum1 = lsum1 * al1 + rs1;                                              \
        _Pragma("unroll")                                                       \
        for (int nt = 0; nt < 8; nt++) {                                        \
            o[nt][0] *= al0; o[nt][1] *= al0; o[nt][2] *= al1; o[nt][3] *= al1; \
        }                                                                       \
    }

#define CVT_P()                                                                 \
    uint32_t af[4][4];                                                          \
    _Pragma("unroll")                                                           \
    for (int ks = 0; ks < 4; ks++) {                                            \
        af[ks][0] = h2(p[2*ks][0],   p[2*ks][1]);                               \
        af[ks][1] = h2(p[2*ks][2],   p[2*ks][3]);                               \
        af[ks][2] = h2(p[2*ks+1][0], p[2*ks+1][1]);                             \
        af[ks][3] = h2(p[2*ks+1][2], p[2*ks+1][3]);                             \
    }

#define PV16(HALF)                                                              \
    _Pragma("unroll")                                                           \
    for (int ks = 0; ks < 4; ks++) {                                            \
        uint32_t vrow = (uint32_t)((HALF) * 64 + ks * 16) + vrbase;             \
        _Pragma("unroll")                                                       \
        for (int ntt = 0; ntt < 4; ntt++) {                                     \
            uint32_t vb[4];                                                     \
            ldsm4t(vb, sV + (vrow * 72 + ntt * 16 + vcoff) * 2);                \
            mma16h(o[2*ntt],   af[ks], vb,   o[2*ntt]);                         \
            mma16h(o[2*ntt+1], af[ks], vb+2, o[2*ntt+1]);                       \
        }                                                                       \
    }

    for (int it = 0; it < 16; it++) {
        uint32_t bo = (uint32_t)(it & 1) * 18432;
        uint32_t sK = sKbase + bo;
        uint32_t sV = sVbase + bo;
        if (it == 15) cpwait<0>(); else cpwait<1>();
        __syncthreads();

        {   // ---- half 0 ----
            float p[8][4];
            AC_MMA(0)
            SOFTMAX_STEP()
            CVT_P()
            LDBD(it * 128 + 64)
            PV16(0)
        }
        {   // ---- half 1 ----
            float p[8][4];
            AC_MMA(1)
            SOFTMAX_STEP()
            CVT_P()
            if (it + 1 < 16) LDBD((it + 1) * 128)
            PV16(1)
        }
        __syncthreads();
        if (it + 2 < 16) PFKV(it + 2, bo)
    }
#undef PFKV
#undef LDBD
#undef AC_MMA
#undef SOFTMAX_STEP
#undef CVT_P
#undef PV16

    float inv0 = 1.f / lsum0, inv1 = 1.f / lsum1;
#pragma unroll
    for (int nt = 0; nt < 8; nt++) {
        int c = h * 64 + nt * 8 + 2 * tc;
        *(__half2*)(g_atth + ((size_t)row0 * B_ + b) * 1024 + c) =
            __floats2half2_rn(o[nt][0] * inv0, o[nt][1] * inv0);
        *(__half2*)(g_atth + ((size_t)row1 * B_ + b) * 1024 + c) =
            __floats2half2_rn(o[nt][2] * inv1, o[nt][3] * inv1);
    }
}

// ============================================================
// LayerNorm over D=1024 per row.
// ============================================================
__global__ __launch_bounds__(256) void ln_k(const float* __restrict__ gamma,
                                            const float* __restrict__ beta,
                                            float* __restrict__ out)
{
    __shared__ float reds[8], redq[8];
    const float* y = g_y + (size_t)blockIdx.x * D_;
    int tid = threadIdx.x;
    float v[4];
    float s = 0.f, q = 0.f;
#pragma unroll
    for (int t = 0; t < 4; t++) {
        v[t] = y[tid + t * 256];
        s += v[t]; q += v[t] * v[t];
    }
#pragma unroll
    for (int o = 16; o; o >>= 1) {
        s += __shfl_xor_sync(0xffffffffu, s, o);
        q += __shfl_xor_sync(0xffffffffu, q, o);
    }
    if ((tid & 31) == 0) { reds[tid >> 5] = s; redq[tid >> 5] = q; }
    __syncthreads();
    float ts = 0.f, tq = 0.f;
#pragma unroll
    for (int wv = 0; wv < 8; wv++) { ts += reds[wv]; tq += redq[wv]; }
    float mu = ts * (1.f / 1024.f);
    float var = tq * (1.f / 1024.f) - mu * mu;
    float inv = rsqrtf(var + 1e-5f);
    float* op = out + (size_t)blockIdx.x * D_;
#pragma unroll
    for (int t = 0; t < 4; t++) {
        int c = tid + t * 256;
        op[c] = (v[t] - mu) * inv * gamma[c] + beta[c];
    }
}

// ============================================================
extern "C" void kernel_launch(void* const* d_in, const int* in_sizes, int n_in,
                              void* d_out, int out_size)
{
    const float* x    = (const float*)d_in[0];
    const float* pe   = (const float*)d_in[1];
    const float* pbu  = (const float*)d_in[2];
    const float* pbv  = (const float*)d_in[3];
    const float* Wqkv = (const float*)d_in[4];
    const float* Wrel = (const float*)d_in[5];
    const float* Wo   = (const float*)d_in[6];
    const float* gam  = (const float*)d_in[7];
    const float* bet  = (const float*)d_in[8];
    float* out = (float*)d_out;

    const int PH_SMEM = 37888;     // fp16 pgemm: 2xA + 2xB stages
    const int BD_SMEM = 69632;     // f32 bd_gemm (also fits 128x132 stage)
    const int FA_SMEM = 92160;     // fp16 fattn: Q + 2xK + 2xV
    cudaFuncSetAttribute(pgemm_h<0>, cudaFuncAttributeMaxDynamicSharedMemorySize, PH_SMEM);
    cudaFuncSetAttribute(pgemm_h<1>, cudaFuncAttributeMaxDynamicSharedMemorySize, PH_SMEM);
    cudaFuncSetAttribute(pgemm_h<2>, cudaFuncAttributeMaxDynamicSharedMemorySize, PH_SMEM);
    cudaFuncSetAttribute(bd_gemm,    cudaFuncAttributeMaxDynamicSharedMemorySize, BD_SMEM);
    cudaFuncSetAttribute(fattn,      cudaFuncAttributeMaxDynamicSharedMemorySize, FA_SMEM);

    __half *xh, *peh, *wqkvh, *wrelh, *woh;
    cudaGetSymbolAddress((void**)&xh,    g_xh);
    cudaGetSymbolAddress((void**)&peh,   g_peh);
    cudaGetSymbolAddress((void**)&wqkvh, g_wqkvh);
    cudaGetSymbolAddress((void**)&wrelh, g_wrelh);
    cudaGetSymbolAddress((void**)&woh,   g_woh);

    // 0) fp16 conversions
    cvt_h<<<4096, 256>>>(x,    xh,    ROWS_ * 1024);
    cvt_h<<<2048, 256>>>(pe,   peh,   S_ * 1024);
    cvt_h<<<3072, 256>>>(Wqkv, wqkvh, 1024 * 3072);
    cvt_h<<<1024, 256>>>(Wrel, wrelh, 1024 * 1024);
    cvt_h<<<1024, 256>>>(Wo,   woh,   1024 * 1024);

    // 1) qkv = x @ W_qkv  (q -> f32 g_q; k,v -> fp16)
    pgemm_h<0><<<dim3(24, 32), 256, PH_SMEM>>>(xh, wqkvh, nullptr, 3072);
    // 2) r = pos_emb @ W_relemb
    pgemm_h<1><<<dim3(8, 16), 256, PH_SMEM>>>(peh, wrelh, nullptr, 1024);
    // 3) pre-shifted fp16 Draw = (q + pbv) @ r^T per (b,h)
    bd_gemm<<<dim3(16, 16, 32), 256, BD_SMEM>>>(pbv);
    // 4) fused: scores + shifted-BD add + softmax + PV -> g_atth fp16
    fattn<<<dim3(16, 32), 256, FA_SMEM>>>(pbu);
    // 5) y = x + attn_vec @ W_o   (A = g_atth selected inside kernel)
    pgemm_h<2><<<dim3(8, 32), 256, PH_SMEM>>>(nullptr, woh, x, 1024);
    // 6) layernorm
    ln_k<<<4096, 256>>>(gam, bet, out);
}

// round 16
// speedup vs baseline: 2.1149x; 1.1310x over previous
#include <cuda_runtime.h>
#include <cuda_fp16.h>
#include <stdint.h>

#define S_    2048
#define B_    2
#define D_    1024
#define H_    16
#define BH_   32
#define ROWS_ 4096

// ---- scratch (static device globals; no allocation) ----
__device__ __half g_xh  [(size_t)ROWS_ * 1024];        // x fp16
__device__ __half g_peh [(size_t)S_ * 1024];           // pos_emb fp16
__device__ __half g_wqkvh[(size_t)1024 * 3072];        // W_qkv fp16
__device__ __half g_wrelh[(size_t)1024 * 1024];        // W_relemb fp16
__device__ __half g_woh [(size_t)1024 * 1024];         // W_o fp16
__device__ __half g_qh [(size_t)ROWS_ * 1024];         // q fp16 [s*B+b][h*64+d]
__device__ __half g_kh [(size_t)ROWS_ * 1024];         // K fp16
__device__ __half g_vh [(size_t)ROWS_ * 1024];         // V fp16
__device__ __half g_rh [(size_t)S_ * 1024];            // r fp16 [t][h*64+d]
__device__ __half g_bd [(size_t)BH_ * S_ * S_];        // PRE-SHIFTED BD, fp16
__device__ __half g_atth[(size_t)ROWS_ * 1024];        // attn_vec fp16
__device__ float  g_y  [(size_t)ROWS_ * D_];           // x + attn_out

// ---------------- mma / cp.async / ldmatrix helpers ----------------
__device__ __forceinline__ void mma16h(float* d, const uint32_t* a,
                                       const uint32_t* b, const float* c) {
    asm volatile(
        "mma.sync.aligned.m16n8k16.row.col.f32.f16.f16.f32 "
        "{%0,%1,%2,%3}, {%4,%5,%6,%7}, {%8,%9}, {%10,%11,%12,%13};\n"
        : "=f"(d[0]), "=f"(d[1]), "=f"(d[2]), "=f"(d[3])
        : "r"(a[0]), "r"(a[1]), "r"(a[2]), "r"(a[3]), "r"(b[0]), "r"(b[1]),
          "f"(c[0]), "f"(c[1]), "f"(c[2]), "f"(c[3]));
}
__device__ __forceinline__ uint32_t h2(float lo, float hi) {
    uint32_t d;
    asm("cvt.rn.f16x2.f32 %0, %1, %2;\n" : "=r"(d) : "f"(hi), "f"(lo));
    return d;
}
__device__ __forceinline__ void cpa16(uint32_t s, const void* g) {
    asm volatile("cp.async.cg.shared.global [%0], [%1], 16;\n" :: "r"(s), "l"(g));
}
__device__ __forceinline__ void cpcommit() { asm volatile("cp.async.commit_group;\n"); }
template <int N> __device__ __forceinline__ void cpwait() {
    asm volatile("cp.async.wait_group %0;\n" :: "n"(N));
}
__device__ __forceinline__ void ldsm4(uint32_t* r, uint32_t a) {
    asm volatile("ldmatrix.sync.aligned.m8n8.x4.shared.b16 {%0,%1,%2,%3}, [%4];\n"
        : "=r"(r[0]), "=r"(r[1]), "=r"(r[2]), "=r"(r[3]) : "r"(a));
}
__device__ __forceinline__ void ldsm4t(uint32_t* r, uint32_t a) {
    asm volatile("ldmatrix.sync.aligned.m8n8.x4.trans.shared.b16 {%0,%1,%2,%3}, [%4];\n"
        : "=r"(r[0]), "=r"(r[1]), "=r"(r[2]), "=r"(r[3]) : "r"(a));
}
__device__ __forceinline__ float ex2(float x) {
    float y; asm("ex2.approx.f32 %0, %1;" : "=f"(y) : "f"(x)); return y;
}

// ============================================================
// f32 -> fp16 conversion (float4 groups)
// ============================================================
__global__ __launch_bounds__(256) void cvt_h(const float* __restrict__ s,
                                             __half* __restrict__ d, int n)
{
    int i = (blockIdx.x * 256 + threadIdx.x) * 4;
    if (i < n) {
        float4 v = *(const float4*)(s + i);
        *(__half2*)(d + i)     = __floats2half2_rn(v.x, v.y);
        *(__half2*)(d + i + 2) = __floats2half2_rn(v.z, v.w);
    }
}

// ============================================================
// fp16 projection GEMM: C[M,N] = A[M,1024] @ B[1024,N].
// Tile 128x128x32, m16n8k16, A via ldsm4, B via ldsm4t, 2-stage.
// MODE 0: q->g_qh / k->g_kh / v->g_vh (all fp16).
// MODE 1: r->g_rh fp16.
// MODE 2: A = g_atth (device symbol), g_y = acc + Xres (f32).
// ============================================================
template <int MODE>
__global__ __launch_bounds__(256) void pgemm_h(const __half* __restrict__ Ah,
                                               const __half* __restrict__ Bh,
                                               const float* __restrict__ Xres,
                                               int N)
{
    extern __shared__ __half smH[];
    uint32_t sb = (uint32_t)__cvta_generic_to_shared(smH);
    int tid = threadIdx.x, l = tid & 31, w = tid >> 5;
    size_t m0 = (size_t)blockIdx.y * 128, n0 = (size_t)blockIdx.x * 128;
    const __half* Ap = (MODE == 2) ? (const __half*)g_atth : Ah;

    float acc[16][4] = {};

#define STG(IT, BUF)                                                            \
    {                                                                           \
        int kk = (IT) * 32;                                                     \
        uint32_t ab = sb + (BUF) * 10240;                                       \
        _Pragma("unroll")                                                       \
        for (int t = 0; t < 2; t++) {                                           \
            int idx = tid + t * 256; int r = idx >> 2, c8 = (idx & 3) << 3;     \
            cpa16(ab + (r * 40 + c8) * 2, Ap + (m0 + r) * 1024 + kk + c8);      \
        }                                                                       \
        uint32_t bb = sb + 20480 + (BUF) * 8704;                                \
        _Pragma("unroll")                                                       \
        for (int t = 0; t < 2; t++) {                                           \
            int idx = tid + t * 256; int r = idx >> 4, c8 = (idx & 15) << 3;    \
            cpa16(bb + (r * 136 + c8) * 2, Bh + (size_t)(kk + r) * N + n0 + c8);\
        }                                                                       \
        cpcommit();                                                             \
    }

    uint32_t aoff = (uint32_t)((w * 16 + (l & 7) + ((l >> 3) & 1) * 8) * 80
                               + ((l >> 4) & 1) * 16);
    uint32_t boff = (uint32_t)(((l & 7) + ((l >> 3) & 1) * 8) * 272 + (l >> 4) * 16);

    STG(0, 0);
    for (int it = 0; it < 32; it++) {
        int buf = it & 1;
        if (it + 1 < 32) { STG(it + 1, buf ^ 1); cpwait<1>(); }
        else             { cpwait<0>(); }
        __syncthreads();
        uint32_t ab = sb + buf * 10240;
        uint32_t bb = sb + 20480 + buf * 8704;
#pragma unroll
        for (int ks = 0; ks < 2; ks++) {
            uint32_t af[4];
            ldsm4(af, ab + aoff + ks * 32);
#pragma unroll
            for (int nb = 0; nb < 8; nb++) {
                uint32_t vb[4];
                ldsm4t(vb, bb + boff + ks * 16 * 272 + nb * 32);
                mma16h(acc[2 * nb],     af, vb,     acc[2 * nb]);
                mma16h(acc[2 * nb + 1], af, vb + 2, acc[2 * nb + 1]);
            }
        }
        __syncthreads();
    }
#undef STG

    size_t r0 = m0 + w * 16 + (l >> 2);
    if (MODE == 0 || MODE == 1) {
        __half* dst;
        size_t cb;
        if (MODE == 1)          { dst = g_rh; cb = n0; }
        else if (n0 < 1024)     { dst = g_qh; cb = n0; }
        else if (n0 < 2048)     { dst = g_kh; cb = n0 - 1024; }
        else                    { dst = g_vh; cb = n0 - 2048; }
#pragma unroll
        for (int nn = 0; nn < 16; nn++) {
            size_t c = cb + nn * 8 + 2 * (l & 3);
            *(__half2*)(dst + r0 * 1024 + c) =
                __floats2half2_rn(acc[nn][0], acc[nn][1]);
            *(__half2*)(dst + (r0 + 8) * 1024 + c) =
                __floats2half2_rn(acc[nn][2], acc[nn][3]);
        }
        return;
    }
#pragma unroll
    for (int nn = 0; nn < 16; nn++) {
        size_t c = n0 + nn * 8 + 2 * (l & 3);
        float2 x0 = *(const float2*)(Xres + r0 * N + c);
        float2 x1 = *(const float2*)(Xres + (r0 + 8) * N + c);
        *(float2*)(g_y + r0 * N + c) =
            make_float2(acc[nn][0] + x0.x, acc[nn][1] + x0.y);
        *(float2*)(g_y + (r0 + 8) * N + c) =
            make_float2(acc[nn][2] + x1.x, acc[nn][3] + x1.y);
    }
}

// ============================================================
// Draw = (q + pos_bias_v) @ r^T per (b,h), PRE-SHIFTED fp16 out.
// fp16 m16n8k16 (q+bias fp16 smem, r via cp.async).
//   tcol = t + i + 1;  if tcol >= S -> (row i, col tcol-S)
//                      else -> (row i-1, col tcol) [dropped if i==0]
// fp16 smem-staged epilogue, lane-consecutive streaming stores.
// ============================================================
__global__ __launch_bounds__(256, 2) void bd_gemm(const float* __restrict__ pbv)
{
    extern __shared__ __half smB[];
    __half* Qs = smB;             // 128 x 72 fp16
    __half* Rs = smB + 9216;      // 128 x 72 fp16
    int tid = threadIdx.x, l = tid & 31, w = tid >> 5;
    int bh = blockIdx.z, b = bh >> 4, h = bh & 15;
    int i0 = blockIdx.y * 128, t0 = blockIdx.x * 128;
    const __half* Qg = g_qh + (size_t)b * 1024 + h * 64;   // row stride 2048
    const __half* Rg = g_rh + h * 64;                      // row stride 1024
    const float* bias = pbv + h * 64;
    uint32_t sQ = (uint32_t)__cvta_generic_to_shared(Qs);
    uint32_t sR = (uint32_t)__cvta_generic_to_shared(Rs);

    // R tile -> smem (raw fp16 copy)
#pragma unroll
    for (int t = 0; t < 4; t++) {
        int idx = tid + t * 256; int r = idx >> 3, c8 = (idx & 7) << 3;
        cpa16(sR + (r * 72 + c8) * 2, Rg + (size_t)(t0 + r) * 1024 + c8);
    }
    cpcommit();
    // Q + bias -> fp16 smem
#pragma unroll
    for (int t = 0; t < 8; t++) {
        int idx = tid + t * 256; int r = idx >> 4, c4 = (idx & 15) << 2;
        float2 f0 = __half22float2(*(const __half2*)(Qg + (size_t)(i0 + r) * 2048 + c4));
        float2 f1 = __half22float2(*(const __half2*)(Qg + (size_t)(i0 + r) * 2048 + c4 + 2));
        float4 u4 = *(const float4*)(bias + c4);
        *(__half2*)(Qs + r * 72 + c4)     = __floats2half2_rn(f0.x + u4.x, f0.y + u4.y);
        *(__half2*)(Qs + r * 72 + c4 + 2) = __floats2half2_rn(f1.x + u4.z, f1.y + u4.w);
    }
    cpwait<0>();
    __syncthreads();

    uint32_t qoff = (uint32_t)((w * 16 + (l & 7) + ((l >> 3) & 1) * 8) * 144
                               + ((l >> 4) & 1) * 16);
    uint32_t roff = (uint32_t)(((l & 7) + (l >> 4) * 8) * 144 + ((l >> 3) & 1) * 16);

    float acc[16][4] = {};
#pragma unroll
    for (int ks = 0; ks < 4; ks++) {
        uint32_t qf[4];
        ldsm4(qf, sQ + qoff + ks * 32);
#pragma unroll
        for (int np = 0; np < 8; np++) {
            uint32_t kb[4];
            ldsm4(kb, sR + roff + (np * 16) * 144 + ks * 32);
            mma16h(acc[2 * np],     qf, kb,     acc[2 * np]);
            mma16h(acc[2 * np + 1], qf, kb + 2, acc[2 * np + 1]);
        }
    }

    // stage fp16 (overlays Qs/Rs), then coalesced shifted stores
    __syncthreads();
    __half* stage = smB;          // 128 x 136 fp16 = 34816 B
    int lr0 = w * 16 + (l >> 2);
#pragma unroll
    for (int nt = 0; nt < 16; nt++) {
        int c = nt * 8 + 2 * (l & 3);
        *(__half2*)&stage[lr0 * 136 + c] =
            __floats2half2_rn(acc[nt][0], acc[nt][1]);
        *(__half2*)&stage[(lr0 + 8) * 136 + c] =
            __floats2half2_rn(acc[nt][2], acc[nt][3]);
    }
    __syncthreads();

    __half* out = g_bd + (size_t)bh * S_ * S_;
#pragma unroll
    for (int rr = 0; rr < 16; rr++) {
        int r = w * 16 + rr;
        int gi = i0 + r;
        int base = t0 + gi + 1;
#pragma unroll
        for (int j = 0; j < 4; j++) {
            int c = l + 32 * j;
            int tcol = base + c;
            __half v = stage[r * 136 + c];
            if (tcol >= S_)      __stcs(out + (size_t)gi * S_ + (tcol - S_), v);
            else if (gi > 0)     __stcs(out + (size_t)(gi - 1) * S_ + tcol, v);
        }
    }
}

// ============================================================
// Fused attention: all-fp16 mma, K/V double-buffered,
// pre-shifted fp16 BD. Output -> g_atth fp16.
// ============================================================
__global__ __launch_bounds__(256, 2) void fattn(const float* __restrict__ pbu)
{
    extern __shared__ __half smh[];
    __half* Qsh = smh;                      // 128 x 72 fp16 (persistent)
    int tid = threadIdx.x, l = tid & 31, w = tid >> 5;
    int bh = blockIdx.y, b = bh >> 4, h = bh & 15;
    int i0 = blockIdx.x * 128;
    const __half* Qg = g_qh + (size_t)b * 1024 + h * 64;   // row stride 2048
    const __half* Kg = g_kh + (size_t)b * 1024 + h * 64;
    const __half* Vg = g_vh + (size_t)b * 1024 + h * 64;
    const __half* bd = g_bd + (size_t)bh * S_ * S_;
    const float* bias = pbu + h * 64;
    uint32_t sQ     = (uint32_t)__cvta_generic_to_shared(Qsh);
    uint32_t sKbase = (uint32_t)__cvta_generic_to_shared(smh + 9216);
    uint32_t sVbase = (uint32_t)__cvta_generic_to_shared(smh + 27648);

    // (q + bias_u) -> fp16 smem
#pragma unroll
    for (int t = 0; t < 8; t++) {
        int idx = tid + t * 256; int r = idx >> 4, c4 = (idx & 15) << 2;
        float2 f0 = __half22float2(*(const __half2*)(Qg + (size_t)(i0 + r) * 2048 + c4));
        float2 f1 = __half22float2(*(const __half2*)(Qg + (size_t)(i0 + r) * 2048 + c4 + 2));
        float4 u4 = *(const float4*)(bias + c4);
        *(__half2*)(Qsh + r * 72 + c4)     = __floats2half2_rn(f0.x + u4.x, f0.y + u4.y);
        *(__half2*)(Qsh + r * 72 + c4 + 2) = __floats2half2_rn(f1.x + u4.z, f1.y + u4.w);
    }

#define PFKV(IT, BO)                                                            \
    {                                                                           \
        const __half* kn = Kg + (size_t)((IT) * 128) * 2048;                    \
        const __half* vn = Vg + (size_t)((IT) * 128) * 2048;                    \
        _Pragma("unroll")                                                       \
        for (int t = 0; t < 4; t++) {                                           \
            int idx = tid + t * 256; int r = idx >> 3, c8 = (idx & 7) << 3;     \
            cpa16(sKbase + (BO) + (r * 72 + c8) * 2, kn + (size_t)r * 2048 + c8);\
            cpa16(sVbase + (BO) + (r * 72 + c8) * 2, vn + (size_t)r * 2048 + c8);\
        }                                                                       \
        cpcommit();                                                             \
    }

    PFKV(0, 0)
    PFKV(1, 18432)

    uint32_t qoff  = (uint32_t)((w * 16 + (l & 7) + ((l >> 3) & 1) * 8) * 144
                                + ((l >> 4) & 1) * 16);
    uint32_t kboff = (uint32_t)(((l & 7) + (l >> 4) * 8) * 144 + ((l >> 3) & 1) * 16);
    uint32_t vrbase = (uint32_t)((l & 7) + ((l >> 3) & 1) * 8);
    uint32_t vcoff  = (uint32_t)((l >> 4) * 8);

    float o[8][4] = {};
    float bdbuf[32];
    float mrow0 = -1e30f, mrow1 = -1e30f, lsum0 = 0.f, lsum1 = 0.f;
    int tc = l & 3;
    int lr0 = w * 16 + (l >> 2);
    int row0 = i0 + lr0, row1 = row0 + 8;
    const float CS = 0.1803368801111204f;   // 0.125 * log2(e)

#define LDBD(JB)                                                                \
    _Pragma("unroll")                                                           \
    for (int nt = 0; nt < 8; nt++) {                                            \
        int c0 = (JB) + nt * 8 + 2 * tc;                                        \
        __half2 h0 = __ldcs((const __half2*)(bd + (size_t)row0 * S_ + c0));     \
        __half2 h1 = __ldcs((const __half2*)(bd + (size_t)row1 * S_ + c0));     \
        float2 v0 = __half22float2(h0);                                         \
        float2 v1 = __half22float2(h1);                                         \
        bdbuf[nt * 4 + 0] = (c0     == row0 + 1) ? 0.f : v0.x;                  \
        bdbuf[nt * 4 + 1] = (c0 + 1 == row0 + 1) ? 0.f : v0.y;                  \
        bdbuf[nt * 4 + 2] = (c0     == row1 + 1) ? 0.f : v1.x;                  \
        bdbuf[nt * 4 + 3] = (c0 + 1 == row1 + 1) ? 0.f : v1.y;                  \
    }

    LDBD(0)

#define AC_MMA(HALF)                                                            \
    _Pragma("unroll")                                                           \
    for (int nt = 0; nt < 8; nt++)                                              \
        p[nt][0] = p[nt][1] = p[nt][2] = p[nt][3] = 0.f;                        \
    _Pragma("unroll")                                                           \
    for (int ks = 0; ks < 4; ks++) {                                            \
        uint32_t qf[4];                                                         \
        ldsm4(qf, sQ + qoff + ks * 32);                                         \
        _Pragma("unroll")                                                       \
        for (int np = 0; np < 4; np++) {                                        \
            uint32_t kb[4];                                                     \
            ldsm4(kb, sK + kboff + ((HALF) * 64 + np * 16) * 144 + ks * 32);    \
            mma16h(p[2 * np],     qf, kb,     p[2 * np]);                       \
            mma16h(p[2 * np + 1], qf, kb + 2, p[2 * np + 1]);                   \
        }                                                                       \
    }

#define SOFTMAX_STEP()                                                          \
    {                                                                           \
        float mx0 = -1e30f, mx1 = -1e30f;                                       \
        _Pragma("unroll")                                                       \
        for (int nt = 0; nt < 8; nt++) {                                        \
            float s;                                                            \
            s = (p[nt][0] + bdbuf[nt*4+0]) * CS; p[nt][0] = s; mx0 = fmaxf(mx0, s); \
            s = (p[nt][1] + bdbuf[nt*4+1]) * CS; p[nt][1] = s; mx0 = fmaxf(mx0, s); \
            s = (p[nt][2] + bdbuf[nt*4+2]) * CS; p[nt][2] = s; mx1 = fmaxf(mx1, s); \
            s = (p[nt][3] + bdbuf[nt*4+3]) * CS; p[nt][3] = s; mx1 = fmaxf(mx1, s); \
        }                                                                       \
        mx0 = fmaxf(mx0, __shfl_xor_sync(~0u, mx0, 1));                         \
        mx0 = fmaxf(mx0, __shfl_xor_sync(~0u, mx0, 2));                         \
        mx1 = fmaxf(mx1, __shfl_xor_sync(~0u, mx1, 1));                         \
        mx1 = fmaxf(mx1, __shfl_xor_sync(~0u, mx1, 2));                         \
        float mn0 = fmaxf(mrow0, mx0), mn1 = fmaxf(mrow1, mx1);                 \
        float al0 = ex2(mrow0 - mn0), al1 = ex2(mrow1 - mn1);                   \
        mrow0 = mn0; mrow1 = mn1;                                               \
        float rs0 = 0.f, rs1 = 0.f;                                             \
        _Pragma("unroll")                                                       \
        for (int nt = 0; nt < 8; nt++) {                                        \
            p[nt][0] = ex2(p[nt][0] - mn0); p[nt][1] = ex2(p[nt][1] - mn0);     \
            p[nt][2] = ex2(p[nt][2] - mn1); p[nt][3] = ex2(p[nt][3] - mn1);     \
            rs0 += p[nt][0] + p[nt][1]; rs1 += p[nt][2] + p[nt][3];             \
        }                                                                       \
        rs0 += __shfl_xor_sync(~0u, rs0, 1); rs0 += __shfl_xor_sync(~0u, rs0, 2);\
        rs1 += __shfl_xor_sync(~0u, rs1, 1); rs1 += __shfl_xor_sync(~0u, rs1, 2);\
        lsum0 = lsum0 * al0 + rs0;                                              \
        lsum1 = lsum1 * al1 + rs1;                                              \
        _Pragma("unroll")                                                       \
        for (int nt = 0; nt < 8; nt++) {                                        \
            o[nt][0] *= al0; o[nt][1] *= al0; o[nt][2] *= al1; o[nt][3] *= al1; \
        }                                                                       \
    }

#define CVT_P()                                                                 \
    uint32_t af[4][4];                                                          \
    _Pragma("unroll")                                                           \
    for (int ks = 0; ks < 4; ks++) {                                            \
        af[ks][0] = h2(p[2*ks][0],   p[2*ks][1]);                               \
        af[ks][1] = h2(p[2*ks][2],   p[2*ks][3]);                               \
        af[ks][2] = h2(p[2*ks+1][0], p[2*ks+1][1]);                             \
        af[ks][3] = h2(p[2*ks+1][2], p[2*ks+1][3]);                             \
    }

#define PV16(HALF)                                                              \
    _Pragma("unroll")                                                           \
    for (int ks = 0; ks < 4; ks++) {                                            \
        uint32_t vrow = (uint32_t)((HALF) * 64 + ks * 16) + vrbase;             \
        _Pragma("unroll")                                                       \
        for (int ntt = 0; ntt < 4; ntt++) {                                     \
            uint32_t vb[4];                                                     \
            ldsm4t(vb, sV + (vrow * 72 + ntt * 16 + vcoff) * 2);                \
            mma16h(o[2*ntt],   af[ks], vb,   o[2*ntt]);                         \
            mma16h(o[2*ntt+1], af[ks], vb+2, o[2*ntt+1]);                       \
        }                                                                       \
    }

    for (int it = 0; it < 16; it++) {
        uint32_t bo = (uint32_t)(it & 1) * 18432;
        uint32_t sK = sKbase + bo;
        uint32_t sV = sVbase + bo;
        if (it == 15) cpwait<0>(); else cpwait<1>();
        __syncthreads();

        {   // ---- half 0 ----
            float p[8][4];
            AC_MMA(0)
            SOFTMAX_STEP()
            CVT_P()
            LDBD(it * 128 + 64)
            PV16(0)
        }
        {   // ---- half 1 ----
            float p[8][4];
            AC_MMA(1)
            SOFTMAX_STEP()
            CVT_P()
            if (it + 1 < 16) LDBD((it + 1) * 128)
            PV16(1)
        }
        __syncthreads();
        if (it + 2 < 16) PFKV(it + 2, bo)
    }
#undef PFKV
#undef LDBD
#undef AC_MMA
#undef SOFTMAX_STEP
#undef CVT_P
#undef PV16

    float inv0 = 1.f / lsum0, inv1 = 1.f / lsum1;
#pragma unroll
    for (int nt = 0; nt < 8; nt++) {
        int c = h * 64 + nt * 8 + 2 * tc;
        *(__half2*)(g_atth + ((size_t)row0 * B_ + b) * 1024 + c) =
            __floats2half2_rn(o[nt][0] * inv0, o[nt][1] * inv0);
        *(__half2*)(g_atth + ((size_t)row1 * B_ + b) * 1024 + c) =
            __floats2half2_rn(o[nt][2] * inv1, o[nt][3] * inv1);
    }
}

// ============================================================
// LayerNorm over D=1024 per row.
// ============================================================
__global__ __launch_bounds__(256) void ln_k(const float* __restrict__ gamma,
                                            const float* __restrict__ beta,
                                            float* __restrict__ out)
{
    __shared__ float reds[8], redq[8];
    const float* y = g_y + (size_t)blockIdx.x * D_;
    int tid = threadIdx.x;
    float v[4];
    float s = 0.f, q = 0.f;
#pragma unroll
    for (int t = 0; t < 4; t++) {
        v[t] = y[tid + t * 256];
        s += v[t]; q += v[t] * v[t];
    }
#pragma unroll
    for (int o = 16; o; o >>= 1) {
        s += __shfl_xor_sync(0xffffffffu, s, o);
        q += __shfl_xor_sync(0xffffffffu, q, o);
    }
    if ((tid & 31) == 0) { reds[tid >> 5] = s; redq[tid >> 5] = q; }
    __syncthreads();
    float ts = 0.f, tq = 0.f;
#pragma unroll
    for (int wv = 0; wv < 8; wv++) { ts += reds[wv]; tq += redq[wv]; }
    float mu = ts * (1.f / 1024.f);
    float var = tq * (1.f / 1024.f) - mu * mu;
    float inv = rsqrtf(var + 1e-5f);
    float* op = out + (size_t)blockIdx.x * D_;
#pragma unroll
    for (int t = 0; t < 4; t++) {
        int c = tid + t * 256;
        op[c] = (v[t] - mu) * inv * gamma[c] + beta[c];
    }
}

// ============================================================
extern "C" void kernel_launch(void* const* d_in, const int* in_sizes, int n_in,
                              void* d_out, int out_size)
{
    const float* x    = (const float*)d_in[0];
    const float* pe   = (const float*)d_in[1];
    const float* pbu  = (const float*)d_in[2];
    const float* pbv  = (const float*)d_in[3];
    const float* Wqkv = (const float*)d_in[4];
    const float* Wrel = (const float*)d_in[5];
    const float* Wo   = (const float*)d_in[6];
    const float* gam  = (const float*)d_in[7];
    const float* bet  = (const float*)d_in[8];
    float* out = (float*)d_out;

    const int PH_SMEM = 37888;     // fp16 pgemm: 2xA + 2xB stages
    const int BD_SMEM = 36864;     // fp16 bd_gemm: Q + R (stage overlays)
    const int FA_SMEM = 92160;     // fp16 fattn: Q + 2xK + 2xV
    cudaFuncSetAttribute(pgemm_h<0>, cudaFuncAttributeMaxDynamicSharedMemorySize, PH_SMEM);
    cudaFuncSetAttribute(pgemm_h<1>, cudaFuncAttributeMaxDynamicSharedMemorySize, PH_SMEM);
    cudaFuncSetAttribute(pgemm_h<2>, cudaFuncAttributeMaxDynamicSharedMemorySize, PH_SMEM);
    cudaFuncSetAttribute(bd_gemm,    cudaFuncAttributeMaxDynamicSharedMemorySize, BD_SMEM);
    cudaFuncSetAttribute(fattn,      cudaFuncAttributeMaxDynamicSharedMemorySize, FA_SMEM);

    __half *xh, *peh, *wqkvh, *wrelh, *woh;
    cudaGetSymbolAddress((void**)&xh,    g_xh);
    cudaGetSymbolAddress((void**)&peh,   g_peh);
    cudaGetSymbolAddress((void**)&wqkvh, g_wqkvh);
    cudaGetSymbolAddress((void**)&wrelh, g_wrelh);
    cudaGetSymbolAddress((void**)&woh,   g_woh);

    // 0) fp16 conversions
    cvt_h<<<4096, 256>>>(x,    xh,    ROWS_ * 1024);
    cvt_h<<<2048, 256>>>(pe,   peh,   S_ * 1024);
    cvt_h<<<3072, 256>>>(Wqkv, wqkvh, 1024 * 3072);
    cvt_h<<<1024, 256>>>(Wrel, wrelh, 1024 * 1024);
    cvt_h<<<1024, 256>>>(Wo,   woh,   1024 * 1024);

    // 1) qkv = x @ W_qkv  (q, k, v -> fp16)
    pgemm_h<0><<<dim3(24, 32), 256, PH_SMEM>>>(xh, wqkvh, nullptr, 3072);
    // 2) r = pos_emb @ W_relemb -> fp16
    pgemm_h<1><<<dim3(8, 16), 256, PH_SMEM>>>(peh, wrelh, nullptr, 1024);
    // 3) pre-shifted fp16 Draw = (q + pbv) @ r^T per (b,h), fp16 mma
    bd_gemm<<<dim3(16, 16, 32), 256, BD_SMEM>>>(pbv);
    // 4) fused: scores + shifted-BD add + softmax + PV -> g_atth fp16
    fattn<<<dim3(16, 32), 256, FA_SMEM>>>(pbu);
    // 5) y = x + attn_vec @ W_o   (A = g_atth selected inside kernel)
    pgemm_h<2><<<dim3(8, 32), 256, PH_SMEM>>>(nullptr, woh, x, 1024);
    // 6) layernorm
    ln_k<<<4096, 256>>>(gam, bet, out);
}

// round 17
// speedup vs baseline: 2.1921x; 1.0365x over previous
#include <cuda_runtime.h>
#include <cuda_fp16.h>
#include <stdint.h>

#define S_    2048
#define B_    2
#define D_    1024
#define H_    16
#define BH_   32
#define ROWS_ 4096

// ---- scratch (static device globals; no allocation) ----
__device__ __half g_xh  [(size_t)ROWS_ * 1024];        // x fp16
__device__ __half g_peh [(size_t)S_ * 1024];           // pos_emb fp16
__device__ __half g_wqkvh[(size_t)1024 * 3072];        // W_qkv fp16
__device__ __half g_wrelh[(size_t)1024 * 1024];        // W_relemb fp16
__device__ __half g_woh [(size_t)1024 * 1024];         // W_o fp16
__device__ __half g_qh [(size_t)ROWS_ * 1024];         // q fp16 [s*B+b][h*64+d]
__device__ __half g_kh [(size_t)ROWS_ * 1024];         // K fp16
__device__ __half g_vh [(size_t)ROWS_ * 1024];         // V fp16
__device__ __half g_rh [(size_t)S_ * 1024];            // r fp16 [t][h*64+d]
__device__ __half g_bd [(size_t)BH_ * S_ * S_];        // PRE-SHIFTED BD, fp16
__device__ __half g_atth[(size_t)ROWS_ * 1024];        // attn_vec fp16
__device__ float  g_y  [(size_t)ROWS_ * D_];           // x + attn_out

// ---------------- mma / cp.async / ldmatrix helpers ----------------
__device__ __forceinline__ void mma16h(float* d, const uint32_t* a,
                                       const uint32_t* b, const float* c) {
    asm volatile(
        "mma.sync.aligned.m16n8k16.row.col.f32.f16.f16.f32 "
        "{%0,%1,%2,%3}, {%4,%5,%6,%7}, {%8,%9}, {%10,%11,%12,%13};\n"
        : "=f"(d[0]), "=f"(d[1]), "=f"(d[2]), "=f"(d[3])
        : "r"(a[0]), "r"(a[1]), "r"(a[2]), "r"(a[3]), "r"(b[0]), "r"(b[1]),
          "f"(c[0]), "f"(c[1]), "f"(c[2]), "f"(c[3]));
}
__device__ __forceinline__ uint32_t h2(float lo, float hi) {
    uint32_t d;
    asm("cvt.rn.f16x2.f32 %0, %1, %2;\n" : "=r"(d) : "f"(hi), "f"(lo));
    return d;
}
__device__ __forceinline__ void cpa16(uint32_t s, const void* g) {
    asm volatile("cp.async.cg.shared.global [%0], [%1], 16;\n" :: "r"(s), "l"(g));
}
__device__ __forceinline__ void cpcommit() { asm volatile("cp.async.commit_group;\n"); }
template <int N> __device__ __forceinline__ void cpwait() {
    asm volatile("cp.async.wait_group %0;\n" :: "n"(N));
}
__device__ __forceinline__ void ldsm4(uint32_t* r, uint32_t a) {
    asm volatile("ldmatrix.sync.aligned.m8n8.x4.shared.b16 {%0,%1,%2,%3}, [%4];\n"
        : "=r"(r[0]), "=r"(r[1]), "=r"(r[2]), "=r"(r[3]) : "r"(a));
}
__device__ __forceinline__ void ldsm4t(uint32_t* r, uint32_t a) {
    asm volatile("ldmatrix.sync.aligned.m8n8.x4.trans.shared.b16 {%0,%1,%2,%3}, [%4];\n"
        : "=r"(r[0]), "=r"(r[1]), "=r"(r[2]), "=r"(r[3]) : "r"(a));
}
__device__ __forceinline__ float ex2(float x) {
    float y; asm("ex2.approx.f32 %0, %1;" : "=f"(y) : "f"(x)); return y;
}

// ============================================================
// Fused f32 -> fp16 conversion of all 5 inputs, one launch.
// Block ranges: [0,4096) x | [4096,6144) pe | [6144,9216) Wqkv |
// [9216,10240) Wrel | [10240,11264) Wo.  Each block: 1024 elems.
// ============================================================
__global__ __launch_bounds__(256) void cvt_all(const float* __restrict__ x,
                                               const float* __restrict__ pe,
                                               const float* __restrict__ wqkv,
                                               const float* __restrict__ wrel,
                                               const float* __restrict__ wo)
{
    int bid = blockIdx.x;
    const float* s; __half* d; int base;
    if (bid < 4096)       { s = x;    d = g_xh;    base = bid; }
    else if (bid < 6144)  { s = pe;   d = g_peh;   base = bid - 4096; }
    else if (bid < 9216)  { s = wqkv; d = g_wqkvh; base = bid - 6144; }
    else if (bid < 10240) { s = wrel; d = g_wrelh; base = bid - 9216; }
    else                  { s = wo;   d = g_woh;   base = bid - 10240; }
    int i = (base * 256 + threadIdx.x) * 4;
    float4 v = *(const float4*)(s + i);
    *(__half2*)(d + i)     = __floats2half2_rn(v.x, v.y);
    *(__half2*)(d + i + 2) = __floats2half2_rn(v.z, v.w);
}

// ============================================================
// fp16 projection GEMM: C[M,N] = A[M,1024] @ B[1024,N].
// Tile 128x128x32, m16n8k16, A via ldsm4, B via ldsm4t, 3-stage.
// MODE 0: q/k/v -> fp16.  MODE 1: r -> fp16.
// MODE 2: A = g_atth (device symbol), g_y = acc + Xres (f32).
// ============================================================
template <int MODE>
__global__ __launch_bounds__(256) void pgemm_h(const __half* __restrict__ Ah,
                                               const __half* __restrict__ Bh,
                                               const float* __restrict__ Xres,
                                               int N)
{
    extern __shared__ __half smH[];
    // A bufs: bytes BUF*10240 (128 x 40 halves); B bufs: 30720 + BUF*8704
    uint32_t sb = (uint32_t)__cvta_generic_to_shared(smH);
    int tid = threadIdx.x, l = tid & 31, w = tid >> 5;
    size_t m0 = (size_t)blockIdx.y * 128, n0 = (size_t)blockIdx.x * 128;
    const __half* Ap = (MODE == 2) ? (const __half*)g_atth : Ah;

    float acc[16][4] = {};

#define STG(IT, BUF)                                                            \
    {                                                                           \
        int kk = (IT) * 32;                                                     \
        uint32_t ab = sb + (BUF) * 10240;                                       \
        _Pragma("unroll")                                                       \
        for (int t = 0; t < 2; t++) {                                           \
            int idx = tid + t * 256; int r = idx >> 2, c8 = (idx & 3) << 3;     \
            cpa16(ab + (r * 40 + c8) * 2, Ap + (m0 + r) * 1024 + kk + c8);      \
        }                                                                       \
        uint32_t bb = sb + 30720 + (BUF) * 8704;                                \
        _Pragma("unroll")                                                       \
        for (int t = 0; t < 2; t++) {                                           \
            int idx = tid + t * 256; int r = idx >> 4, c8 = (idx & 15) << 3;    \
            cpa16(bb + (r * 136 + c8) * 2, Bh + (size_t)(kk + r) * N + n0 + c8);\
        }                                                                       \
        cpcommit();                                                             \
    }

    uint32_t aoff = (uint32_t)((w * 16 + (l & 7) + ((l >> 3) & 1) * 8) * 80
                               + ((l >> 4) & 1) * 16);
    uint32_t boff = (uint32_t)(((l & 7) + ((l >> 3) & 1) * 8) * 272 + (l >> 4) * 16);

    STG(0, 0);
    STG(1, 1);
    for (int it = 0; it < 32; it++) {
        int buf = it % 3;
        if (it + 2 < 32)      { STG(it + 2, (it + 2) % 3); cpwait<2>(); }
        else if (it + 1 < 32) { cpwait<1>(); }
        else                  { cpwait<0>(); }
        __syncthreads();
        uint32_t ab = sb + buf * 10240;
        uint32_t bb = sb + 30720 + buf * 8704;
#pragma unroll
        for (int ks = 0; ks < 2; ks++) {
            uint32_t af[4];
            ldsm4(af, ab + aoff + ks * 32);
#pragma unroll
            for (int nb = 0; nb < 8; nb++) {
                uint32_t vb[4];
                ldsm4t(vb, bb + boff + ks * 16 * 272 + nb * 32);
                mma16h(acc[2 * nb],     af, vb,     acc[2 * nb]);
                mma16h(acc[2 * nb + 1], af, vb + 2, acc[2 * nb + 1]);
            }
        }
        __syncthreads();
    }
#undef STG

    size_t r0 = m0 + w * 16 + (l >> 2);
    if (MODE == 0 || MODE == 1) {
        __half* dst;
        size_t cb;
        if (MODE == 1)          { dst = g_rh; cb = n0; }
        else if (n0 < 1024)     { dst = g_qh; cb = n0; }
        else if (n0 < 2048)     { dst = g_kh; cb = n0 - 1024; }
        else                    { dst = g_vh; cb = n0 - 2048; }
#pragma unroll
        for (int nn = 0; nn < 16; nn++) {
            size_t c = cb + nn * 8 + 2 * (l & 3);
            *(__half2*)(dst + r0 * 1024 + c) =
                __floats2half2_rn(acc[nn][0], acc[nn][1]);
            *(__half2*)(dst + (r0 + 8) * 1024 + c) =
                __floats2half2_rn(acc[nn][2], acc[nn][3]);
        }
        return;
    }
#pragma unroll
    for (int nn = 0; nn < 16; nn++) {
        size_t c = n0 + nn * 8 + 2 * (l & 3);
        float2 x0 = *(const float2*)(Xres + r0 * N + c);
        float2 x1 = *(const float2*)(Xres + (r0 + 8) * N + c);
        *(float2*)(g_y + r0 * N + c) =
            make_float2(acc[nn][0] + x0.x, acc[nn][1] + x0.y);
        *(float2*)(g_y + (r0 + 8) * N + c) =
            make_float2(acc[nn][2] + x1.x, acc[nn][3] + x1.y);
    }
}

// ============================================================
// Draw = (q + pos_bias_v) @ r^T per (b,h), PRE-SHIFTED fp16 out.
// One CTA: 128 i-rows x 512 t-cols (4 R-tiles, double-buffered);
// Q staged once, q-fragments register-persistent.
//   tcol = t + i + 1;  if tcol >= S -> (row i, col tcol-S)
//                      else -> (row i-1, col tcol) [dropped if i==0]
// fp16 smem-staged epilogue, lane-consecutive streaming stores.
// ============================================================
__global__ __launch_bounds__(256, 2) void bd_gemm(const float* __restrict__ pbv)
{
    extern __shared__ __half smB[];
    __half* Qs = smB;                  // 128 x 72
    // R bufs at bytes 18432 + buf*18432; stage at bytes 55296 (128 x 136)
    int tid = threadIdx.x, l = tid & 31, w = tid >> 5;
    int bh = blockIdx.z, b = bh >> 4, h = bh & 15;
    int i0 = blockIdx.y * 128;
    int tg0 = blockIdx.x * 512;
    const __half* Qg = g_qh + (size_t)b * 1024 + h * 64;   // row stride 2048
    const __half* Rg = g_rh + h * 64;                      // row stride 1024
    const float* bias = pbv + h * 64;
    uint32_t sQ  = (uint32_t)__cvta_generic_to_shared(Qs);
    uint32_t sR0 = sQ + 18432;
    __half* stage = smB + 27648;       // halves offset (55296 bytes)

#define PFR(TT)                                                                 \
    {                                                                           \
        uint32_t rb = sR0 + ((TT) & 1) * 18432;                                 \
        const __half* rg = Rg + (size_t)(tg0 + (TT) * 128) * 1024;              \
        _Pragma("unroll")                                                       \
        for (int t = 0; t < 4; t++) {                                           \
            int idx = tid + t * 256; int r = idx >> 3, c8 = (idx & 7) << 3;     \
            cpa16(rb + (r * 72 + c8) * 2, rg + (size_t)r * 1024 + c8);          \
        }                                                                       \
        cpcommit();                                                             \
    }

    PFR(0)
    // Q + bias -> fp16 smem
#pragma unroll
    for (int t = 0; t < 8; t++) {
        int idx = tid + t * 256; int r = idx >> 4, c4 = (idx & 15) << 2;
        float2 f0 = __half22float2(*(const __half2*)(Qg + (size_t)(i0 + r) * 2048 + c4));
        float2 f1 = __half22float2(*(const __half2*)(Qg + (size_t)(i0 + r) * 2048 + c4 + 2));
        float4 u4 = *(const float4*)(bias + c4);
        *(__half2*)(Qs + r * 72 + c4)     = __floats2half2_rn(f0.x + u4.x, f0.y + u4.y);
        *(__half2*)(Qs + r * 72 + c4 + 2) = __floats2half2_rn(f1.x + u4.z, f1.y + u4.w);
    }
    __syncthreads();   // Qs visible

    uint32_t qoff = (uint32_t)((w * 16 + (l & 7) + ((l >> 3) & 1) * 8) * 144
                               + ((l >> 4) & 1) * 16);
    uint32_t roff = (uint32_t)(((l & 7) + (l >> 4) * 8) * 144 + ((l >> 3) & 1) * 16);

    uint32_t qa[4][4];
#pragma unroll
    for (int ks = 0; ks < 4; ks++) ldsm4(qa[ks], sQ + qoff + ks * 32);

    int lr0 = w * 16 + (l >> 2);
    __half* out = g_bd + (size_t)bh * S_ * S_;

    for (int tt = 0; tt < 4; tt++) {
        if (tt + 1 < 4) { PFR(tt + 1) cpwait<1>(); }
        else            { cpwait<0>(); }
        __syncthreads();          // R(tt) visible to all warps
        uint32_t rb = sR0 + (tt & 1) * 18432;

        float acc[16][4] = {};
#pragma unroll
        for (int ks = 0; ks < 4; ks++)
#pragma unroll
            for (int np = 0; np < 8; np++) {
                uint32_t kb[4];
                ldsm4(kb, rb + roff + (np * 16) * 144 + ks * 32);
                mma16h(acc[2 * np],     qa[ks], kb,     acc[2 * np]);
                mma16h(acc[2 * np + 1], qa[ks], kb + 2, acc[2 * np + 1]);
            }

        // stage fp16, then coalesced shifted stores
#pragma unroll
        for (int nt = 0; nt < 16; nt++) {
            int c = nt * 8 + 2 * (l & 3);
            *(__half2*)&stage[lr0 * 136 + c] =
                __floats2half2_rn(acc[nt][0], acc[nt][1]);
            *(__half2*)&stage[(lr0 + 8) * 136 + c] =
                __floats2half2_rn(acc[nt][2], acc[nt][3]);
        }
        __syncthreads();          // stage visible

        int t0 = tg0 + tt * 128;
#pragma unroll
        for (int rr = 0; rr < 16; rr++) {
            int r = w * 16 + rr;
            int gi = i0 + r;
            int base = t0 + gi + 1;
#pragma unroll
            for (int j = 0; j < 4; j++) {
                int c = l + 32 * j;
                int tcol = base + c;
                __half v = stage[r * 136 + c];
                if (tcol >= S_)      __stcs(out + (size_t)gi * S_ + (tcol - S_), v);
                else if (gi > 0)     __stcs(out + (size_t)(gi - 1) * S_ + tcol, v);
            }
        }
        __syncthreads();          // stage reusable
    }
#undef PFR
}

// ============================================================
// Fused attention: all-fp16 mma, K/V double-buffered,
// pre-shifted fp16 BD. Output -> g_atth fp16.  (unchanged)
// ============================================================
__global__ __launch_bounds__(256, 2) void fattn(const float* __restrict__ pbu)
{
    extern __shared__ __half smh[];
    __half* Qsh = smh;                      // 128 x 72 fp16 (persistent)
    int tid = threadIdx.x, l = tid & 31, w = tid >> 5;
    int bh = blockIdx.y, b = bh >> 4, h = bh & 15;
    int i0 = blockIdx.x * 128;
    const __half* Qg = g_qh + (size_t)b * 1024 + h * 64;   // row stride 2048
    const __half* Kg = g_kh + (size_t)b * 1024 + h * 64;
    const __half* Vg = g_vh + (size_t)b * 1024 + h * 64;
    const __half* bd = g_bd + (size_t)bh * S_ * S_;
    const float* bias = pbu + h * 64;
    uint32_t sQ     = (uint32_t)__cvta_generic_to_shared(Qsh);
    uint32_t sKbase = (uint32_t)__cvta_generic_to_shared(smh + 9216);
    uint32_t sVbase = (uint32_t)__cvta_generic_to_shared(smh + 27648);

    // (q + bias_u) -> fp16 smem
#pragma unroll
    for (int t = 0; t < 8; t++) {
        int idx = tid + t * 256; int r = idx >> 4, c4 = (idx & 15) << 2;
        float2 f0 = __half22float2(*(const __half2*)(Qg + (size_t)(i0 + r) * 2048 + c4));
        float2 f1 = __half22float2(*(const __half2*)(Qg + (size_t)(i0 + r) * 2048 + c4 + 2));
        float4 u4 = *(const float4*)(bias + c4);
        *(__half2*)(Qsh + r * 72 + c4)     = __floats2half2_rn(f0.x + u4.x, f0.y + u4.y);
        *(__half2*)(Qsh + r * 72 + c4 + 2) = __floats2half2_rn(f1.x + u4.z, f1.y + u4.w);
    }

#define PFKV(IT, BO)                                                            \
    {                                                                           \
        const __half* kn = Kg + (size_t)((IT) * 128) * 2048;                    \
        const __half* vn = Vg + (size_t)((IT) * 128) * 2048;                    \
        _Pragma("unroll")                                                       \
        for (int t = 0; t < 4; t++) {                                           \
            int idx = tid + t * 256; int r = idx >> 3, c8 = (idx & 7) << 3;     \
            cpa16(sKbase + (BO) + (r * 72 + c8) * 2, kn + (size_t)r * 2048 + c8);\
            cpa16(sVbase + (BO) + (r * 72 + c8) * 2, vn + (size_t)r * 2048 + c8);\
        }                                                                       \
        cpcommit();                                                             \
    }

    PFKV(0, 0)
    PFKV(1, 18432)

    uint32_t qoff  = (uint32_t)((w * 16 + (l & 7) + ((l >> 3) & 1) * 8) * 144
                                + ((l >> 4) & 1) * 16);
    uint32_t kboff = (uint32_t)(((l & 7) + (l >> 4) * 8) * 144 + ((l >> 3) & 1) * 16);
    uint32_t vrbase = (uint32_t)((l & 7) + ((l >> 3) & 1) * 8);
    uint32_t vcoff  = (uint32_t)((l >> 4) * 8);

    float o[8][4] = {};
    float bdbuf[32];
    float mrow0 = -1e30f, mrow1 = -1e30f, lsum0 = 0.f, lsum1 = 0.f;
    int tc = l & 3;
    int lr0 = w * 16 + (l >> 2);
    int row0 = i0 + lr0, row1 = row0 + 8;
    const float CS = 0.1803368801111204f;   // 0.125 * log2(e)

#define LDBD(JB)                                                                \
    _Pragma("unroll")                                                           \
    for (int nt = 0; nt < 8; nt++) {                                            \
        int c0 = (JB) + nt * 8 + 2 * tc;                                        \
        __half2 h0 = __ldcs((const __half2*)(bd + (size_t)row0 * S_ + c0));     \
        __half2 h1 = __ldcs((const __half2*)(bd + (size_t)row1 * S_ + c0));     \
        float2 v0 = __half22float2(h0);                                         \
        float2 v1 = __half22float2(h1);                                         \
        bdbuf[nt * 4 + 0] = (c0     == row0 + 1) ? 0.f : v0.x;                  \
        bdbuf[nt * 4 + 1] = (c0 + 1 == row0 + 1) ? 0.f : v0.y;                  \
        bdbuf[nt * 4 + 2] = (c0     == row1 + 1) ? 0.f : v1.x;                  \
        bdbuf[nt * 4 + 3] = (c0 + 1 == row1 + 1) ? 0.f : v1.y;                  \
    }

    LDBD(0)

#define AC_MMA(HALF)                                                            \
    _Pragma("unroll")                                                           \
    for (int nt = 0; nt < 8; nt++)                                              \
        p[nt][0] = p[nt][1] = p[nt][2] = p[nt][3] = 0.f;                        \
    _Pragma("unroll")                                                           \
    for (int ks = 0; ks < 4; ks++) {                                            \
        uint32_t qf[4];                                                         \
        ldsm4(qf, sQ + qoff + ks * 32);                                         \
        _Pragma("unroll")                                                       \
        for (int np = 0; np < 4; np++) {                                        \
            uint32_t kb[4];                                                     \
            ldsm4(kb, sK + kboff + ((HALF) * 64 + np * 16) * 144 + ks * 32);    \
            mma16h(p[2 * np],     qf, kb,     p[2 * np]);                       \
            mma16h(p[2 * np + 1], qf, kb + 2, p[2 * np + 1]);                   \
        }                                                                       \
    }

#define SOFTMAX_STEP()                                                          \
    {                                                                           \
        float mx0 = -1e30f, mx1 = -1e30f;                                       \
        _Pragma("unroll")                                                       \
        for (int nt = 0; nt < 8; nt++) {                                        \
            float s;                                                            \
            s = (p[nt][0] + bdbuf[nt*4+0]) * CS; p[nt][0] = s; mx0 = fmaxf(mx0, s); \
            s = (p[nt][1] + bdbuf[nt*4+1]) * CS; p[nt][1] = s; mx0 = fmaxf(mx0, s); \
            s = (p[nt][2] + bdbuf[nt*4+2]) * CS; p[nt][2] = s; mx1 = fmaxf(mx1, s); \
            s = (p[nt][3] + bdbuf[nt*4+3]) * CS; p[nt][3] = s; mx1 = fmaxf(mx1, s); \
        }                                                                       \
        mx0 = fmaxf(mx0, __shfl_xor_sync(~0u, mx0, 1));                         \
        mx0 = fmaxf(mx0, __shfl_xor_sync(~0u, mx0, 2));                         \
        mx1 = fmaxf(mx1, __shfl_xor_sync(~0u, mx1, 1));                         \
        mx1 = fmaxf(mx1, __shfl_xor_sync(~0u, mx1, 2));                         \
        float mn0 = fmaxf(mrow0, mx0), mn1 = fmaxf(mrow1, mx1);                 \
        float al0 = ex2(mrow0 - mn0), al1 = ex2(mrow1 - mn1);                   \
        mrow0 = mn0; mrow1 = mn1;                                               \
        float rs0 = 0.f, rs1 = 0.f;                                             \
        _Pragma("unroll")                                                       \
        for (int nt = 0; nt < 8; nt++) {                                        \
            p[nt][0] = ex2(p[nt][0] - mn0); p[nt][1] = ex2(p[nt][1] - mn0);     \
            p[nt][2] = ex2(p[nt][2] - mn1); p[nt][3] = ex2(p[nt][3] - mn1);     \
            rs0 += p[nt][0] + p[nt][1]; rs1 += p[nt][2] + p[nt][3];             \
        }                                                                       \
        rs0 += __shfl_xor_sync(~0u, rs0, 1); rs0 += __shfl_xor_sync(~0u, rs0, 2);\
        rs1 += __shfl_xor_sync(~0u, rs1, 1); rs1 += __shfl_xor_sync(~0u, rs1, 2);\
        lsum0 = lsum0 * al0 + rs0;                                              \
        lsum1 = lsum1 * al1 + rs1;                                              \
        _Pragma("unroll")                                                       \
        for (int nt = 0; nt < 8; nt++) {                                        \
            o[nt][0] *= al0; o[nt][1] *= al0; o[nt][2] *= al1; o[nt][3] *= al1; \
        }                                                                       \
    }

#define CVT_P()                                                                 \
    uint32_t af[4][4];                                                          \
    _Pragma("unroll")                                                           \
    for (int ks = 0; ks < 4; ks++) {                                            \
        af[ks][0] = h2(p[2*ks][0],   p[2*ks][1]);                               \
        af[ks][1] = h2(p[2*ks][2],   p[2*ks][3]);                               \
        af[ks][2] = h2(p[2*ks+1][0], p[2*ks+1][1]);                             \
        af[ks][3] = h2(p[2*ks+1][2], p[2*ks+1][3]);                             \
    }

#define PV16(HALF)                                                              \
    _Pragma("unroll")                                                           \
    for (int ks = 0; ks < 4; ks++) {                                            \
        uint32_t vrow = (uint32_t)((HALF) * 64 + ks * 16) + vrbase;             \
        _Pragma("unroll")                                                       \
        for (int ntt = 0; ntt < 4; ntt++) {                                     \
            uint32_t vb[4];                                                     \
            ldsm4t(vb, sV + (vrow * 72 + ntt * 16 + vcoff) * 2);                \
            mma16h(o[2*ntt],   af[ks], vb,   o[2*ntt]);                         \
            mma16h(o[2*ntt+1], af[ks], vb+2, o[2*ntt+1]);                       \
        }                                                                       \
    }

    for (int it = 0; it < 16; it++) {
        uint32_t bo = (uint32_t)(it & 1) * 18432;
        uint32_t sK = sKbase + bo;
        uint32_t sV = sVbase + bo;
        if (it == 15) cpwait<0>(); else cpwait<1>();
        __syncthreads();

        {   // ---- half 0 ----
            float p[8][4];
            AC_MMA(0)
            SOFTMAX_STEP()
            CVT_P()
            LDBD(it * 128 + 64)
            PV16(0)
        }
        {   // ---- half 1 ----
            float p[8][4];
            AC_MMA(1)
            SOFTMAX_STEP()
            CVT_P()
            if (it + 1 < 16) LDBD((it + 1) * 128)
            PV16(1)
        }
        __syncthreads();
        if (it + 2 < 16) PFKV(it + 2, bo)
    }
#undef PFKV
#undef LDBD
#undef AC_MMA
#undef SOFTMAX_STEP
#undef CVT_P
#undef PV16

    float inv0 = 1.f / lsum0, inv1 = 1.f / lsum1;
#pragma unroll
    for (int nt = 0; nt < 8; nt++) {
        int c = h * 64 + nt * 8 + 2 * tc;
        *(__half2*)(g_atth + ((size_t)row0 * B_ + b) * 1024 + c) =
            __floats2half2_rn(o[nt][0] * inv0, o[nt][1] * inv0);
        *(__half2*)(g_atth + ((size_t)row1 * B_ + b) * 1024 + c) =
            __floats2half2_rn(o[nt][2] * inv1, o[nt][3] * inv1);
    }
}

// ============================================================
// LayerNorm over D=1024 per row.
// ============================================================
__global__ __launch_bounds__(256) void ln_k(const float* __restrict__ gamma,
                                            const float* __restrict__ beta,
                                            float* __restrict__ out)
{
    __shared__ float reds[8], redq[8];
    const float* y = g_y + (size_t)blockIdx.x * D_;
    int tid = threadIdx.x;
    float v[4];
    float s = 0.f, q = 0.f;
#pragma unroll
    for (int t = 0; t < 4; t++) {
        v[t] = y[tid + t * 256];
        s += v[t]; q += v[t] * v[t];
    }
#pragma unroll
    for (int o = 16; o; o >>= 1) {
        s += __shfl_xor_sync(0xffffffffu, s, o);
        q += __shfl_xor_sync(0xffffffffu, q, o);
    }
    if ((tid & 31) == 0) { reds[tid >> 5] = s; redq[tid >> 5] = q; }
    __syncthreads();
    float ts = 0.f, tq = 0.f;
#pragma unroll
    for (int wv = 0; wv < 8; wv++) { ts += reds[wv]; tq += redq[wv]; }
    float mu = ts * (1.f / 1024.f);
    float var = tq * (1.f / 1024.f) - mu * mu;
    float inv = rsqrtf(var + 1e-5f);
    float* op = out + (size_t)blockIdx.x * D_;
#pragma unroll
    for (int t = 0; t < 4; t++) {
        int c = tid + t * 256;
        op[c] = (v[t] - mu) * inv * gamma[c] + beta[c];
    }
}

// ============================================================
extern "C" void kernel_launch(void* const* d_in, const int* in_sizes, int n_in,
                              void* d_out, int out_size)
{
    const float* x    = (const float*)d_in[0];
    const float* pe   = (const float*)d_in[1];
    const float* pbu  = (const float*)d_in[2];
    const float* pbv  = (const float*)d_in[3];
    const float* Wqkv = (const float*)d_in[4];
    const float* Wrel = (const float*)d_in[5];
    const float* Wo   = (const float*)d_in[6];
    const float* gam  = (const float*)d_in[7];
    const float* bet  = (const float*)d_in[8];
    float* out = (float*)d_out;

    const int PH_SMEM = 56832;     // fp16 pgemm: 3xA + 3xB stages
    const int BD_SMEM = 90112;     // fp16 bd_gemm: Q + 2xR + stage
    const int FA_SMEM = 92160;     // fp16 fattn: Q + 2xK + 2xV
    cudaFuncSetAttribute(pgemm_h<0>, cudaFuncAttributeMaxDynamicSharedMemorySize, PH_SMEM);
    cudaFuncSetAttribute(pgemm_h<1>, cudaFuncAttributeMaxDynamicSharedMemorySize, PH_SMEM);
    cudaFuncSetAttribute(pgemm_h<2>, cudaFuncAttributeMaxDynamicSharedMemorySize, PH_SMEM);
    cudaFuncSetAttribute(bd_gemm,    cudaFuncAttributeMaxDynamicSharedMemorySize, BD_SMEM);
    cudaFuncSetAttribute(fattn,      cudaFuncAttributeMaxDynamicSharedMemorySize, FA_SMEM);

    __half *xh, *peh, *wqkvh, *wrelh, *woh;
    cudaGetSymbolAddress((void**)&xh,    g_xh);
    cudaGetSymbolAddress((void**)&peh,   g_peh);
    cudaGetSymbolAddress((void**)&wqkvh, g_wqkvh);
    cudaGetSymbolAddress((void**)&wrelh, g_wrelh);
    cudaGetSymbolAddress((void**)&woh,   g_woh);

    // 0) all fp16 conversions in one launch
    cvt_all<<<11264, 256>>>(x, pe, Wqkv, Wrel, Wo);
    // 1) qkv = x @ W_qkv  (q, k, v -> fp16)
    pgemm_h<0><<<dim3(24, 32), 256, PH_SMEM>>>(xh, wqkvh, nullptr, 3072);
    // 2) r = pos_emb @ W_relemb -> fp16
    pgemm_h<1><<<dim3(8, 16), 256, PH_SMEM>>>(peh, wrelh, nullptr, 1024);
    // 3) pre-shifted fp16 Draw = (q + pbv) @ r^T per (b,h)
    bd_gemm<<<dim3(4, 16, 32), 256, BD_SMEM>>>(pbv);
    // 4) fused: scores + shifted-BD add + softmax + PV -> g_atth fp16
    fattn<<<dim3(16, 32), 256, FA_SMEM>>>(pbu);
    // 5) y = x + attn_vec @ W_o   (A = g_atth selected inside kernel)
    pgemm_h<2><<<dim3(8, 32), 256, PH_SMEM>>>(nullptr, woh, x, 1024);
    // 6) layernorm
    ln_k<<<4096, 256>>>(gam, bet, out);
}